// round 1
// baseline (speedup 1.0000x reference)
#include <cuda_runtime.h>
#include <math.h>

#define H 1024
#define NHEADS 16
#define HD 64
#define SEQ 2048
#define BATCH 2
#define ROWS (BATCH*SEQ)   // 4096
#define NS 3

// Scratch (device globals: allocation-free per harness rules)
__device__ float g_q[ROWS*H];
__device__ float g_k[ROWS*H];
__device__ float g_v[ROWS*H];
__device__ float g_att[ROWS*H];
__device__ float g_enh[ROWS*H];
__device__ float g_wavg[H*H];
__device__ float g_bavg[H];

// ---------------------------------------------------------------------------
// C[M,N] = A[M,K] @ W[N,K]^T + bias[N]   (both operands K-contiguous, "NT")
// 128x128 tile, BK=8, 256 threads, 8x8 register blocking.
// ---------------------------------------------------------------------------
__global__ __launch_bounds__(256) void gemm_nt(
    const float* __restrict__ A, const float* __restrict__ W,
    const float* __restrict__ bias, float* __restrict__ C,
    int M, int N, int K)
{
    const int BM = 128, BN = 128, BK = 8;
    __shared__ float As[BK][BM + 4];
    __shared__ float Bs[BK][BN + 4];

    int t  = threadIdx.x;
    int tx = t & 15;        // 0..15 -> output cols tx*8..tx*8+7
    int ty = t >> 4;        // 0..15 -> output rows ty*8..ty*8+7
    int m0 = blockIdx.y * BM;
    int n0 = blockIdx.x * BN;

    float acc[8][8];
    #pragma unroll
    for (int i = 0; i < 8; i++)
        #pragma unroll
        for (int j = 0; j < 8; j++) acc[i][j] = 0.0f;

    int lrow = t >> 1;            // 0..127
    int lc4  = (t & 1) * 4;       // 0 or 4
    const float* Ag = A + (size_t)(m0 + lrow) * K + lc4;
    const float* Wg = W + (size_t)(n0 + lrow) * K + lc4;

    for (int kb = 0; kb < K; kb += BK) {
        float4 av = *(const float4*)(Ag + kb);
        float4 wv = *(const float4*)(Wg + kb);
        As[lc4 + 0][lrow] = av.x; As[lc4 + 1][lrow] = av.y;
        As[lc4 + 2][lrow] = av.z; As[lc4 + 3][lrow] = av.w;
        Bs[lc4 + 0][lrow] = wv.x; Bs[lc4 + 1][lrow] = wv.y;
        Bs[lc4 + 2][lrow] = wv.z; Bs[lc4 + 3][lrow] = wv.w;
        __syncthreads();

        #pragma unroll
        for (int k = 0; k < BK; k++) {
            float a[8], b[8];
            #pragma unroll
            for (int i = 0; i < 8; i++) a[i] = As[k][ty * 8 + i];
            #pragma unroll
            for (int j = 0; j < 8; j++) b[j] = Bs[k][tx * 8 + j];
            #pragma unroll
            for (int i = 0; i < 8; i++)
                #pragma unroll
                for (int j = 0; j < 8; j++)
                    acc[i][j] += a[i] * b[j];
        }
        __syncthreads();
    }

    #pragma unroll
    for (int i = 0; i < 8; i++) {
        int row = m0 + ty * 8 + i;
        #pragma unroll
        for (int j = 0; j < 8; j++) {
            int col = n0 + tx * 8 + j;
            C[(size_t)row * N + col] = acc[i][j] + bias[col];
        }
    }
}

// ---------------------------------------------------------------------------
// Averaging of strata weights: mean_n(a @ Ws[n]^T + bs[n]) == a @ mean(Ws)^T + mean(bs)
// ---------------------------------------------------------------------------
__global__ void avg_kernel(const float* __restrict__ Ws, const float* __restrict__ bs)
{
    int i = blockIdx.x * 256 + threadIdx.x;
    if (i < H * H)
        g_wavg[i] = (Ws[i] + Ws[i + H * H] + Ws[i + 2 * H * H]) * (1.0f / 3.0f);
    if (i < H)
        g_bavg[i] = (bs[i] + bs[i + H] + bs[i + 2 * H]) * (1.0f / 3.0f);
}

// ---------------------------------------------------------------------------
// Flash attention, fp32. One CTA = 64 query rows of one (batch, head).
// 256 threads; each thread owns 2 rows x 8 cols of S/P and 2 rows x 8 dims of O.
// smem: Qs,Ks,Vs,Ps each [64][65] floats -> 66560 B dynamic.
// ---------------------------------------------------------------------------
#define SM_STRIDE 65
#define ATTN_SMEM (4 * 64 * SM_STRIDE * 4)

__global__ __launch_bounds__(256) void attn_kernel(
    const float* __restrict__ q, const float* __restrict__ k,
    const float* __restrict__ v, float* __restrict__ out)
{
    extern __shared__ float sm[];
    float* Qs = sm;
    float* Ks = Qs + 64 * SM_STRIDE;
    float* Vs = Ks + 64 * SM_STRIDE;
    float* Ps = Vs + 64 * SM_STRIDE;

    int t  = threadIdx.x;
    int qb = blockIdx.x;      // query block 0..31
    int h  = blockIdx.y;      // head
    int b  = blockIdx.z;      // batch

    int rg = t >> 3;          // 0..31  -> rows 2*rg, 2*rg+1
    int cg = t & 7;           // 0..7   -> cols cg*8..cg*8+7
    int r0 = rg * 2, r1 = r0 + 1;

    // cooperative tile loads: each thread loads 16 consecutive floats of one row
    int lr = t >> 2;              // 0..63
    int lc = (t & 3) * 16;        // 0,16,32,48
    const float scale = 0.125f;   // 1/sqrt(64)

    {   // load Q (pre-scaled)
        const float* qg = q + (size_t)(b * SEQ + qb * 64 + lr) * H + h * HD + lc;
        #pragma unroll
        for (int i = 0; i < 4; i++) {
            float4 v4 = *(const float4*)(qg + i * 4);
            Qs[lr * SM_STRIDE + lc + i * 4 + 0] = v4.x * scale;
            Qs[lr * SM_STRIDE + lc + i * 4 + 1] = v4.y * scale;
            Qs[lr * SM_STRIDE + lc + i * 4 + 2] = v4.z * scale;
            Qs[lr * SM_STRIDE + lc + i * 4 + 3] = v4.w * scale;
        }
    }

    float m0v = -1e30f, m1v = -1e30f, l0 = 0.0f, l1 = 0.0f;
    float o0[8], o1[8];
    #pragma unroll
    for (int d = 0; d < 8; d++) { o0[d] = 0.0f; o1[d] = 0.0f; }

    for (int kb = 0; kb < SEQ / 64; kb++) {
        __syncthreads();  // previous iteration's Ks/Vs/Ps reads done
        {
            const float* kg = k + (size_t)(b * SEQ + kb * 64 + lr) * H + h * HD + lc;
            const float* vg = v + (size_t)(b * SEQ + kb * 64 + lr) * H + h * HD + lc;
            #pragma unroll
            for (int i = 0; i < 4; i++) {
                float4 kv4 = *(const float4*)(kg + i * 4);
                float4 vv4 = *(const float4*)(vg + i * 4);
                Ks[lr * SM_STRIDE + lc + i * 4 + 0] = kv4.x;
                Ks[lr * SM_STRIDE + lc + i * 4 + 1] = kv4.y;
                Ks[lr * SM_STRIDE + lc + i * 4 + 2] = kv4.z;
                Ks[lr * SM_STRIDE + lc + i * 4 + 3] = kv4.w;
                Vs[lr * SM_STRIDE + lc + i * 4 + 0] = vv4.x;
                Vs[lr * SM_STRIDE + lc + i * 4 + 1] = vv4.y;
                Vs[lr * SM_STRIDE + lc + i * 4 + 2] = vv4.z;
                Vs[lr * SM_STRIDE + lc + i * 4 + 3] = vv4.w;
            }
        }
        __syncthreads();

        // S = (Q*scale) @ K^T  : 2 rows x 8 cols per thread
        float s0[8], s1[8];
        #pragma unroll
        for (int c = 0; c < 8; c++) { s0[c] = 0.0f; s1[c] = 0.0f; }
        #pragma unroll 8
        for (int kk = 0; kk < 64; kk++) {
            float qa = Qs[r0 * SM_STRIDE + kk];
            float qc = Qs[r1 * SM_STRIDE + kk];
            #pragma unroll
            for (int c = 0; c < 8; c++) {
                float kvv = Ks[(cg * 8 + c) * SM_STRIDE + kk];
                s0[c] += qa * kvv;
                s1[c] += qc * kvv;
            }
        }

        // online softmax: reduce max/sum across the 8 lanes of a row group
        float mt0 = s0[0], mt1 = s1[0];
        #pragma unroll
        for (int c = 1; c < 8; c++) { mt0 = fmaxf(mt0, s0[c]); mt1 = fmaxf(mt1, s1[c]); }
        #pragma unroll
        for (int off = 1; off < 8; off <<= 1) {
            mt0 = fmaxf(mt0, __shfl_xor_sync(0xffffffffu, mt0, off));
            mt1 = fmaxf(mt1, __shfl_xor_sync(0xffffffffu, mt1, off));
        }
        float mn0 = fmaxf(m0v, mt0), mn1 = fmaxf(m1v, mt1);
        float a0 = __expf(m0v - mn0), a1 = __expf(m1v - mn1);

        float ps0 = 0.0f, ps1 = 0.0f;
        #pragma unroll
        for (int c = 0; c < 8; c++) {
            s0[c] = __expf(s0[c] - mn0);  ps0 += s0[c];
            s1[c] = __expf(s1[c] - mn1);  ps1 += s1[c];
            Ps[r0 * SM_STRIDE + cg * 8 + c] = s0[c];
            Ps[r1 * SM_STRIDE + cg * 8 + c] = s1[c];
        }
        #pragma unroll
        for (int off = 1; off < 8; off <<= 1) {
            ps0 += __shfl_xor_sync(0xffffffffu, ps0, off);
            ps1 += __shfl_xor_sync(0xffffffffu, ps1, off);
        }
        l0 = l0 * a0 + ps0;  l1 = l1 * a1 + ps1;
        m0v = mn0;           m1v = mn1;
        #pragma unroll
        for (int d = 0; d < 8; d++) { o0[d] *= a0; o1[d] *= a1; }

        __syncthreads();  // Ps fully written

        // O += P @ V : 2 rows x 8 dims per thread
        #pragma unroll 8
        for (int j = 0; j < 64; j++) {
            float p0 = Ps[r0 * SM_STRIDE + j];
            float p1 = Ps[r1 * SM_STRIDE + j];
            #pragma unroll
            for (int d = 0; d < 8; d++) {
                float vv = Vs[j * SM_STRIDE + cg * 8 + d];
                o0[d] += p0 * vv;
                o1[d] += p1 * vv;
            }
        }
    }

    float inv0 = 1.0f / l0, inv1 = 1.0f / l1;
    size_t gr0 = (size_t)(b * SEQ + qb * 64 + r0) * H + h * HD + cg * 8;
    size_t gr1 = (size_t)(b * SEQ + qb * 64 + r1) * H + h * HD + cg * 8;
    #pragma unroll
    for (int d = 0; d < 8; d++) {
        out[gr0 + d] = o0[d] * inv0;
        out[gr1 + d] = o1[d] * inv1;
    }
}

// ---------------------------------------------------------------------------
extern "C" void kernel_launch(void* const* d_in, const int* in_sizes, int n_in,
                              void* d_out, int out_size)
{
    const float* x  = (const float*)d_in[0];
    const float* Wq = (const float*)d_in[1];
    const float* bq = (const float*)d_in[2];
    const float* Wk = (const float*)d_in[3];
    const float* bk = (const float*)d_in[4];
    const float* Wv = (const float*)d_in[5];
    const float* bv = (const float*)d_in[6];
    const float* Ws = (const float*)d_in[7];
    const float* bs = (const float*)d_in[8];
    const float* Wo = (const float*)d_in[9];
    const float* bo = (const float*)d_in[10];

    float *qp, *kp, *vp, *attp, *enhp, *wavgp, *bavgp;
    cudaGetSymbolAddress((void**)&qp,    g_q);
    cudaGetSymbolAddress((void**)&kp,    g_k);
    cudaGetSymbolAddress((void**)&vp,    g_v);
    cudaGetSymbolAddress((void**)&attp,  g_att);
    cudaGetSymbolAddress((void**)&enhp,  g_enh);
    cudaGetSymbolAddress((void**)&wavgp, g_wavg);
    cudaGetSymbolAddress((void**)&bavgp, g_bavg);

    cudaFuncSetAttribute(attn_kernel,
                         cudaFuncAttributeMaxDynamicSharedMemorySize, ATTN_SMEM);

    dim3 gg(H / 128, ROWS / 128);   // 8 x 32

    gemm_nt<<<gg, 256>>>(x, Wq, bq, qp, ROWS, H, H);
    gemm_nt<<<gg, 256>>>(x, Wk, bk, kp, ROWS, H, H);
    gemm_nt<<<gg, 256>>>(x, Wv, bv, vp, ROWS, H, H);

    attn_kernel<<<dim3(SEQ / 64, NHEADS, BATCH), 256, ATTN_SMEM>>>(qp, kp, vp, attp);

    avg_kernel<<<(H * H + 255) / 256, 256>>>(Ws, bs);

    gemm_nt<<<gg, 256>>>(attp, wavgp, bavgp, enhp, ROWS, H, H);
    gemm_nt<<<gg, 256>>>(enhp, Wo, bo, (float*)d_out, ROWS, H, H);
}

// round 2
// speedup vs baseline: 1.8595x; 1.8595x over previous
#include <cuda_runtime.h>
#include <math.h>

#define H 1024
#define NHEADS 16
#define HD 64
#define SEQ 2048
#define BATCH 2
#define ROWS (BATCH*SEQ)   // 4096

// Scratch (device globals: allocation-free per harness rules)
__device__ float g_q[ROWS*H];
__device__ float g_k[ROWS*H];
__device__ float g_v[ROWS*H];
__device__ float g_att[ROWS*H];
__device__ float g_enh[ROWS*H];
__device__ float g_wavg[H*H];
__device__ float g_bavg[H];

// ---------------------------------------------------------------------------
__device__ __forceinline__ unsigned f2tf(float x) {
    unsigned u; asm("cvt.rna.tf32.f32 %0, %1;" : "=r"(u) : "f"(x)); return u;
}

__device__ __forceinline__ void mma8(float* c, const unsigned* a, const unsigned* b) {
    asm volatile(
        "mma.sync.aligned.m16n8k8.row.col.f32.tf32.tf32.f32 "
        "{%0,%1,%2,%3}, {%4,%5,%6,%7}, {%8,%9}, {%0,%1,%2,%3};"
        : "+f"(c[0]), "+f"(c[1]), "+f"(c[2]), "+f"(c[3])
        : "r"(a[0]), "r"(a[1]), "r"(a[2]), "r"(a[3]), "r"(b[0]), "r"(b[1]));
}

// ---------------------------------------------------------------------------
// C[M,N] = A[M,K] @ W[N,K]^T + bias[N], 3xTF32 (hi*hi + hi*lo + lo*hi).
// BM=BN=128, BK=16, 256 threads (8 warps, 2x4), warp tile 64x32, mma m16n8k8.
// Smem stride 20 words -> conflict-free fragment loads.
// ---------------------------------------------------------------------------
#define GSTR 20
__global__ __launch_bounds__(256) void gemm3(
    const float* __restrict__ A, const float* __restrict__ W,
    const float* __restrict__ bias, float* __restrict__ C,
    int M, int N, int K)
{
    __shared__ unsigned Ah[128*GSTR], Al[128*GSTR], Bh[128*GSTR], Bl[128*GSTR];

    int t = threadIdx.x, lane = t & 31, warp = t >> 5;
    int wm = (warp >> 2) * 64;   // 0 or 64
    int wn = (warp & 3) * 32;    // 0,32,64,96
    int m0 = blockIdx.y * 128, n0 = blockIdx.x * 128;

    float acc[16][4];
    #pragma unroll
    for (int i = 0; i < 16; i++)
        #pragma unroll
        for (int j = 0; j < 4; j++) acc[i][j] = 0.0f;

    int lr = t >> 1;            // 0..127
    int lk = (t & 1) * 8;       // 0 or 8
    const float* Ag = A + (size_t)(m0 + lr) * K + lk;
    const float* Wg = W + (size_t)(n0 + lr) * K + lk;

    for (int kb = 0; kb < K; kb += 16) {
        float4 av0 = *(const float4*)(Ag + kb);
        float4 av1 = *(const float4*)(Ag + kb + 4);
        float4 wv0 = *(const float4*)(Wg + kb);
        float4 wv1 = *(const float4*)(Wg + kb + 4);
        float aval[8] = {av0.x, av0.y, av0.z, av0.w, av1.x, av1.y, av1.z, av1.w};
        float wval[8] = {wv0.x, wv0.y, wv0.z, wv0.w, wv1.x, wv1.y, wv1.z, wv1.w};
        #pragma unroll
        for (int i = 0; i < 8; i++) {
            unsigned h = f2tf(aval[i]);
            Ah[lr*GSTR + lk + i] = h;
            Al[lr*GSTR + lk + i] = f2tf(aval[i] - __uint_as_float(h));
            unsigned g = f2tf(wval[i]);
            Bh[lr*GSTR + lk + i] = g;
            Bl[lr*GSTR + lk + i] = f2tf(wval[i] - __uint_as_float(g));
        }
        __syncthreads();

        #pragma unroll
        for (int ks = 0; ks < 2; ks++) {
            int k0 = ks*8 + (lane & 3);
            unsigned ah[4][4], al_[4][4], bh[4][2], bl[4][2];
            #pragma unroll
            for (int mt = 0; mt < 4; mt++) {
                int r = wm + mt*16 + (lane >> 2);
                ah[mt][0] = Ah[r*GSTR + k0];       ah[mt][1] = Ah[(r+8)*GSTR + k0];
                ah[mt][2] = Ah[r*GSTR + k0 + 4];   ah[mt][3] = Ah[(r+8)*GSTR + k0 + 4];
                al_[mt][0] = Al[r*GSTR + k0];      al_[mt][1] = Al[(r+8)*GSTR + k0];
                al_[mt][2] = Al[r*GSTR + k0 + 4];  al_[mt][3] = Al[(r+8)*GSTR + k0 + 4];
            }
            #pragma unroll
            for (int nt = 0; nt < 4; nt++) {
                int cn = wn + nt*8 + (lane >> 2);
                bh[nt][0] = Bh[cn*GSTR + k0];      bh[nt][1] = Bh[cn*GSTR + k0 + 4];
                bl[nt][0] = Bl[cn*GSTR + k0];      bl[nt][1] = Bl[cn*GSTR + k0 + 4];
            }
            #pragma unroll
            for (int mt = 0; mt < 4; mt++)
                #pragma unroll
                for (int nt = 0; nt < 4; nt++) {
                    mma8(acc[mt*4+nt], ah[mt],  bh[nt]);
                    mma8(acc[mt*4+nt], ah[mt],  bl[nt]);
                    mma8(acc[mt*4+nt], al_[mt], bh[nt]);
                }
        }
        __syncthreads();
    }

    #pragma unroll
    for (int mt = 0; mt < 4; mt++) {
        int row = m0 + wm + mt*16 + (lane >> 2);
        #pragma unroll
        for (int nt = 0; nt < 4; nt++) {
            int col = n0 + wn + nt*8 + (lane & 3)*2;
            float b0 = __ldg(bias + col), b1 = __ldg(bias + col + 1);
            float2 v;
            v.x = acc[mt*4+nt][0] + b0; v.y = acc[mt*4+nt][1] + b1;
            *(float2*)(C + (size_t)row * N + col) = v;
            v.x = acc[mt*4+nt][2] + b0; v.y = acc[mt*4+nt][3] + b1;
            *(float2*)(C + (size_t)(row + 8) * N + col) = v;
        }
    }
}

// ---------------------------------------------------------------------------
// mean over strata: mean_n(a @ Ws[n]^T + bs[n]) == a @ mean(Ws)^T + mean(bs)
// ---------------------------------------------------------------------------
__global__ void avg_kernel(const float* __restrict__ Ws, const float* __restrict__ bs)
{
    int i = blockIdx.x * 256 + threadIdx.x;
    if (i < H * H)
        g_wavg[i] = (Ws[i] + Ws[i + H*H] + Ws[i + 2*H*H]) * (1.0f/3.0f);
    if (i < H)
        g_bavg[i] = (bs[i] + bs[i + H] + bs[i + 2*H]) * (1.0f/3.0f);
}

// ---------------------------------------------------------------------------
// Flash attention with tf32 mma. One CTA = 64 q-rows of one (b,h); 4 warps,
// each warp owns 16 rows. S: Q(split) @ K(split)^T, 3 passes. Softmax in
// accumulator layout. P stored tf32 (single), PV: P @ (Vhi + Vlo), 2 passes.
// Smem stride 76 words -> conflict-free fragment loads.
// ---------------------------------------------------------------------------
#define ASTR 76
#define ATTN_SMEM (5*64*ASTR*4)

__global__ __launch_bounds__(128) void attn3(
    const float* __restrict__ q, const float* __restrict__ k,
    const float* __restrict__ v, float* __restrict__ out)
{
    extern __shared__ unsigned smu[];
    unsigned* Ksh = smu;
    unsigned* Ksl = Ksh + 64*ASTR;
    unsigned* Vth = Ksl + 64*ASTR;
    unsigned* Vtl = Vth + 64*ASTR;
    unsigned* Psu = Vtl + 64*ASTR;
    float*    Psf = (float*)Psu;

    int t = threadIdx.x, lane = t & 31, warp = t >> 5;
    int qb = blockIdx.x, h = blockIdx.y, b = blockIdx.z;
    int lrow = t >> 1;            // 0..63
    int lseg = (t & 1) * 32;      // 0 or 32
    const float scale = 0.125f;   // 1/sqrt(64)

    // stage Q (pre-scaled) into Psf
    {
        const float* qg = q + (size_t)(b*SEQ + qb*64 + lrow) * H + h*HD + lseg;
        #pragma unroll
        for (int i = 0; i < 8; i++) {
            float4 v4 = *(const float4*)(qg + i*4);
            Psf[lrow*ASTR + lseg + i*4 + 0] = v4.x * scale;
            Psf[lrow*ASTR + lseg + i*4 + 1] = v4.y * scale;
            Psf[lrow*ASTR + lseg + i*4 + 2] = v4.z * scale;
            Psf[lrow*ASTR + lseg + i*4 + 3] = v4.w * scale;
        }
    }
    __syncthreads();

    // persistent Q fragments (hi/lo)
    int r = warp*16 + (lane >> 2);
    unsigned qh[8][4], ql[8][4];
    #pragma unroll
    for (int ks = 0; ks < 8; ks++) {
        int k0 = ks*8 + (lane & 3);
        float v0 = Psf[r*ASTR + k0];
        float v1 = Psf[(r+8)*ASTR + k0];
        float v2 = Psf[r*ASTR + k0 + 4];
        float v3 = Psf[(r+8)*ASTR + k0 + 4];
        qh[ks][0] = f2tf(v0); ql[ks][0] = f2tf(v0 - __uint_as_float(qh[ks][0]));
        qh[ks][1] = f2tf(v1); ql[ks][1] = f2tf(v1 - __uint_as_float(qh[ks][1]));
        qh[ks][2] = f2tf(v2); ql[ks][2] = f2tf(v2 - __uint_as_float(qh[ks][2]));
        qh[ks][3] = f2tf(v3); ql[ks][3] = f2tf(v3 - __uint_as_float(qh[ks][3]));
    }

    float o[8][4];
    #pragma unroll
    for (int i = 0; i < 8; i++)
        #pragma unroll
        for (int j = 0; j < 4; j++) o[i][j] = 0.0f;
    float m0 = -1e30f, m1 = -1e30f, l0 = 0.0f, l1 = 0.0f;

    for (int kb = 0; kb < SEQ/64; kb++) {
        __syncthreads();   // everyone done with prior K/V/P tiles (and Q frags loaded)
        {
            const float* kg = k + (size_t)(b*SEQ + kb*64 + lrow) * H + h*HD + lseg;
            const float* vg = v + (size_t)(b*SEQ + kb*64 + lrow) * H + h*HD + lseg;
            #pragma unroll
            for (int i = 0; i < 8; i++) {
                float4 kv4 = *(const float4*)(kg + i*4);
                float4 vv4 = *(const float4*)(vg + i*4);
                float ka[4] = {kv4.x, kv4.y, kv4.z, kv4.w};
                float va[4] = {vv4.x, vv4.y, vv4.z, vv4.w};
                #pragma unroll
                for (int j = 0; j < 4; j++) {
                    int c = lseg + i*4 + j;
                    unsigned hh = f2tf(ka[j]);
                    Ksh[lrow*ASTR + c] = hh;
                    Ksl[lrow*ASTR + c] = f2tf(ka[j] - __uint_as_float(hh));
                    unsigned vh = f2tf(va[j]);
                    Vth[c*ASTR + lrow] = vh;                 // transposed [d][kv]
                    Vtl[c*ASTR + lrow] = f2tf(va[j] - __uint_as_float(vh));
                }
            }
        }
        __syncthreads();

        // S = Q @ K^T (3-pass split tf32)
        float s[8][4];
        #pragma unroll
        for (int i = 0; i < 8; i++)
            #pragma unroll
            for (int j = 0; j < 4; j++) s[i][j] = 0.0f;

        #pragma unroll
        for (int ks = 0; ks < 8; ks++) {
            int k0 = ks*8 + (lane & 3);
            unsigned bh[8][2], bl[8][2];
            #pragma unroll
            for (int nt = 0; nt < 8; nt++) {
                int cn = nt*8 + (lane >> 2);
                bh[nt][0] = Ksh[cn*ASTR + k0]; bh[nt][1] = Ksh[cn*ASTR + k0 + 4];
                bl[nt][0] = Ksl[cn*ASTR + k0]; bl[nt][1] = Ksl[cn*ASTR + k0 + 4];
            }
            #pragma unroll
            for (int nt = 0; nt < 8; nt++) {
                mma8(s[nt], qh[ks], bh[nt]);
                mma8(s[nt], qh[ks], bl[nt]);
                mma8(s[nt], ql[ks], bh[nt]);
            }
        }

        // online softmax (rows r and r+8; 4 lanes per row -> shfl_xor 1,2)
        float mx0 = -1e30f, mx1 = -1e30f;
        #pragma unroll
        for (int nt = 0; nt < 8; nt++) {
            mx0 = fmaxf(mx0, fmaxf(s[nt][0], s[nt][1]));
            mx1 = fmaxf(mx1, fmaxf(s[nt][2], s[nt][3]));
        }
        mx0 = fmaxf(mx0, __shfl_xor_sync(0xffffffffu, mx0, 1));
        mx0 = fmaxf(mx0, __shfl_xor_sync(0xffffffffu, mx0, 2));
        mx1 = fmaxf(mx1, __shfl_xor_sync(0xffffffffu, mx1, 1));
        mx1 = fmaxf(mx1, __shfl_xor_sync(0xffffffffu, mx1, 2));
        float nm0 = fmaxf(m0, mx0), nm1 = fmaxf(m1, mx1);
        float a0 = __expf(m0 - nm0), a1 = __expf(m1 - nm1);

        float sum0 = 0.0f, sum1 = 0.0f;
        #pragma unroll
        for (int nt = 0; nt < 8; nt++) {
            s[nt][0] = __expf(s[nt][0] - nm0); sum0 += s[nt][0];
            s[nt][1] = __expf(s[nt][1] - nm0); sum0 += s[nt][1];
            s[nt][2] = __expf(s[nt][2] - nm1); sum1 += s[nt][2];
            s[nt][3] = __expf(s[nt][3] - nm1); sum1 += s[nt][3];
        }
        sum0 += __shfl_xor_sync(0xffffffffu, sum0, 1);
        sum0 += __shfl_xor_sync(0xffffffffu, sum0, 2);
        sum1 += __shfl_xor_sync(0xffffffffu, sum1, 1);
        sum1 += __shfl_xor_sync(0xffffffffu, sum1, 2);
        l0 = l0*a0 + sum0;  l1 = l1*a1 + sum1;
        m0 = nm0;           m1 = nm1;
        #pragma unroll
        for (int nt = 0; nt < 8; nt++) {
            o[nt][0] *= a0; o[nt][1] *= a0;
            o[nt][2] *= a1; o[nt][3] *= a1;
        }

        // write P (tf32). Rows r,r+8 are warp-private -> syncwarp suffices.
        #pragma unroll
        for (int nt = 0; nt < 8; nt++) {
            int col = nt*8 + (lane & 3)*2;
            Psu[r*ASTR + col]         = f2tf(s[nt][0]);
            Psu[r*ASTR + col + 1]     = f2tf(s[nt][1]);
            Psu[(r+8)*ASTR + col]     = f2tf(s[nt][2]);
            Psu[(r+8)*ASTR + col + 1] = f2tf(s[nt][3]);
        }
        __syncwarp();

        // O += P @ V (2-pass: V hi + V lo)
        #pragma unroll
        for (int ks = 0; ks < 8; ks++) {
            int k0 = ks*8 + (lane & 3);
            unsigned ap[4];
            ap[0] = Psu[r*ASTR + k0];      ap[1] = Psu[(r+8)*ASTR + k0];
            ap[2] = Psu[r*ASTR + k0 + 4];  ap[3] = Psu[(r+8)*ASTR + k0 + 4];
            #pragma unroll
            for (int nt = 0; nt < 8; nt++) {
                int cn = nt*8 + (lane >> 2);
                unsigned bv[2]  = {Vth[cn*ASTR + k0], Vth[cn*ASTR + k0 + 4]};
                unsigned bvl[2] = {Vtl[cn*ASTR + k0], Vtl[cn*ASTR + k0 + 4]};
                mma8(o[nt], ap, bv);
                mma8(o[nt], ap, bvl);
            }
        }
    }

    float inv0 = 1.0f / l0, inv1 = 1.0f / l1;
    size_t gr0 = (size_t)(b*SEQ + qb*64 + r) * H + h*HD;
    size_t gr1 = (size_t)(b*SEQ + qb*64 + r + 8) * H + h*HD;
    int col = (lane & 3)*2;
    #pragma unroll
    for (int nt = 0; nt < 8; nt++) {
        float2 v0 = {o[nt][0]*inv0, o[nt][1]*inv0};
        *(float2*)(out + gr0 + nt*8 + col) = v0;
        float2 v1 = {o[nt][2]*inv1, o[nt][3]*inv1};
        *(float2*)(out + gr1 + nt*8 + col) = v1;
    }
}

// ---------------------------------------------------------------------------
extern "C" void kernel_launch(void* const* d_in, const int* in_sizes, int n_in,
                              void* d_out, int out_size)
{
    const float* x  = (const float*)d_in[0];
    const float* Wq = (const float*)d_in[1];
    const float* bq = (const float*)d_in[2];
    const float* Wk = (const float*)d_in[3];
    const float* bk = (const float*)d_in[4];
    const float* Wv = (const float*)d_in[5];
    const float* bv = (const float*)d_in[6];
    const float* Ws = (const float*)d_in[7];
    const float* bs = (const float*)d_in[8];
    const float* Wo = (const float*)d_in[9];
    const float* bo = (const float*)d_in[10];

    float *qp, *kp, *vp, *attp, *enhp, *wavgp, *bavgp;
    cudaGetSymbolAddress((void**)&qp,    g_q);
    cudaGetSymbolAddress((void**)&kp,    g_k);
    cudaGetSymbolAddress((void**)&vp,    g_v);
    cudaGetSymbolAddress((void**)&attp,  g_att);
    cudaGetSymbolAddress((void**)&enhp,  g_enh);
    cudaGetSymbolAddress((void**)&wavgp, g_wavg);
    cudaGetSymbolAddress((void**)&bavgp, g_bavg);

    cudaFuncSetAttribute(attn3,
                         cudaFuncAttributeMaxDynamicSharedMemorySize, ATTN_SMEM);

    dim3 gg(H / 128, ROWS / 128);   // 8 x 32

    gemm3<<<gg, 256>>>(x, Wq, bq, qp, ROWS, H, H);
    gemm3<<<gg, 256>>>(x, Wk, bk, kp, ROWS, H, H);
    gemm3<<<gg, 256>>>(x, Wv, bv, vp, ROWS, H, H);

    attn3<<<dim3(SEQ/64, NHEADS, BATCH), 128, ATTN_SMEM>>>(qp, kp, vp, attp);

    avg_kernel<<<(H*H + 255) / 256, 256>>>(Ws, bs);

    gemm3<<<gg, 256>>>(attp, wavgp, bavgp, enhp, ROWS, H, H);
    gemm3<<<gg, 256>>>(enhp, Wo, bo, (float*)d_out, ROWS, H, H);
}

// round 3
// speedup vs baseline: 3.0528x; 1.6417x over previous
#include <cuda_runtime.h>
#include <cuda_bf16.h>
#include <math.h>

#define H 1024
#define NHEADS 16
#define HD 64
#define SEQ 2048
#define BATCH 2
#define ROWS (BATCH*SEQ)   // 4096

// Scratch (device globals: allocation-free per harness rules)
__device__ float g_att[ROWS*H];
__device__ float g_enh[ROWS*H];
__device__ float g_wavg[H*H];
__device__ float g_bavg[H];
__device__ __nv_bfloat16 g_qh[ROWS*H];
__device__ __nv_bfloat16 g_ql[ROWS*H];
__device__ __nv_bfloat16 g_kh[ROWS*H];
__device__ __nv_bfloat16 g_kl[ROWS*H];
__device__ __nv_bfloat16 g_vh[ROWS*H];
__device__ __nv_bfloat16 g_vl[ROWS*H];

// ---------------------------------------------------------------------------
__device__ __forceinline__ unsigned smaddr(const void* p) {
    return (unsigned)__cvta_generic_to_shared(p);
}
__device__ __forceinline__ void ldsm4(unsigned& r0, unsigned& r1, unsigned& r2,
                                      unsigned& r3, unsigned a) {
    asm volatile("ldmatrix.sync.aligned.m8n8.x4.shared.b16 {%0,%1,%2,%3}, [%4];"
                 : "=r"(r0), "=r"(r1), "=r"(r2), "=r"(r3) : "r"(a));
}
__device__ __forceinline__ void ldsm4t(unsigned& r0, unsigned& r1, unsigned& r2,
                                       unsigned& r3, unsigned a) {
    asm volatile("ldmatrix.sync.aligned.m8n8.x4.trans.shared.b16 {%0,%1,%2,%3}, [%4];"
                 : "=r"(r0), "=r"(r1), "=r"(r2), "=r"(r3) : "r"(a));
}
__device__ __forceinline__ void mma16(float* c, const unsigned* a, const unsigned* b) {
    asm volatile(
        "mma.sync.aligned.m16n8k16.row.col.f32.bf16.bf16.f32 "
        "{%0,%1,%2,%3}, {%4,%5,%6,%7}, {%8,%9}, {%0,%1,%2,%3};"
        : "+f"(c[0]), "+f"(c[1]), "+f"(c[2]), "+f"(c[3])
        : "r"(a[0]), "r"(a[1]), "r"(a[2]), "r"(a[3]), "r"(b[0]), "r"(b[1]));
}
__device__ __forceinline__ void cpa16(unsigned dst, const void* src) {
    asm volatile("cp.async.ca.shared.global [%0], [%1], 16;" :: "r"(dst), "l"(src));
}
__device__ __forceinline__ void split2(float x0, float x1, unsigned& hi, unsigned& lo) {
    __nv_bfloat16 h0 = __float2bfloat16(x0);
    __nv_bfloat16 h1 = __float2bfloat16(x1);
    __nv_bfloat16 e0 = __float2bfloat16(x0 - __bfloat162float(h0));
    __nv_bfloat16 e1 = __float2bfloat16(x1 - __bfloat162float(h1));
    unsigned short u0 = *(unsigned short*)&h0, u1 = *(unsigned short*)&h1;
    unsigned short v0 = *(unsigned short*)&e0, v1 = *(unsigned short*)&e1;
    hi = ((unsigned)u1 << 16) | u0;
    lo = ((unsigned)v1 << 16) | v0;
}

// ---------------------------------------------------------------------------
// C[M,N] = (A[M,K] @ W[N,K]^T + bias)*scale.  3xBF16 split, m16n8k16.
// BM=BN=128, BK=32, 256 thr (8 warps 2x4, warp 64x32). Reg-prefetch pipeline.
// OUTMODE 0: fp32 C.  OUTMODE 1: bf16 hi/lo split outputs.
// ---------------------------------------------------------------------------
#define GSTR 20   // words per row (16 data + 4 pad); rows step 20 banks
template<int OUTMODE>
__global__ __launch_bounds__(256) void gemm_bf3(
    const float* __restrict__ A, const float* __restrict__ W,
    const float* __restrict__ bias, float* __restrict__ C,
    __nv_bfloat16* __restrict__ Chi, __nv_bfloat16* __restrict__ Clo,
    float scale, int M, int N, int K)
{
    __shared__ unsigned Ah[128*GSTR], Al[128*GSTR], Bh[128*GSTR], Bl[128*GSTR];
    const int t = threadIdx.x, lane = t & 31, warp = t >> 5;
    const int wm = (warp >> 2) * 64, wn = (warp & 3) * 32;
    const int m0 = blockIdx.y * 128, n0 = blockIdx.x * 128;

    float acc[16][4];
    #pragma unroll
    for (int i = 0; i < 16; i++)
        #pragma unroll
        for (int j = 0; j < 4; j++) acc[i][j] = 0.0f;

    const int lr = t >> 1, half = t & 1;
    const float* Ag = A + (size_t)(m0 + lr) * K + half * 16;
    const float* Wg = W + (size_t)(n0 + lr) * K + half * 16;
    const int sw = lr * GSTR + half * 8;

    float4 pa[4], pw[4];
    #pragma unroll
    for (int i = 0; i < 4; i++) {
        pa[i] = *(const float4*)(Ag + i * 4);
        pw[i] = *(const float4*)(Wg + i * 4);
    }

    const int NB = K / 32;
    for (int bi = 0; bi < NB; bi++) {
        #pragma unroll
        for (int i = 0; i < 4; i++) {
            unsigned h, l;
            split2(pa[i].x, pa[i].y, h, l); Ah[sw + i*2]   = h; Al[sw + i*2]   = l;
            split2(pa[i].z, pa[i].w, h, l); Ah[sw + i*2+1] = h; Al[sw + i*2+1] = l;
            split2(pw[i].x, pw[i].y, h, l); Bh[sw + i*2]   = h; Bl[sw + i*2]   = l;
            split2(pw[i].z, pw[i].w, h, l); Bh[sw + i*2+1] = h; Bl[sw + i*2+1] = l;
        }
        __syncthreads();
        if (bi + 1 < NB) {
            int off = (bi + 1) * 32;
            #pragma unroll
            for (int i = 0; i < 4; i++) {
                pa[i] = *(const float4*)(Ag + off + i * 4);
                pw[i] = *(const float4*)(Wg + off + i * 4);
            }
        }
        #pragma unroll
        for (int ks = 0; ks < 2; ks++) {
            const int arow = ((lane >> 3) & 1) * 8 + (lane & 7);
            const int aw   = ks * 8 + (lane >> 4) * 4;
            unsigned ah[4][4], am[4][4];
            #pragma unroll
            for (int mt = 0; mt < 4; mt++) {
                int r = (wm + mt*16 + arow) * GSTR + aw;
                ldsm4(ah[mt][0], ah[mt][1], ah[mt][2], ah[mt][3], smaddr(&Ah[r]));
                ldsm4(am[mt][0], am[mt][1], am[mt][2], am[mt][3], smaddr(&Al[r]));
            }
            const int brow = ((lane >> 4) & 1) * 8 + (lane & 7);
            const int bw   = ks * 8 + ((lane >> 3) & 1) * 4;
            unsigned bh[2][4], bm[2][4];
            #pragma unroll
            for (int np = 0; np < 2; np++) {
                int r = (wn + np*16 + brow) * GSTR + bw;
                ldsm4(bh[np][0], bh[np][1], bh[np][2], bh[np][3], smaddr(&Bh[r]));
                ldsm4(bm[np][0], bm[np][1], bm[np][2], bm[np][3], smaddr(&Bl[r]));
            }
            #pragma unroll
            for (int mt = 0; mt < 4; mt++)
                #pragma unroll
                for (int nt = 0; nt < 4; nt++) {
                    unsigned* bhp = &bh[nt >> 1][(nt & 1) * 2];
                    unsigned* blp = &bm[nt >> 1][(nt & 1) * 2];
                    mma16(acc[mt*4+nt], ah[mt], bhp);
                    mma16(acc[mt*4+nt], ah[mt], blp);
                    mma16(acc[mt*4+nt], am[mt], bhp);
                }
        }
        __syncthreads();
    }

    #pragma unroll
    for (int mt = 0; mt < 4; mt++) {
        int row = m0 + wm + mt*16 + (lane >> 2);
        #pragma unroll
        for (int nt = 0; nt < 4; nt++) {
            int col = n0 + wn + nt*8 + (lane & 3) * 2;
            float b0 = __ldg(bias + col), b1 = __ldg(bias + col + 1);
            float* a = acc[mt*4+nt];
            float v00 = (a[0] + b0) * scale, v01 = (a[1] + b1) * scale;
            float v10 = (a[2] + b0) * scale, v11 = (a[3] + b1) * scale;
            if (OUTMODE == 0) {
                float2 u;
                u.x = v00; u.y = v01; *(float2*)(C + (size_t)row * N + col) = u;
                u.x = v10; u.y = v11; *(float2*)(C + (size_t)(row + 8) * N + col) = u;
            } else {
                unsigned h, l;
                split2(v00, v01, h, l);
                *(unsigned*)(Chi + (size_t)row * N + col) = h;
                *(unsigned*)(Clo + (size_t)row * N + col) = l;
                split2(v10, v11, h, l);
                *(unsigned*)(Chi + (size_t)(row + 8) * N + col) = h;
                *(unsigned*)(Clo + (size_t)(row + 8) * N + col) = l;
            }
        }
    }
}

// ---------------------------------------------------------------------------
__global__ void avg_kernel(const float* __restrict__ Ws, const float* __restrict__ bs)
{
    int i = blockIdx.x * 256 + threadIdx.x;
    if (i < H * H)
        g_wavg[i] = (Ws[i] + Ws[i + H*H] + Ws[i + 2*H*H]) * (1.0f/3.0f);
    if (i < H)
        g_bavg[i] = (bs[i] + bs[i + H] + bs[i + 2*H]) * (1.0f/3.0f);
}

// ---------------------------------------------------------------------------
// Flash attention, 3xBF16 mma, pre-split inputs, cp.async double-buffered K/V.
// CTA = 64 q-rows of one (b,h), 4 warps (16 rows each). NT=32 kv tiles of 64.
// ---------------------------------------------------------------------------
#define ASTR 36                 // words per 64-bf16 row (32 data + 4 pad)
#define TILE_W (64*ASTR)        // 2304 words
#define ATTN_SMEM (10*TILE_W*4) // 2 bufs x 4 arrays + Ph + Pl = 92160 B

__global__ __launch_bounds__(128) void attn_bf3(
    const __nv_bfloat16* __restrict__ qhi, const __nv_bfloat16* __restrict__ qlo,
    const __nv_bfloat16* __restrict__ khi, const __nv_bfloat16* __restrict__ klo,
    const __nv_bfloat16* __restrict__ vhi, const __nv_bfloat16* __restrict__ vlo,
    float* __restrict__ out)
{
    extern __shared__ unsigned smu[];
    unsigned* bufs = smu;            // [2][4][TILE_W]: Kh,Kl,Vh,Vl per buffer
    unsigned* Ph   = smu + 8*TILE_W;
    unsigned* Pl   = Ph + TILE_W;

    const int t = threadIdx.x, lane = t & 31, warp = t >> 5;
    const int qb = blockIdx.x, h = blockIdx.y, b = blockIdx.z;
    const int lrow = t >> 1, cb = (t & 1) * 4;   // loader: row + 4 chunks of 16B
    const int NT = SEQ / 64;

    // stage Q (pre-scaled, pre-split) into Ph/Pl
    {
        size_t qoff = ((size_t)(b*SEQ + qb*64 + lrow)) * H + h*HD + cb*8;
        unsigned d = lrow * ASTR + cb * 4;
        #pragma unroll
        for (int i = 0; i < 4; i++) {
            cpa16(smaddr(&Ph[d + i*4]), qhi + qoff + i*8);
            cpa16(smaddr(&Pl[d + i*4]), qlo + qoff + i*8);
        }
        asm volatile("cp.async.commit_group;");
    }
    // issue KV tile 0
    {
        size_t base = ((size_t)(b*SEQ + lrow)) * H + h*HD + cb*8;
        unsigned d = lrow * ASTR + cb * 4;
        #pragma unroll
        for (int i = 0; i < 4; i++) {
            cpa16(smaddr(&bufs[0*TILE_W + d + i*4]), khi + base + i*8);
            cpa16(smaddr(&bufs[1*TILE_W + d + i*4]), klo + base + i*8);
            cpa16(smaddr(&bufs[2*TILE_W + d + i*4]), vhi + base + i*8);
            cpa16(smaddr(&bufs[3*TILE_W + d + i*4]), vlo + base + i*8);
        }
        asm volatile("cp.async.commit_group;");
    }

    asm volatile("cp.async.wait_group 1;");   // Q ready
    __syncthreads();

    // persistent Q fragments
    unsigned qh[4][4], ql[4][4];
    {
        const int arow = warp*16 + ((lane >> 3) & 1) * 8 + (lane & 7);
        #pragma unroll
        for (int ks = 0; ks < 4; ks++) {
            int w = ks * 8 + (lane >> 4) * 4;
            ldsm4(qh[ks][0], qh[ks][1], qh[ks][2], qh[ks][3], smaddr(&Ph[arow*ASTR + w]));
            ldsm4(ql[ks][0], ql[ks][1], ql[ks][2], ql[ks][3], smaddr(&Pl[arow*ASTR + w]));
        }
    }

    float o[8][4];
    #pragma unroll
    for (int i = 0; i < 8; i++)
        #pragma unroll
        for (int j = 0; j < 4; j++) o[i][j] = 0.0f;
    float m0 = -1e30f, m1 = -1e30f, l0 = 0.0f, l1 = 0.0f;
    const int r = warp*16 + (lane >> 2);

    for (int kb = 0; kb < NT; kb++) {
        if (kb + 1 < NT) {
            size_t base = ((size_t)(b*SEQ + (kb+1)*64 + lrow)) * H + h*HD + cb*8;
            unsigned* B = bufs + ((kb+1) & 1) * 4 * TILE_W;
            unsigned d = lrow * ASTR + cb * 4;
            #pragma unroll
            for (int i = 0; i < 4; i++) {
                cpa16(smaddr(&B[0*TILE_W + d + i*4]), khi + base + i*8);
                cpa16(smaddr(&B[1*TILE_W + d + i*4]), klo + base + i*8);
                cpa16(smaddr(&B[2*TILE_W + d + i*4]), vhi + base + i*8);
                cpa16(smaddr(&B[3*TILE_W + d + i*4]), vlo + base + i*8);
            }
            asm volatile("cp.async.commit_group;");
            asm volatile("cp.async.wait_group 1;");
        } else {
            asm volatile("cp.async.wait_group 0;");
        }
        __syncthreads();

        unsigned* Kh = bufs + (kb & 1) * 4 * TILE_W;
        unsigned* Kl = Kh + TILE_W;
        unsigned* Vh = Kh + 2*TILE_W;
        unsigned* Vl = Kh + 3*TILE_W;

        // S = Q @ K^T  (3-pass)
        float s[8][4];
        #pragma unroll
        for (int i = 0; i < 8; i++)
            #pragma unroll
            for (int j = 0; j < 4; j++) s[i][j] = 0.0f;

        #pragma unroll
        for (int ks = 0; ks < 4; ks++) {
            const int brow = ((lane >> 4) & 1) * 8 + (lane & 7);
            const int bw   = ks * 8 + ((lane >> 3) & 1) * 4;
            unsigned bh[4][4], bm[4][4];
            #pragma unroll
            for (int np = 0; np < 4; np++) {
                int rr = (np*16 + brow) * ASTR + bw;
                ldsm4(bh[np][0], bh[np][1], bh[np][2], bh[np][3], smaddr(&Kh[rr]));
                ldsm4(bm[np][0], bm[np][1], bm[np][2], bm[np][3], smaddr(&Kl[rr]));
            }
            #pragma unroll
            for (int nt = 0; nt < 8; nt++) {
                unsigned* bhp = &bh[nt >> 1][(nt & 1) * 2];
                unsigned* blp = &bm[nt >> 1][(nt & 1) * 2];
                mma16(s[nt], qh[ks], bhp);
                mma16(s[nt], qh[ks], blp);
                mma16(s[nt], ql[ks], bhp);
            }
        }

        // online softmax (rows r, r+8; 4 lanes per row)
        float mx0 = -1e30f, mx1 = -1e30f;
        #pragma unroll
        for (int nt = 0; nt < 8; nt++) {
            mx0 = fmaxf(mx0, fmaxf(s[nt][0], s[nt][1]));
            mx1 = fmaxf(mx1, fmaxf(s[nt][2], s[nt][3]));
        }
        mx0 = fmaxf(mx0, __shfl_xor_sync(0xffffffffu, mx0, 1));
        mx0 = fmaxf(mx0, __shfl_xor_sync(0xffffffffu, mx0, 2));
        mx1 = fmaxf(mx1, __shfl_xor_sync(0xffffffffu, mx1, 1));
        mx1 = fmaxf(mx1, __shfl_xor_sync(0xffffffffu, mx1, 2));
        float nm0 = fmaxf(m0, mx0), nm1 = fmaxf(m1, mx1);
        float a0 = __expf(m0 - nm0), a1 = __expf(m1 - nm1);

        float sum0 = 0.0f, sum1 = 0.0f;
        #pragma unroll
        for (int nt = 0; nt < 8; nt++) {
            s[nt][0] = __expf(s[nt][0] - nm0); sum0 += s[nt][0];
            s[nt][1] = __expf(s[nt][1] - nm0); sum0 += s[nt][1];
            s[nt][2] = __expf(s[nt][2] - nm1); sum1 += s[nt][2];
            s[nt][3] = __expf(s[nt][3] - nm1); sum1 += s[nt][3];
        }
        sum0 += __shfl_xor_sync(0xffffffffu, sum0, 1);
        sum0 += __shfl_xor_sync(0xffffffffu, sum0, 2);
        sum1 += __shfl_xor_sync(0xffffffffu, sum1, 1);
        sum1 += __shfl_xor_sync(0xffffffffu, sum1, 2);
        l0 = l0*a0 + sum0;  l1 = l1*a1 + sum1;
        m0 = nm0;           m1 = nm1;
        #pragma unroll
        for (int nt = 0; nt < 8; nt++) {
            o[nt][0] *= a0; o[nt][1] *= a0;
            o[nt][2] *= a1; o[nt][3] *= a1;
        }

        // write P split (warp-private rows r, r+8)
        #pragma unroll
        for (int nt = 0; nt < 8; nt++) {
            int w = nt*4 + (lane & 3);
            unsigned hh, ll;
            split2(s[nt][0], s[nt][1], hh, ll);
            Ph[r*ASTR + w] = hh;  Pl[r*ASTR + w] = ll;
            split2(s[nt][2], s[nt][3], hh, ll);
            Ph[(r+8)*ASTR + w] = hh;  Pl[(r+8)*ASTR + w] = ll;
        }
        __syncwarp();

        // O += P @ V  (3-pass: ph*vh, pl*vh, ph*vl)
        #pragma unroll
        for (int ks = 0; ks < 4; ks++) {
            unsigned ph[4], pl[4];
            {
                int arow = warp*16 + ((lane >> 3) & 1) * 8 + (lane & 7);
                int w = ks * 8 + (lane >> 4) * 4;
                ldsm4(ph[0], ph[1], ph[2], ph[3], smaddr(&Ph[arow*ASTR + w]));
                ldsm4(pl[0], pl[1], pl[2], pl[3], smaddr(&Pl[arow*ASTR + w]));
            }
            const int vr = ks*16 + ((lane >> 3) & 1) * 8 + (lane & 7);
            unsigned vh[4][4], vm[4][4];
            #pragma unroll
            for (int np = 0; np < 4; np++) {
                int vw = np*8 + (lane >> 4) * 4;
                ldsm4t(vh[np][0], vh[np][1], vh[np][2], vh[np][3], smaddr(&Vh[vr*ASTR + vw]));
                ldsm4t(vm[np][0], vm[np][1], vm[np][2], vm[np][3], smaddr(&Vl[vr*ASTR + vw]));
            }
            #pragma unroll
            for (int nt = 0; nt < 8; nt++) {
                unsigned* bvh = &vh[nt >> 1][(nt & 1) * 2];
                unsigned* bvl = &vm[nt >> 1][(nt & 1) * 2];
                mma16(o[nt], ph, bvh);
                mma16(o[nt], pl, bvh);
                mma16(o[nt], ph, bvl);
            }
        }
        __syncthreads();
    }

    float inv0 = 1.0f / l0, inv1 = 1.0f / l1;
    size_t gr0 = (size_t)(b*SEQ + qb*64 + r) * H + h*HD;
    size_t gr1 = (size_t)(b*SEQ + qb*64 + r + 8) * H + h*HD;
    int col = (lane & 3) * 2;
    #pragma unroll
    for (int nt = 0; nt < 8; nt++) {
        float2 v0 = {o[nt][0]*inv0, o[nt][1]*inv0};
        *(float2*)(out + gr0 + nt*8 + col) = v0;
        float2 v1 = {o[nt][2]*inv1, o[nt][3]*inv1};
        *(float2*)(out + gr1 + nt*8 + col) = v1;
    }
}

// ---------------------------------------------------------------------------
extern "C" void kernel_launch(void* const* d_in, const int* in_sizes, int n_in,
                              void* d_out, int out_size)
{
    const float* x  = (const float*)d_in[0];
    const float* Wq = (const float*)d_in[1];
    const float* bq = (const float*)d_in[2];
    const float* Wk = (const float*)d_in[3];
    const float* bk = (const float*)d_in[4];
    const float* Wv = (const float*)d_in[5];
    const float* bv = (const float*)d_in[6];
    const float* Ws = (const float*)d_in[7];
    const float* bs = (const float*)d_in[8];
    const float* Wo = (const float*)d_in[9];
    const float* bo = (const float*)d_in[10];

    float *attp, *enhp, *wavgp, *bavgp;
    __nv_bfloat16 *qh, *ql, *kh, *kl, *vh, *vl;
    cudaGetSymbolAddress((void**)&attp,  g_att);
    cudaGetSymbolAddress((void**)&enhp,  g_enh);
    cudaGetSymbolAddress((void**)&wavgp, g_wavg);
    cudaGetSymbolAddress((void**)&bavgp, g_bavg);
    cudaGetSymbolAddress((void**)&qh, g_qh);
    cudaGetSymbolAddress((void**)&ql, g_ql);
    cudaGetSymbolAddress((void**)&kh, g_kh);
    cudaGetSymbolAddress((void**)&kl, g_kl);
    cudaGetSymbolAddress((void**)&vh, g_vh);
    cudaGetSymbolAddress((void**)&vl, g_vl);

    cudaFuncSetAttribute(attn_bf3,
                         cudaFuncAttributeMaxDynamicSharedMemorySize, ATTN_SMEM);

    dim3 gg(H / 128, ROWS / 128);   // 8 x 32

    gemm_bf3<1><<<gg, 256>>>(x, Wq, bq, nullptr, qh, ql, 0.125f, ROWS, H, H);
    gemm_bf3<1><<<gg, 256>>>(x, Wk, bk, nullptr, kh, kl, 1.0f,   ROWS, H, H);
    gemm_bf3<1><<<gg, 256>>>(x, Wv, bv, nullptr, vh, vl, 1.0f,   ROWS, H, H);

    attn_bf3<<<dim3(SEQ/64, NHEADS, BATCH), 128, ATTN_SMEM>>>(qh, ql, kh, kl, vh, vl, attp);

    avg_kernel<<<(H*H + 255) / 256, 256>>>(Ws, bs);

    gemm_bf3<0><<<gg, 256>>>(attp, wavgp, bavgp, enhp, nullptr, nullptr, 1.0f, ROWS, H, H);
    gemm_bf3<0><<<gg, 256>>>(enhp, Wo, bo, (float*)d_out, nullptr, nullptr, 1.0f, ROWS, H, H);
}

// round 4
// speedup vs baseline: 3.9712x; 1.3009x over previous
#include <cuda_runtime.h>
#include <cuda_bf16.h>
#include <math.h>

#define H 1024
#define NHEADS 16
#define HD 64
#define SEQ 2048
#define BATCH 2
#define ROWS (BATCH*SEQ)   // 4096

// ---------------- scratch (device globals; allocation-free) ----------------
__device__ __nv_bfloat16 g_xh[ROWS*H],  g_xl[ROWS*H];
__device__ __nv_bfloat16 g_qh[ROWS*H],  g_ql[ROWS*H];
__device__ __nv_bfloat16 g_kh[ROWS*H],  g_kl[ROWS*H];
__device__ __nv_bfloat16 g_vh[ROWS*H],  g_vl[ROWS*H];
__device__ __nv_bfloat16 g_ath[ROWS*H], g_atl[ROWS*H];
__device__ __nv_bfloat16 g_enh_h[ROWS*H], g_enh_l[ROWS*H];
__device__ __nv_bfloat16 g_wqh[H*H], g_wql[H*H];
__device__ __nv_bfloat16 g_wkh[H*H], g_wkl[H*H];
__device__ __nv_bfloat16 g_wvh[H*H], g_wvl[H*H];
__device__ __nv_bfloat16 g_woh[H*H], g_wol[H*H];
__device__ __nv_bfloat16 g_wah[H*H], g_wal[H*H];
__device__ float g_bavg[H];

// ---------------------------------------------------------------------------
__device__ __forceinline__ unsigned smaddr(const void* p) {
    return (unsigned)__cvta_generic_to_shared(p);
}
__device__ __forceinline__ void ldsm4(unsigned& r0, unsigned& r1, unsigned& r2,
                                      unsigned& r3, unsigned a) {
    asm volatile("ldmatrix.sync.aligned.m8n8.x4.shared.b16 {%0,%1,%2,%3}, [%4];"
                 : "=r"(r0), "=r"(r1), "=r"(r2), "=r"(r3) : "r"(a));
}
__device__ __forceinline__ void ldsm4t(unsigned& r0, unsigned& r1, unsigned& r2,
                                       unsigned& r3, unsigned a) {
    asm volatile("ldmatrix.sync.aligned.m8n8.x4.trans.shared.b16 {%0,%1,%2,%3}, [%4];"
                 : "=r"(r0), "=r"(r1), "=r"(r2), "=r"(r3) : "r"(a));
}
__device__ __forceinline__ void mma16(float* c, const unsigned* a, const unsigned* b) {
    asm volatile(
        "mma.sync.aligned.m16n8k16.row.col.f32.bf16.bf16.f32 "
        "{%0,%1,%2,%3}, {%4,%5,%6,%7}, {%8,%9}, {%0,%1,%2,%3};"
        : "+f"(c[0]), "+f"(c[1]), "+f"(c[2]), "+f"(c[3])
        : "r"(a[0]), "r"(a[1]), "r"(a[2]), "r"(a[3]), "r"(b[0]), "r"(b[1]));
}
__device__ __forceinline__ void cpa16(unsigned dst, const void* src) {
    asm volatile("cp.async.ca.shared.global [%0], [%1], 16;" :: "r"(dst), "l"(src));
}
__device__ __forceinline__ void split2(float x0, float x1, unsigned& hi, unsigned& lo) {
    __nv_bfloat16 h0 = __float2bfloat16(x0);
    __nv_bfloat16 h1 = __float2bfloat16(x1);
    __nv_bfloat16 e0 = __float2bfloat16(x0 - __bfloat162float(h0));
    __nv_bfloat16 e1 = __float2bfloat16(x1 - __bfloat162float(h1));
    unsigned short u0 = *(unsigned short*)&h0, u1 = *(unsigned short*)&h1;
    unsigned short v0 = *(unsigned short*)&e0, v1 = *(unsigned short*)&e1;
    hi = ((unsigned)u1 << 16) | u0;
    lo = ((unsigned)v1 << 16) | v0;
}

// ---------------------------------------------------------------------------
// split fp32 -> bf16 hi/lo
// ---------------------------------------------------------------------------
__global__ void split_fp32(const float* __restrict__ src,
                           __nv_bfloat16* __restrict__ hi,
                           __nv_bfloat16* __restrict__ lo, int n)
{
    int i = blockIdx.x * 256 + threadIdx.x;
    if (i < n) {
        float x = src[i];
        __nv_bfloat16 h = __float2bfloat16(x);
        hi[i] = h;
        lo[i] = __float2bfloat16(x - __bfloat162float(h));
    }
}
__global__ void avgsplit_kernel(const float* __restrict__ Ws, const float* __restrict__ bs)
{
    int i = blockIdx.x * 256 + threadIdx.x;
    if (i < H * H) {
        float x = (Ws[i] + Ws[i + H*H] + Ws[i + 2*H*H]) * (1.0f/3.0f);
        __nv_bfloat16 h = __float2bfloat16(x);
        g_wah[i] = h;
        g_wal[i] = __float2bfloat16(x - __bfloat162float(h));
    }
    if (i < H)
        g_bavg[i] = (bs[i] + bs[i + H] + bs[i + 2*H]) * (1.0f/3.0f);
}

// ---------------------------------------------------------------------------
// GEMM on pre-split inputs: C = (Ahi+Alo)[M,K] @ (Bhi+Blo)[N,K]^T + bias, *scale
// 3xBF16 passes. BM=BN=128, BK=32, 256 thr, cp.async double-buffered.
// ---------------------------------------------------------------------------
#define GSTR 20                     // words per 32-bf16 row (16 data + 4 pad)
#define GARR (128*GSTR)             // words per array
#define GEMM_SMEM (2*4*GARR*4)      // 81920 B
template<int OUTMODE>
__global__ __launch_bounds__(256, 2) void gemm_sp(
    const __nv_bfloat16* __restrict__ Ahi, const __nv_bfloat16* __restrict__ Alo,
    const __nv_bfloat16* __restrict__ Bhi, const __nv_bfloat16* __restrict__ Blo,
    const float* __restrict__ bias, float scale,
    float* __restrict__ C,
    __nv_bfloat16* __restrict__ Chi, __nv_bfloat16* __restrict__ Clo,
    int M, int N, int K)
{
    extern __shared__ unsigned gsm[];
    const int t = threadIdx.x, lane = t & 31, warp = t >> 5;
    const int wm = (warp >> 2) * 64, wn = (warp & 3) * 32;
    const int m0 = blockIdx.y * 128, n0 = blockIdx.x * 128;

    float acc[16][4];
    #pragma unroll
    for (int i = 0; i < 16; i++)
        #pragma unroll
        for (int j = 0; j < 4; j++) acc[i][j] = 0.0f;

    const int lr = t >> 1, half = t & 1;
    const size_t arow = (size_t)(m0 + lr) * K + half * 16;
    const size_t brow = (size_t)(n0 + lr) * K + half * 16;
    const int sw = lr * GSTR + half * 8;
    const int NB = K / 32;

    // issue k-block 0 into buffer 0
    {
        unsigned* B0 = gsm;
        cpa16(smaddr(&B0[0*GARR + sw]),     Ahi + arow);
        cpa16(smaddr(&B0[0*GARR + sw + 4]), Ahi + arow + 8);
        cpa16(smaddr(&B0[1*GARR + sw]),     Alo + arow);
        cpa16(smaddr(&B0[1*GARR + sw + 4]), Alo + arow + 8);
        cpa16(smaddr(&B0[2*GARR + sw]),     Bhi + brow);
        cpa16(smaddr(&B0[2*GARR + sw + 4]), Bhi + brow + 8);
        cpa16(smaddr(&B0[3*GARR + sw]),     Blo + brow);
        cpa16(smaddr(&B0[3*GARR + sw + 4]), Blo + brow + 8);
        asm volatile("cp.async.commit_group;");
    }

    for (int bi = 0; bi < NB; bi++) {
        if (bi + 1 < NB) {
            unsigned* Bn = gsm + ((bi + 1) & 1) * 4 * GARR;
            size_t ko = (size_t)(bi + 1) * 32;
            cpa16(smaddr(&Bn[0*GARR + sw]),     Ahi + arow + ko);
            cpa16(smaddr(&Bn[0*GARR + sw + 4]), Ahi + arow + ko + 8);
            cpa16(smaddr(&Bn[1*GARR + sw]),     Alo + arow + ko);
            cpa16(smaddr(&Bn[1*GARR + sw + 4]), Alo + arow + ko + 8);
            cpa16(smaddr(&Bn[2*GARR + sw]),     Bhi + brow + ko);
            cpa16(smaddr(&Bn[2*GARR + sw + 4]), Bhi + brow + ko + 8);
            cpa16(smaddr(&Bn[3*GARR + sw]),     Blo + brow + ko);
            cpa16(smaddr(&Bn[3*GARR + sw + 4]), Blo + brow + ko + 8);
            asm volatile("cp.async.commit_group;");
            asm volatile("cp.async.wait_group 1;");
        } else {
            asm volatile("cp.async.wait_group 0;");
        }
        __syncthreads();

        unsigned* Ah = gsm + (bi & 1) * 4 * GARR;
        unsigned* Al = Ah + GARR;
        unsigned* Bh = Ah + 2*GARR;
        unsigned* Bl = Ah + 3*GARR;

        #pragma unroll
        for (int ks = 0; ks < 2; ks++) {
            const int ar = ((lane >> 3) & 1) * 8 + (lane & 7);
            const int aw = ks * 8 + (lane >> 4) * 4;
            unsigned ah[4][4], am[4][4];
            #pragma unroll
            for (int mt = 0; mt < 4; mt++) {
                int r = (wm + mt*16 + ar) * GSTR + aw;
                ldsm4(ah[mt][0], ah[mt][1], ah[mt][2], ah[mt][3], smaddr(&Ah[r]));
                ldsm4(am[mt][0], am[mt][1], am[mt][2], am[mt][3], smaddr(&Al[r]));
            }
            const int br = ((lane >> 4) & 1) * 8 + (lane & 7);
            const int bw = ks * 8 + ((lane >> 3) & 1) * 4;
            unsigned bh[2][4], bm[2][4];
            #pragma unroll
            for (int np = 0; np < 2; np++) {
                int r = (wn + np*16 + br) * GSTR + bw;
                ldsm4(bh[np][0], bh[np][1], bh[np][2], bh[np][3], smaddr(&Bh[r]));
                ldsm4(bm[np][0], bm[np][1], bm[np][2], bm[np][3], smaddr(&Bl[r]));
            }
            #pragma unroll
            for (int mt = 0; mt < 4; mt++)
                #pragma unroll
                for (int nt = 0; nt < 4; nt++) {
                    unsigned* bhp = &bh[nt >> 1][(nt & 1) * 2];
                    unsigned* blp = &bm[nt >> 1][(nt & 1) * 2];
                    mma16(acc[mt*4+nt], ah[mt], bhp);
                    mma16(acc[mt*4+nt], ah[mt], blp);
                    mma16(acc[mt*4+nt], am[mt], bhp);
                }
        }
        __syncthreads();
    }

    #pragma unroll
    for (int mt = 0; mt < 4; mt++) {
        int row = m0 + wm + mt*16 + (lane >> 2);
        #pragma unroll
        for (int nt = 0; nt < 4; nt++) {
            int col = n0 + wn + nt*8 + (lane & 3) * 2;
            float b0 = __ldg(bias + col), b1 = __ldg(bias + col + 1);
            float* a = acc[mt*4+nt];
            float v00 = (a[0] + b0) * scale, v01 = (a[1] + b1) * scale;
            float v10 = (a[2] + b0) * scale, v11 = (a[3] + b1) * scale;
            if (OUTMODE == 0) {
                float2 u;
                u.x = v00; u.y = v01; *(float2*)(C + (size_t)row * N + col) = u;
                u.x = v10; u.y = v11; *(float2*)(C + (size_t)(row + 8) * N + col) = u;
            } else {
                unsigned h, l;
                split2(v00, v01, h, l);
                *(unsigned*)(Chi + (size_t)row * N + col) = h;
                *(unsigned*)(Clo + (size_t)row * N + col) = l;
                split2(v10, v11, h, l);
                *(unsigned*)(Chi + (size_t)(row + 8) * N + col) = h;
                *(unsigned*)(Clo + (size_t)(row + 8) * N + col) = l;
            }
        }
    }
}

// ---------------------------------------------------------------------------
// Flash attention, 3xBF16, P kept in registers (C-frag == A-frag layout).
// CTA = 64 q-rows of one (b,h), 4 warps. KV double-buffered via cp.async.
// Q staged through buffer 1 (dead after fragment extraction).
// Writes split bf16 output for the following GEMM.
// ---------------------------------------------------------------------------
#define ASTR 36                 // words per 64-bf16 row (32 data + 4 pad)
#define TILE_W (64*ASTR)        // 2304 words
#define ATTN_SMEM (8*TILE_W*4)  // 73728 B

__global__ __launch_bounds__(128, 3) void attn_bf3r(
    const __nv_bfloat16* __restrict__ qhi, const __nv_bfloat16* __restrict__ qlo,
    const __nv_bfloat16* __restrict__ khi, const __nv_bfloat16* __restrict__ klo,
    const __nv_bfloat16* __restrict__ vhi, const __nv_bfloat16* __restrict__ vlo,
    __nv_bfloat16* __restrict__ athi, __nv_bfloat16* __restrict__ atlo)
{
    extern __shared__ unsigned smu[];
    unsigned* bufs = smu;       // [2][4][TILE_W]: Kh,Kl,Vh,Vl

    const int t = threadIdx.x, lane = t & 31, warp = t >> 5;
    const int qb = blockIdx.x, h = blockIdx.y, b = blockIdx.z;
    const int lrow = t >> 1, cb = (t & 1) * 4;
    const int NT = SEQ / 64;
    const unsigned d0 = lrow * ASTR + cb * 4;

    // stage Q into buffer 1 (arrays 0,1)
    {
        size_t qoff = ((size_t)(b*SEQ + qb*64 + lrow)) * H + h*HD + cb*8;
        unsigned* B1 = bufs + 4*TILE_W;
        #pragma unroll
        for (int i = 0; i < 4; i++) {
            cpa16(smaddr(&B1[0*TILE_W + d0 + i*4]), qhi + qoff + i*8);
            cpa16(smaddr(&B1[1*TILE_W + d0 + i*4]), qlo + qoff + i*8);
        }
        asm volatile("cp.async.commit_group;");
    }
    // issue KV tile 0 -> buffer 0
    {
        size_t base = ((size_t)(b*SEQ + lrow)) * H + h*HD + cb*8;
        #pragma unroll
        for (int i = 0; i < 4; i++) {
            cpa16(smaddr(&bufs[0*TILE_W + d0 + i*4]), khi + base + i*8);
            cpa16(smaddr(&bufs[1*TILE_W + d0 + i*4]), klo + base + i*8);
            cpa16(smaddr(&bufs[2*TILE_W + d0 + i*4]), vhi + base + i*8);
            cpa16(smaddr(&bufs[3*TILE_W + d0 + i*4]), vlo + base + i*8);
        }
        asm volatile("cp.async.commit_group;");
    }

    asm volatile("cp.async.wait_group 1;");   // Q ready
    __syncthreads();

    // persistent Q fragments from buffer 1
    unsigned qh[4][4], ql[4][4];
    {
        const int ar = warp*16 + ((lane >> 3) & 1) * 8 + (lane & 7);
        unsigned* B1 = bufs + 4*TILE_W;
        #pragma unroll
        for (int ks = 0; ks < 4; ks++) {
            int w = ks * 8 + (lane >> 4) * 4;
            ldsm4(qh[ks][0], qh[ks][1], qh[ks][2], qh[ks][3],
                  smaddr(&B1[0*TILE_W + ar*ASTR + w]));
            ldsm4(ql[ks][0], ql[ks][1], ql[ks][2], ql[ks][3],
                  smaddr(&B1[1*TILE_W + ar*ASTR + w]));
        }
    }
    __syncthreads();   // buffer 1 free for KV prefetch

    float o[8][4];
    #pragma unroll
    for (int i = 0; i < 8; i++)
        #pragma unroll
        for (int j = 0; j < 4; j++) o[i][j] = 0.0f;
    float m0 = -1e30f, m1 = -1e30f, l0 = 0.0f, l1 = 0.0f;
    const int r = warp*16 + (lane >> 2);

    for (int kb = 0; kb < NT; kb++) {
        if (kb + 1 < NT) {
            size_t base = ((size_t)(b*SEQ + (kb+1)*64 + lrow)) * H + h*HD + cb*8;
            unsigned* Bn = bufs + ((kb+1) & 1) * 4 * TILE_W;
            #pragma unroll
            for (int i = 0; i < 4; i++) {
                cpa16(smaddr(&Bn[0*TILE_W + d0 + i*4]), khi + base + i*8);
                cpa16(smaddr(&Bn[1*TILE_W + d0 + i*4]), klo + base + i*8);
                cpa16(smaddr(&Bn[2*TILE_W + d0 + i*4]), vhi + base + i*8);
                cpa16(smaddr(&Bn[3*TILE_W + d0 + i*4]), vlo + base + i*8);
            }
            asm volatile("cp.async.commit_group;");
            asm volatile("cp.async.wait_group 1;");
        } else {
            asm volatile("cp.async.wait_group 0;");
        }
        __syncthreads();

        unsigned* Kh = bufs + (kb & 1) * 4 * TILE_W;
        unsigned* Kl = Kh + TILE_W;
        unsigned* Vh = Kh + 2*TILE_W;
        unsigned* Vl = Kh + 3*TILE_W;

        // S = Q @ K^T (3-pass)
        float s[8][4];
        #pragma unroll
        for (int i = 0; i < 8; i++)
            #pragma unroll
            for (int j = 0; j < 4; j++) s[i][j] = 0.0f;

        #pragma unroll
        for (int ks = 0; ks < 4; ks++) {
            const int br = ((lane >> 4) & 1) * 8 + (lane & 7);
            const int bw = ks * 8 + ((lane >> 3) & 1) * 4;
            unsigned bh[4][4], bm[4][4];
            #pragma unroll
            for (int np = 0; np < 4; np++) {
                int rr = (np*16 + br) * ASTR + bw;
                ldsm4(bh[np][0], bh[np][1], bh[np][2], bh[np][3], smaddr(&Kh[rr]));
                ldsm4(bm[np][0], bm[np][1], bm[np][2], bm[np][3], smaddr(&Kl[rr]));
            }
            #pragma unroll
            for (int nt = 0; nt < 8; nt++) {
                unsigned* bhp = &bh[nt >> 1][(nt & 1) * 2];
                unsigned* blp = &bm[nt >> 1][(nt & 1) * 2];
                mma16(s[nt], qh[ks], bhp);
                mma16(s[nt], qh[ks], blp);
                mma16(s[nt], ql[ks], bhp);
            }
        }

        // online softmax (rows r, r+8; 4 lanes per row)
        float mx0 = -1e30f, mx1 = -1e30f;
        #pragma unroll
        for (int nt = 0; nt < 8; nt++) {
            mx0 = fmaxf(mx0, fmaxf(s[nt][0], s[nt][1]));
            mx1 = fmaxf(mx1, fmaxf(s[nt][2], s[nt][3]));
        }
        mx0 = fmaxf(mx0, __shfl_xor_sync(0xffffffffu, mx0, 1));
        mx0 = fmaxf(mx0, __shfl_xor_sync(0xffffffffu, mx0, 2));
        mx1 = fmaxf(mx1, __shfl_xor_sync(0xffffffffu, mx1, 1));
        mx1 = fmaxf(mx1, __shfl_xor_sync(0xffffffffu, mx1, 2));
        float nm0 = fmaxf(m0, mx0), nm1 = fmaxf(m1, mx1);
        float a0 = __expf(m0 - nm0), a1 = __expf(m1 - nm1);

        float sum0 = 0.0f, sum1 = 0.0f;
        #pragma unroll
        for (int nt = 0; nt < 8; nt++) {
            s[nt][0] = __expf(s[nt][0] - nm0); sum0 += s[nt][0];
            s[nt][1] = __expf(s[nt][1] - nm0); sum0 += s[nt][1];
            s[nt][2] = __expf(s[nt][2] - nm1); sum1 += s[nt][2];
            s[nt][3] = __expf(s[nt][3] - nm1); sum1 += s[nt][3];
        }
        sum0 += __shfl_xor_sync(0xffffffffu, sum0, 1);
        sum0 += __shfl_xor_sync(0xffffffffu, sum0, 2);
        sum1 += __shfl_xor_sync(0xffffffffu, sum1, 1);
        sum1 += __shfl_xor_sync(0xffffffffu, sum1, 2);
        l0 = l0*a0 + sum0;  l1 = l1*a1 + sum1;
        m0 = nm0;           m1 = nm1;
        #pragma unroll
        for (int nt = 0; nt < 8; nt++) {
            o[nt][0] *= a0; o[nt][1] *= a0;
            o[nt][2] *= a1; o[nt][3] *= a1;
        }

        // O += P @ V, P built directly from S registers (C-frag == A-frag)
        #pragma unroll
        for (int ks = 0; ks < 4; ks++) {
            unsigned ph[4], pl[4];
            split2(s[2*ks][0],   s[2*ks][1],   ph[0], pl[0]);
            split2(s[2*ks][2],   s[2*ks][3],   ph[1], pl[1]);
            split2(s[2*ks+1][0], s[2*ks+1][1], ph[2], pl[2]);
            split2(s[2*ks+1][2], s[2*ks+1][3], ph[3], pl[3]);

            const int vr = ks*16 + ((lane >> 3) & 1) * 8 + (lane & 7);
            unsigned vh[4][4], vm[4][4];
            #pragma unroll
            for (int np = 0; np < 4; np++) {
                int vw = np*8 + (lane >> 4) * 4;
                ldsm4t(vh[np][0], vh[np][1], vh[np][2], vh[np][3], smaddr(&Vh[vr*ASTR + vw]));
                ldsm4t(vm[np][0], vm[np][1], vm[np][2], vm[np][3], smaddr(&Vl[vr*ASTR + vw]));
            }
            #pragma unroll
            for (int nt = 0; nt < 8; nt++) {
                unsigned* bvh = &vh[nt >> 1][(nt & 1) * 2];
                unsigned* bvl = &vm[nt >> 1][(nt & 1) * 2];
                mma16(o[nt], ph, bvh);
                mma16(o[nt], pl, bvh);
                mma16(o[nt], ph, bvl);
            }
        }
        __syncthreads();
    }

    float inv0 = 1.0f / l0, inv1 = 1.0f / l1;
    size_t gr0 = (size_t)(b*SEQ + qb*64 + r) * H + h*HD;
    size_t gr1 = (size_t)(b*SEQ + qb*64 + r + 8) * H + h*HD;
    int col = (lane & 3) * 2;
    #pragma unroll
    for (int nt = 0; nt < 8; nt++) {
        unsigned hh, ll;
        split2(o[nt][0]*inv0, o[nt][1]*inv0, hh, ll);
        *(unsigned*)(athi + gr0 + nt*8 + col) = hh;
        *(unsigned*)(atlo + gr0 + nt*8 + col) = ll;
        split2(o[nt][2]*inv1, o[nt][3]*inv1, hh, ll);
        *(unsigned*)(athi + gr1 + nt*8 + col) = hh;
        *(unsigned*)(atlo + gr1 + nt*8 + col) = ll;
    }
}

// ---------------------------------------------------------------------------
extern "C" void kernel_launch(void* const* d_in, const int* in_sizes, int n_in,
                              void* d_out, int out_size)
{
    const float* x  = (const float*)d_in[0];
    const float* Wq = (const float*)d_in[1];
    const float* bq = (const float*)d_in[2];
    const float* Wk = (const float*)d_in[3];
    const float* bk = (const float*)d_in[4];
    const float* Wv = (const float*)d_in[5];
    const float* bv = (const float*)d_in[6];
    const float* Ws = (const float*)d_in[7];
    const float* bs = (const float*)d_in[8];
    const float* Wo = (const float*)d_in[9];
    const float* bo = (const float*)d_in[10];

    __nv_bfloat16 *xh, *xl, *qh, *ql, *kh, *kl, *vh, *vl, *ath, *atl, *eh, *el;
    __nv_bfloat16 *wqh, *wql, *wkh, *wkl, *wvh, *wvl, *woh, *wol, *wah, *wal;
    float* bavgp;
    cudaGetSymbolAddress((void**)&xh, g_xh);  cudaGetSymbolAddress((void**)&xl, g_xl);
    cudaGetSymbolAddress((void**)&qh, g_qh);  cudaGetSymbolAddress((void**)&ql, g_ql);
    cudaGetSymbolAddress((void**)&kh, g_kh);  cudaGetSymbolAddress((void**)&kl, g_kl);
    cudaGetSymbolAddress((void**)&vh, g_vh);  cudaGetSymbolAddress((void**)&vl, g_vl);
    cudaGetSymbolAddress((void**)&ath, g_ath); cudaGetSymbolAddress((void**)&atl, g_atl);
    cudaGetSymbolAddress((void**)&eh, g_enh_h); cudaGetSymbolAddress((void**)&el, g_enh_l);
    cudaGetSymbolAddress((void**)&wqh, g_wqh); cudaGetSymbolAddress((void**)&wql, g_wql);
    cudaGetSymbolAddress((void**)&wkh, g_wkh); cudaGetSymbolAddress((void**)&wkl, g_wkl);
    cudaGetSymbolAddress((void**)&wvh, g_wvh); cudaGetSymbolAddress((void**)&wvl, g_wvl);
    cudaGetSymbolAddress((void**)&woh, g_woh); cudaGetSymbolAddress((void**)&wol, g_wol);
    cudaGetSymbolAddress((void**)&wah, g_wah); cudaGetSymbolAddress((void**)&wal, g_wal);
    cudaGetSymbolAddress((void**)&bavgp, g_bavg);

    cudaFuncSetAttribute(attn_bf3r,
                         cudaFuncAttributeMaxDynamicSharedMemorySize, ATTN_SMEM);
    cudaFuncSetAttribute(gemm_sp<0>,
                         cudaFuncAttributeMaxDynamicSharedMemorySize, GEMM_SMEM);
    cudaFuncSetAttribute(gemm_sp<1>,
                         cudaFuncAttributeMaxDynamicSharedMemorySize, GEMM_SMEM);

    // pre-split inputs and weights
    split_fp32<<<(ROWS*H + 255)/256, 256>>>(x,  xh,  xl,  ROWS*H);
    split_fp32<<<(H*H + 255)/256, 256>>>(Wq, wqh, wql, H*H);
    split_fp32<<<(H*H + 255)/256, 256>>>(Wk, wkh, wkl, H*H);
    split_fp32<<<(H*H + 255)/256, 256>>>(Wv, wvh, wvl, H*H);
    split_fp32<<<(H*H + 255)/256, 256>>>(Wo, woh, wol, H*H);
    avgsplit_kernel<<<(H*H + 255)/256, 256>>>(Ws, bs);

    dim3 gg(H / 128, ROWS / 128);   // 8 x 32

    gemm_sp<1><<<gg, 256, GEMM_SMEM>>>(xh, xl, wqh, wql, bq, 0.125f,
                                       nullptr, qh, ql, ROWS, H, H);
    gemm_sp<1><<<gg, 256, GEMM_SMEM>>>(xh, xl, wkh, wkl, bk, 1.0f,
                                       nullptr, kh, kl, ROWS, H, H);
    gemm_sp<1><<<gg, 256, GEMM_SMEM>>>(xh, xl, wvh, wvl, bv, 1.0f,
                                       nullptr, vh, vl, ROWS, H, H);

    attn_bf3r<<<dim3(SEQ/64, NHEADS, BATCH), 128, ATTN_SMEM>>>(
        qh, ql, kh, kl, vh, vl, ath, atl);

    gemm_sp<1><<<gg, 256, GEMM_SMEM>>>(ath, atl, wah, wal, bavgp, 1.0f,
                                       nullptr, eh, el, ROWS, H, H);
    gemm_sp<0><<<gg, 256, GEMM_SMEM>>>(eh, el, woh, wol, bo, 1.0f,
                                       (float*)d_out, nullptr, nullptr, ROWS, H, H);
}

// round 5
// speedup vs baseline: 4.2009x; 1.0579x over previous
#include <cuda_runtime.h>
#include <cuda_bf16.h>
#include <math.h>

#define H 1024
#define NHEADS 16
#define HD 64
#define SEQ 2048
#define BATCH 2
#define ROWS (BATCH*SEQ)   // 4096

// ---------------- scratch (device globals; allocation-free) ----------------
__device__ __nv_bfloat16 g_xh[ROWS*H],  g_xl[ROWS*H];
__device__ __nv_bfloat16 g_qh[ROWS*H],  g_ql[ROWS*H];
__device__ __nv_bfloat16 g_kh[ROWS*H],  g_kl[ROWS*H];
__device__ __nv_bfloat16 g_vh[ROWS*H],  g_vl[ROWS*H];
__device__ __nv_bfloat16 g_ath[ROWS*H], g_atl[ROWS*H];
__device__ __nv_bfloat16 g_wqkvh[3*H*H], g_wqkvl[3*H*H];   // packed Wq|Wk|Wv split
__device__ __nv_bfloat16 g_woh[H*H], g_wol[H*H];
__device__ __nv_bfloat16 g_wath[H*H], g_watl[H*H];          // mean(Ws)^T split
__device__ __nv_bfloat16 g_wch[H*H], g_wcl[H*H];            // Wc = Wo @ Wa split
__device__ float g_bqkv[3*H];
__device__ float g_bavg[H];
__device__ float g_bc[H];
__device__ float g_zero[H];      // stays 0 (never written)

// ---------------------------------------------------------------------------
__device__ __forceinline__ unsigned smaddr(const void* p) {
    return (unsigned)__cvta_generic_to_shared(p);
}
__device__ __forceinline__ void ldsm4(unsigned& r0, unsigned& r1, unsigned& r2,
                                      unsigned& r3, unsigned a) {
    asm volatile("ldmatrix.sync.aligned.m8n8.x4.shared.b16 {%0,%1,%2,%3}, [%4];"
                 : "=r"(r0), "=r"(r1), "=r"(r2), "=r"(r3) : "r"(a));
}
__device__ __forceinline__ void ldsm4t(unsigned& r0, unsigned& r1, unsigned& r2,
                                       unsigned& r3, unsigned a) {
    asm volatile("ldmatrix.sync.aligned.m8n8.x4.trans.shared.b16 {%0,%1,%2,%3}, [%4];"
                 : "=r"(r0), "=r"(r1), "=r"(r2), "=r"(r3) : "r"(a));
}
__device__ __forceinline__ void mma16(float* c, const unsigned* a, const unsigned* b) {
    asm volatile(
        "mma.sync.aligned.m16n8k16.row.col.f32.bf16.bf16.f32 "
        "{%0,%1,%2,%3}, {%4,%5,%6,%7}, {%8,%9}, {%0,%1,%2,%3};"
        : "+f"(c[0]), "+f"(c[1]), "+f"(c[2]), "+f"(c[3])
        : "r"(a[0]), "r"(a[1]), "r"(a[2]), "r"(a[3]), "r"(b[0]), "r"(b[1]));
}
__device__ __forceinline__ void cpa16(unsigned dst, const void* src) {
    asm volatile("cp.async.ca.shared.global [%0], [%1], 16;" :: "r"(dst), "l"(src));
}
__device__ __forceinline__ void split2(float x0, float x1, unsigned& hi, unsigned& lo) {
    __nv_bfloat16 h0 = __float2bfloat16(x0);
    __nv_bfloat16 h1 = __float2bfloat16(x1);
    __nv_bfloat16 e0 = __float2bfloat16(x0 - __bfloat162float(h0));
    __nv_bfloat16 e1 = __float2bfloat16(x1 - __bfloat162float(h1));
    unsigned short u0 = *(unsigned short*)&h0, u1 = *(unsigned short*)&h1;
    unsigned short v0 = *(unsigned short*)&e0, v1 = *(unsigned short*)&e1;
    hi = ((unsigned)u1 << 16) | u0;
    lo = ((unsigned)v1 << 16) | v0;
}

// ---------------------------------------------------------------------------
__global__ void split_fp32(const float* __restrict__ src,
                           __nv_bfloat16* __restrict__ hi,
                           __nv_bfloat16* __restrict__ lo, int n)
{
    int i = blockIdx.x * 256 + threadIdx.x;
    if (i < n) {
        float x = src[i];
        __nv_bfloat16 h = __float2bfloat16(x);
        hi[i] = h;
        lo[i] = __float2bfloat16(x - __bfloat162float(h));
    }
}

// pack QKV biases, compute mean stratum bias
__global__ void packb(const float* __restrict__ bq, const float* __restrict__ bk,
                      const float* __restrict__ bv, const float* __restrict__ bs)
{
    int i = blockIdx.x * 256 + threadIdx.x;
    if (i < H) {
        g_bqkv[i]       = bq[i];
        g_bqkv[H + i]   = bk[i];
        g_bqkv[2*H + i] = bv[i];
        g_bavg[i] = (bs[i] + bs[i + H] + bs[i + 2*H]) * (1.0f/3.0f);
    }
}

// WaT[h][j] = mean_n Ws[n][j][h], split to bf16 hi/lo. Tiled transpose.
__global__ void avgT_split(const float* __restrict__ Ws)
{
    __shared__ float tile[32][33];
    int j0 = blockIdx.x * 32, h0 = blockIdx.y * 32;
    int tx = threadIdx.x, ty = threadIdx.y;     // 32 x 8
    #pragma unroll
    for (int dy = 0; dy < 32; dy += 8) {
        int j = j0 + ty + dy, h = h0 + tx;
        tile[ty + dy][tx] = (Ws[j*H + h] + Ws[H*H + j*H + h] + Ws[2*H*H + j*H + h])
                            * (1.0f/3.0f);
    }
    __syncthreads();
    #pragma unroll
    for (int dy = 0; dy < 32; dy += 8) {
        int h = h0 + ty + dy, j = j0 + tx;
        float v = tile[tx][ty + dy];
        __nv_bfloat16 hh = __float2bfloat16(v);
        g_wath[h*H + j] = hh;
        g_watl[h*H + j] = __float2bfloat16(v - __bfloat162float(hh));
    }
}

// bc[g] = sum_j Wo[g][j] * bavg[j] + bo[g]   (one warp per g)
__global__ void bc_kernel(const float* __restrict__ Wo, const float* __restrict__ bo)
{
    int g = blockIdx.x * 8 + (threadIdx.x >> 5);
    int lane = threadIdx.x & 31;
    float s = 0.0f;
    for (int j = lane; j < H; j += 32) s += Wo[(size_t)g*H + j] * g_bavg[j];
    #pragma unroll
    for (int o = 16; o; o >>= 1) s += __shfl_xor_sync(0xffffffffu, s, o);
    if (lane == 0) g_bc[g] = s + bo[g];
}

// ---------------------------------------------------------------------------
// GEMM on pre-split inputs: C = (Ahi+Alo)[M,K] @ (Bhi+Blo)[N,K]^T + bias
// 3xBF16 passes. BM=BN=128, BK=32, 256 thr, cp.async double-buffered.
// OUTMODE 0: fp32 C.  OUTMODE 1: split bf16 pair.  OUTMODE 2: QKV routing
// (column band 0 -> Chi/Clo with scale, band 1 -> Chi2/Clo2, band 2 -> Chi3/Clo3)
// ---------------------------------------------------------------------------
#define GSTR 20
#define GARR (128*GSTR)
#define GEMM_SMEM (2*4*GARR*4)      // 81920 B
template<int OUTMODE>
__global__ __launch_bounds__(256, 2) void gemm_sp(
    const __nv_bfloat16* __restrict__ Ahi, const __nv_bfloat16* __restrict__ Alo,
    const __nv_bfloat16* __restrict__ Bhi, const __nv_bfloat16* __restrict__ Blo,
    const float* __restrict__ bias, float scale,
    float* __restrict__ C,
    __nv_bfloat16* __restrict__ Chi,  __nv_bfloat16* __restrict__ Clo,
    __nv_bfloat16* __restrict__ Chi2, __nv_bfloat16* __restrict__ Clo2,
    __nv_bfloat16* __restrict__ Chi3, __nv_bfloat16* __restrict__ Clo3,
    int M, int N, int K)
{
    extern __shared__ unsigned gsm[];
    const int t = threadIdx.x, lane = t & 31, warp = t >> 5;
    const int wm = (warp >> 2) * 64, wn = (warp & 3) * 32;
    const int m0 = blockIdx.y * 128, n0 = blockIdx.x * 128;

    float acc[16][4];
    #pragma unroll
    for (int i = 0; i < 16; i++)
        #pragma unroll
        for (int j = 0; j < 4; j++) acc[i][j] = 0.0f;

    const int lr = t >> 1, half = t & 1;
    const size_t arow = (size_t)(m0 + lr) * K + half * 16;
    const size_t brow = (size_t)(n0 + lr) * K + half * 16;
    const int sw = lr * GSTR + half * 8;
    const int NB = K / 32;

    {
        unsigned* B0 = gsm;
        cpa16(smaddr(&B0[0*GARR + sw]),     Ahi + arow);
        cpa16(smaddr(&B0[0*GARR + sw + 4]), Ahi + arow + 8);
        cpa16(smaddr(&B0[1*GARR + sw]),     Alo + arow);
        cpa16(smaddr(&B0[1*GARR + sw + 4]), Alo + arow + 8);
        cpa16(smaddr(&B0[2*GARR + sw]),     Bhi + brow);
        cpa16(smaddr(&B0[2*GARR + sw + 4]), Bhi + brow + 8);
        cpa16(smaddr(&B0[3*GARR + sw]),     Blo + brow);
        cpa16(smaddr(&B0[3*GARR + sw + 4]), Blo + brow + 8);
        asm volatile("cp.async.commit_group;");
    }

    for (int bi = 0; bi < NB; bi++) {
        if (bi + 1 < NB) {
            unsigned* Bn = gsm + ((bi + 1) & 1) * 4 * GARR;
            size_t ko = (size_t)(bi + 1) * 32;
            cpa16(smaddr(&Bn[0*GARR + sw]),     Ahi + arow + ko);
            cpa16(smaddr(&Bn[0*GARR + sw + 4]), Ahi + arow + ko + 8);
            cpa16(smaddr(&Bn[1*GARR + sw]),     Alo + arow + ko);
            cpa16(smaddr(&Bn[1*GARR + sw + 4]), Alo + arow + ko + 8);
            cpa16(smaddr(&Bn[2*GARR + sw]),     Bhi + brow + ko);
            cpa16(smaddr(&Bn[2*GARR + sw + 4]), Bhi + brow + ko + 8);
            cpa16(smaddr(&Bn[3*GARR + sw]),     Blo + brow + ko);
            cpa16(smaddr(&Bn[3*GARR + sw + 4]), Blo + brow + ko + 8);
            asm volatile("cp.async.commit_group;");
            asm volatile("cp.async.wait_group 1;");
        } else {
            asm volatile("cp.async.wait_group 0;");
        }
        __syncthreads();

        unsigned* Ah = gsm + (bi & 1) * 4 * GARR;
        unsigned* Al = Ah + GARR;
        unsigned* Bh = Ah + 2*GARR;
        unsigned* Bl = Ah + 3*GARR;

        #pragma unroll
        for (int ks = 0; ks < 2; ks++) {
            const int ar = ((lane >> 3) & 1) * 8 + (lane & 7);
            const int aw = ks * 8 + (lane >> 4) * 4;
            unsigned ah[4][4], am[4][4];
            #pragma unroll
            for (int mt = 0; mt < 4; mt++) {
                int r = (wm + mt*16 + ar) * GSTR + aw;
                ldsm4(ah[mt][0], ah[mt][1], ah[mt][2], ah[mt][3], smaddr(&Ah[r]));
                ldsm4(am[mt][0], am[mt][1], am[mt][2], am[mt][3], smaddr(&Al[r]));
            }
            const int br = ((lane >> 4) & 1) * 8 + (lane & 7);
            const int bw = ks * 8 + ((lane >> 3) & 1) * 4;
            unsigned bh[2][4], bm[2][4];
            #pragma unroll
            for (int np = 0; np < 2; np++) {
                int r = (wn + np*16 + br) * GSTR + bw;
                ldsm4(bh[np][0], bh[np][1], bh[np][2], bh[np][3], smaddr(&Bh[r]));
                ldsm4(bm[np][0], bm[np][1], bm[np][2], bm[np][3], smaddr(&Bl[r]));
            }
            #pragma unroll
            for (int mt = 0; mt < 4; mt++)
                #pragma unroll
                for (int nt = 0; nt < 4; nt++) {
                    unsigned* bhp = &bh[nt >> 1][(nt & 1) * 2];
                    unsigned* blp = &bm[nt >> 1][(nt & 1) * 2];
                    mma16(acc[mt*4+nt], ah[mt], bhp);
                    mma16(acc[mt*4+nt], ah[mt], blp);
                    mma16(acc[mt*4+nt], am[mt], bhp);
                }
        }
        __syncthreads();
    }

    // output routing
    __nv_bfloat16 *oh = Chi, *ol = Clo;
    float sc = scale;
    if (OUTMODE == 2) {
        int which = n0 >> 10;
        if (which == 1)      { oh = Chi2; ol = Clo2; sc = 1.0f; }
        else if (which == 2) { oh = Chi3; ol = Clo3; sc = 1.0f; }
    }

    #pragma unroll
    for (int mt = 0; mt < 4; mt++) {
        int row = m0 + wm + mt*16 + (lane >> 2);
        #pragma unroll
        for (int nt = 0; nt < 4; nt++) {
            int col = n0 + wn + nt*8 + (lane & 3) * 2;
            float b0 = __ldg(bias + col), b1 = __ldg(bias + col + 1);
            float* a = acc[mt*4+nt];
            float v00 = (a[0] + b0) * sc, v01 = (a[1] + b1) * sc;
            float v10 = (a[2] + b0) * sc, v11 = (a[3] + b1) * sc;
            if (OUTMODE == 0) {
                float2 u;
                u.x = v00; u.y = v01; *(float2*)(C + (size_t)row * N + col) = u;
                u.x = v10; u.y = v11; *(float2*)(C + (size_t)(row + 8) * N + col) = u;
            } else {
                int cl = (OUTMODE == 2) ? (col & 1023) : col;
                int nn = (OUTMODE == 2) ? H : N;
                unsigned hh, ll;
                split2(v00, v01, hh, ll);
                *(unsigned*)(oh + (size_t)row * nn + cl) = hh;
                *(unsigned*)(ol + (size_t)row * nn + cl) = ll;
                split2(v10, v11, hh, ll);
                *(unsigned*)(oh + (size_t)(row + 8) * nn + cl) = hh;
                *(unsigned*)(ol + (size_t)(row + 8) * nn + cl) = ll;
            }
        }
    }
}

// ---------------------------------------------------------------------------
// Flash attention, 3xBF16, P in registers. CTA = 64 q-rows, 4 warps.
// KV double-buffered cp.async; Q staged through buffer 1. Split bf16 output.
// ---------------------------------------------------------------------------
#define ASTR 36
#define TILE_W (64*ASTR)
#define ATTN_SMEM (8*TILE_W*4)  // 73728 B

__global__ __launch_bounds__(128, 3) void attn_bf3r(
    const __nv_bfloat16* __restrict__ qhi, const __nv_bfloat16* __restrict__ qlo,
    const __nv_bfloat16* __restrict__ khi, const __nv_bfloat16* __restrict__ klo,
    const __nv_bfloat16* __restrict__ vhi, const __nv_bfloat16* __restrict__ vlo,
    __nv_bfloat16* __restrict__ athi, __nv_bfloat16* __restrict__ atlo)
{
    extern __shared__ unsigned smu[];
    unsigned* bufs = smu;

    const int t = threadIdx.x, lane = t & 31, warp = t >> 5;
    const int qb = blockIdx.x, h = blockIdx.y, b = blockIdx.z;
    const int lrow = t >> 1, cb = (t & 1) * 4;
    const int NT = SEQ / 64;
    const unsigned d0 = lrow * ASTR + cb * 4;

    {
        size_t qoff = ((size_t)(b*SEQ + qb*64 + lrow)) * H + h*HD + cb*8;
        unsigned* B1 = bufs + 4*TILE_W;
        #pragma unroll
        for (int i = 0; i < 4; i++) {
            cpa16(smaddr(&B1[0*TILE_W + d0 + i*4]), qhi + qoff + i*8);
            cpa16(smaddr(&B1[1*TILE_W + d0 + i*4]), qlo + qoff + i*8);
        }
        asm volatile("cp.async.commit_group;");
    }
    {
        size_t base = ((size_t)(b*SEQ + lrow)) * H + h*HD + cb*8;
        #pragma unroll
        for (int i = 0; i < 4; i++) {
            cpa16(smaddr(&bufs[0*TILE_W + d0 + i*4]), khi + base + i*8);
            cpa16(smaddr(&bufs[1*TILE_W + d0 + i*4]), klo + base + i*8);
            cpa16(smaddr(&bufs[2*TILE_W + d0 + i*4]), vhi + base + i*8);
            cpa16(smaddr(&bufs[3*TILE_W + d0 + i*4]), vlo + base + i*8);
        }
        asm volatile("cp.async.commit_group;");
    }

    asm volatile("cp.async.wait_group 1;");
    __syncthreads();

    unsigned qh[4][4], ql[4][4];
    {
        const int ar = warp*16 + ((lane >> 3) & 1) * 8 + (lane & 7);
        unsigned* B1 = bufs + 4*TILE_W;
        #pragma unroll
        for (int ks = 0; ks < 4; ks++) {
            int w = ks * 8 + (lane >> 4) * 4;
            ldsm4(qh[ks][0], qh[ks][1], qh[ks][2], qh[ks][3],
                  smaddr(&B1[0*TILE_W + ar*ASTR + w]));
            ldsm4(ql[ks][0], ql[ks][1], ql[ks][2], ql[ks][3],
                  smaddr(&B1[1*TILE_W + ar*ASTR + w]));
        }
    }
    __syncthreads();

    float o[8][4];
    #pragma unroll
    for (int i = 0; i < 8; i++)
        #pragma unroll
        for (int j = 0; j < 4; j++) o[i][j] = 0.0f;
    float m0 = -1e30f, m1 = -1e30f, l0 = 0.0f, l1 = 0.0f;
    const int r = warp*16 + (lane >> 2);

    for (int kb = 0; kb < NT; kb++) {
        if (kb + 1 < NT) {
            size_t base = ((size_t)(b*SEQ + (kb+1)*64 + lrow)) * H + h*HD + cb*8;
            unsigned* Bn = bufs + ((kb+1) & 1) * 4 * TILE_W;
            #pragma unroll
            for (int i = 0; i < 4; i++) {
                cpa16(smaddr(&Bn[0*TILE_W + d0 + i*4]), khi + base + i*8);
                cpa16(smaddr(&Bn[1*TILE_W + d0 + i*4]), klo + base + i*8);
                cpa16(smaddr(&Bn[2*TILE_W + d0 + i*4]), vhi + base + i*8);
                cpa16(smaddr(&Bn[3*TILE_W + d0 + i*4]), vlo + base + i*8);
            }
            asm volatile("cp.async.commit_group;");
            asm volatile("cp.async.wait_group 1;");
        } else {
            asm volatile("cp.async.wait_group 0;");
        }
        __syncthreads();

        unsigned* Kh = bufs + (kb & 1) * 4 * TILE_W;
        unsigned* Kl = Kh + TILE_W;
        unsigned* Vh = Kh + 2*TILE_W;
        unsigned* Vl = Kh + 3*TILE_W;

        float s[8][4];
        #pragma unroll
        for (int i = 0; i < 8; i++)
            #pragma unroll
            for (int j = 0; j < 4; j++) s[i][j] = 0.0f;

        #pragma unroll
        for (int ks = 0; ks < 4; ks++) {
            const int br = ((lane >> 4) & 1) * 8 + (lane & 7);
            const int bw = ks * 8 + ((lane >> 3) & 1) * 4;
            unsigned bh[4][4], bm[4][4];
            #pragma unroll
            for (int np = 0; np < 4; np++) {
                int rr = (np*16 + br) * ASTR + bw;
                ldsm4(bh[np][0], bh[np][1], bh[np][2], bh[np][3], smaddr(&Kh[rr]));
                ldsm4(bm[np][0], bm[np][1], bm[np][2], bm[np][3], smaddr(&Kl[rr]));
            }
            #pragma unroll
            for (int nt = 0; nt < 8; nt++) {
                unsigned* bhp = &bh[nt >> 1][(nt & 1) * 2];
                unsigned* blp = &bm[nt >> 1][(nt & 1) * 2];
                mma16(s[nt], qh[ks], bhp);
                mma16(s[nt], qh[ks], blp);
                mma16(s[nt], ql[ks], bhp);
            }
        }

        float mx0 = -1e30f, mx1 = -1e30f;
        #pragma unroll
        for (int nt = 0; nt < 8; nt++) {
            mx0 = fmaxf(mx0, fmaxf(s[nt][0], s[nt][1]));
            mx1 = fmaxf(mx1, fmaxf(s[nt][2], s[nt][3]));
        }
        mx0 = fmaxf(mx0, __shfl_xor_sync(0xffffffffu, mx0, 1));
        mx0 = fmaxf(mx0, __shfl_xor_sync(0xffffffffu, mx0, 2));
        mx1 = fmaxf(mx1, __shfl_xor_sync(0xffffffffu, mx1, 1));
        mx1 = fmaxf(mx1, __shfl_xor_sync(0xffffffffu, mx1, 2));
        float nm0 = fmaxf(m0, mx0), nm1 = fmaxf(m1, mx1);
        float a0 = __expf(m0 - nm0), a1 = __expf(m1 - nm1);

        float sum0 = 0.0f, sum1 = 0.0f;
        #pragma unroll
        for (int nt = 0; nt < 8; nt++) {
            s[nt][0] = __expf(s[nt][0] - nm0); sum0 += s[nt][0];
            s[nt][1] = __expf(s[nt][1] - nm0); sum0 += s[nt][1];
            s[nt][2] = __expf(s[nt][2] - nm1); sum1 += s[nt][2];
            s[nt][3] = __expf(s[nt][3] - nm1); sum1 += s[nt][3];
        }
        sum0 += __shfl_xor_sync(0xffffffffu, sum0, 1);
        sum0 += __shfl_xor_sync(0xffffffffu, sum0, 2);
        sum1 += __shfl_xor_sync(0xffffffffu, sum1, 1);
        sum1 += __shfl_xor_sync(0xffffffffu, sum1, 2);
        l0 = l0*a0 + sum0;  l1 = l1*a1 + sum1;
        m0 = nm0;           m1 = nm1;
        #pragma unroll
        for (int nt = 0; nt < 8; nt++) {
            o[nt][0] *= a0; o[nt][1] *= a0;
            o[nt][2] *= a1; o[nt][3] *= a1;
        }

        #pragma unroll
        for (int ks = 0; ks < 4; ks++) {
            unsigned ph[4], pl[4];
            split2(s[2*ks][0],   s[2*ks][1],   ph[0], pl[0]);
            split2(s[2*ks][2],   s[2*ks][3],   ph[1], pl[1]);
            split2(s[2*ks+1][0], s[2*ks+1][1], ph[2], pl[2]);
            split2(s[2*ks+1][2], s[2*ks+1][3], ph[3], pl[3]);

            const int vr = ks*16 + ((lane >> 3) & 1) * 8 + (lane & 7);
            unsigned vh[4][4], vm[4][4];
            #pragma unroll
            for (int np = 0; np < 4; np++) {
                int vw = np*8 + (lane >> 4) * 4;
                ldsm4t(vh[np][0], vh[np][1], vh[np][2], vh[np][3], smaddr(&Vh[vr*ASTR + vw]));
                ldsm4t(vm[np][0], vm[np][1], vm[np][2], vm[np][3], smaddr(&Vl[vr*ASTR + vw]));
            }
            #pragma unroll
            for (int nt = 0; nt < 8; nt++) {
                unsigned* bvh = &vh[nt >> 1][(nt & 1) * 2];
                unsigned* bvl = &vm[nt >> 1][(nt & 1) * 2];
                mma16(o[nt], ph, bvh);
                mma16(o[nt], pl, bvh);
                mma16(o[nt], ph, bvl);
            }
        }
        __syncthreads();
    }

    float inv0 = 1.0f / l0, inv1 = 1.0f / l1;
    size_t gr0 = (size_t)(b*SEQ + qb*64 + r) * H + h*HD;
    size_t gr1 = (size_t)(b*SEQ + qb*64 + r + 8) * H + h*HD;
    int col = (lane & 3) * 2;
    #pragma unroll
    for (int nt = 0; nt < 8; nt++) {
        unsigned hh, ll;
        split2(o[nt][0]*inv0, o[nt][1]*inv0, hh, ll);
        *(unsigned*)(athi + gr0 + nt*8 + col) = hh;
        *(unsigned*)(atlo + gr0 + nt*8 + col) = ll;
        split2(o[nt][2]*inv1, o[nt][3]*inv1, hh, ll);
        *(unsigned*)(athi + gr1 + nt*8 + col) = hh;
        *(unsigned*)(atlo + gr1 + nt*8 + col) = ll;
    }
}

// ---------------------------------------------------------------------------
extern "C" void kernel_launch(void* const* d_in, const int* in_sizes, int n_in,
                              void* d_out, int out_size)
{
    const float* x  = (const float*)d_in[0];
    const float* Wq = (const float*)d_in[1];
    const float* bq = (const float*)d_in[2];
    const float* Wk = (const float*)d_in[3];
    const float* bk = (const float*)d_in[4];
    const float* Wv = (const float*)d_in[5];
    const float* bv = (const float*)d_in[6];
    const float* Ws = (const float*)d_in[7];
    const float* bs = (const float*)d_in[8];
    const float* Wo = (const float*)d_in[9];
    const float* bo = (const float*)d_in[10];

    __nv_bfloat16 *xh, *xl, *qh, *ql, *kh, *kl, *vh, *vl, *ath, *atl;
    __nv_bfloat16 *wqkvh, *wqkvl, *woh, *wol, *wath, *watl, *wch, *wcl;
    float *bqkvp, *bcp, *zerop;
    cudaGetSymbolAddress((void**)&xh, g_xh);   cudaGetSymbolAddress((void**)&xl, g_xl);
    cudaGetSymbolAddress((void**)&qh, g_qh);   cudaGetSymbolAddress((void**)&ql, g_ql);
    cudaGetSymbolAddress((void**)&kh, g_kh);   cudaGetSymbolAddress((void**)&kl, g_kl);
    cudaGetSymbolAddress((void**)&vh, g_vh);   cudaGetSymbolAddress((void**)&vl, g_vl);
    cudaGetSymbolAddress((void**)&ath, g_ath); cudaGetSymbolAddress((void**)&atl, g_atl);
    cudaGetSymbolAddress((void**)&wqkvh, g_wqkvh); cudaGetSymbolAddress((void**)&wqkvl, g_wqkvl);
    cudaGetSymbolAddress((void**)&woh, g_woh); cudaGetSymbolAddress((void**)&wol, g_wol);
    cudaGetSymbolAddress((void**)&wath, g_wath); cudaGetSymbolAddress((void**)&watl, g_watl);
    cudaGetSymbolAddress((void**)&wch, g_wch); cudaGetSymbolAddress((void**)&wcl, g_wcl);
    cudaGetSymbolAddress((void**)&bqkvp, g_bqkv);
    cudaGetSymbolAddress((void**)&bcp, g_bc);
    cudaGetSymbolAddress((void**)&zerop, g_zero);

    cudaFuncSetAttribute(attn_bf3r,
                         cudaFuncAttributeMaxDynamicSharedMemorySize, ATTN_SMEM);
    cudaFuncSetAttribute(gemm_sp<0>,
                         cudaFuncAttributeMaxDynamicSharedMemorySize, GEMM_SMEM);
    cudaFuncSetAttribute(gemm_sp<1>,
                         cudaFuncAttributeMaxDynamicSharedMemorySize, GEMM_SMEM);
    cudaFuncSetAttribute(gemm_sp<2>,
                         cudaFuncAttributeMaxDynamicSharedMemorySize, GEMM_SMEM);

    // pre-split / precompute
    split_fp32<<<(ROWS*H + 255)/256, 256>>>(x, xh, xl, ROWS*H);
    split_fp32<<<(H*H + 255)/256, 256>>>(Wq, wqkvh,         wqkvl,         H*H);
    split_fp32<<<(H*H + 255)/256, 256>>>(Wk, wqkvh + H*H,   wqkvl + H*H,   H*H);
    split_fp32<<<(H*H + 255)/256, 256>>>(Wv, wqkvh + 2*H*H, wqkvl + 2*H*H, H*H);
    split_fp32<<<(H*H + 255)/256, 256>>>(Wo, woh, wol, H*H);
    packb<<<4, 256>>>(bq, bk, bv, bs);
    avgT_split<<<dim3(32, 32), dim3(32, 8)>>>(Ws);

    // Wc = Wo @ mean(Ws): C[g,h] = sum_j Wo[g,j] * WaT[h,j]
    gemm_sp<1><<<dim3(8, 8), 256, GEMM_SMEM>>>(
        woh, wol, wath, watl, zerop, 1.0f,
        nullptr, wch, wcl, nullptr, nullptr, nullptr, nullptr, H, H, H);
    bc_kernel<<<H/8, 256>>>(Wo, bo);

    // fused QKV: [4096, 3072]
    gemm_sp<2><<<dim3(3*H/128, ROWS/128), 256, GEMM_SMEM>>>(
        xh, xl, wqkvh, wqkvl, bqkvp, 0.125f,
        nullptr, qh, ql, kh, kl, vh, vl, ROWS, 3*H, H);

    attn_bf3r<<<dim3(SEQ/64, NHEADS, BATCH), 128, ATTN_SMEM>>>(
        qh, ql, kh, kl, vh, vl, ath, atl);

    // out = att @ Wc^T + bc
    gemm_sp<0><<<dim3(H/128, ROWS/128), 256, GEMM_SMEM>>>(
        ath, atl, wch, wcl, bcp, 1.0f,
        (float*)d_out, nullptr, nullptr, nullptr, nullptr, nullptr, nullptr,
        ROWS, H, H);
}

// round 9
// speedup vs baseline: 6.7177x; 1.5991x over previous
#include <cuda_runtime.h>
#include <cuda_fp16.h>
#include <math.h>
#include <stdint.h>

#define H 1024
#define NHEADS 16
#define HD 64
#define SEQ 2048
#define BATCH 2
#define ROWS (BATCH*SEQ)   // 4096

// ---------------- scratch (device globals; allocation-free) ----------------
__device__ __half g_xh[ROWS*H],  g_xl[ROWS*H];
__device__ __half g_qh[ROWS*H],  g_ql[ROWS*H];
__device__ __half g_kh[ROWS*H];
__device__ __half g_vh[ROWS*H];
__device__ __half g_ath[ROWS*H], g_atl[ROWS*H];
__device__ __half g_wqkvh[3*H*H];          // packed Wq|Wk|Wv, hi only
__device__ __half g_woh[H*H], g_wol[H*H];  // Wo split (A of Wc GEMM)
__device__ __half g_wath[H*H];             // mean(Ws)^T hi only
__device__ __half g_wch[H*H];              // Wc = Wo @ Wa, hi only
__device__ float g_bqkv[3*H];
__device__ float g_bavg[H];
__device__ float g_bc[H];
__device__ float g_zero[H];                // stays 0

// ---------------------------------------------------------------------------
__device__ __forceinline__ unsigned smaddr(const void* p) {
    return (unsigned)__cvta_generic_to_shared(p);
}
__device__ __forceinline__ void ldsm4(unsigned& r0, unsigned& r1, unsigned& r2,
                                      unsigned& r3, unsigned a) {
    asm volatile("ldmatrix.sync.aligned.m8n8.x4.shared.b16 {%0,%1,%2,%3}, [%4];"
                 : "=r"(r0), "=r"(r1), "=r"(r2), "=r"(r3) : "r"(a));
}
__device__ __forceinline__ void ldsm4t(unsigned& r0, unsigned& r1, unsigned& r2,
                                       unsigned& r3, unsigned a) {
    asm volatile("ldmatrix.sync.aligned.m8n8.x4.trans.shared.b16 {%0,%1,%2,%3}, [%4];"
                 : "=r"(r0), "=r"(r1), "=r"(r2), "=r"(r3) : "r"(a));
}
__device__ __forceinline__ void mma16h(float* c, const unsigned* a, const unsigned* b) {
    asm volatile(
        "mma.sync.aligned.m16n8k16.row.col.f32.f16.f16.f32 "
        "{%0,%1,%2,%3}, {%4,%5,%6,%7}, {%8,%9}, {%0,%1,%2,%3};"
        : "+f"(c[0]), "+f"(c[1]), "+f"(c[2]), "+f"(c[3])
        : "r"(a[0]), "r"(a[1]), "r"(a[2]), "r"(a[3]), "r"(b[0]), "r"(b[1]));
}
__device__ __forceinline__ void cpa16(unsigned dst, const void* src) {
    asm volatile("cp.async.ca.shared.global [%0], [%1], 16;" :: "r"(dst), "l"(src));
}
__device__ __forceinline__ void split2h(float x0, float x1, unsigned& hi, unsigned& lo) {
    __half h0 = __float2half_rn(x0), h1 = __float2half_rn(x1);
    __half e0 = __float2half_rn(x0 - __half2float(h0));
    __half e1 = __float2half_rn(x1 - __half2float(h1));
    hi = ((unsigned)__half_as_ushort(h1) << 16) | __half_as_ushort(h0);
    lo = ((unsigned)__half_as_ushort(e1) << 16) | __half_as_ushort(e0);
}
__device__ __forceinline__ unsigned pack2h(float x0, float x1) {
    __half h0 = __float2half_rn(x0), h1 = __float2half_rn(x1);
    return ((unsigned)__half_as_ushort(h1) << 16) | __half_as_ushort(h0);
}

// ---------------------------------------------------------------------------
__global__ void split_h(const float* __restrict__ src,
                        __half* __restrict__ hi, __half* __restrict__ lo, int n)
{
    int i = blockIdx.x * 256 + threadIdx.x;
    if (i < n) {
        float x = src[i];
        __half h = __float2half_rn(x);
        hi[i] = h;
        lo[i] = __float2half_rn(x - __half2float(h));
    }
}
__global__ void trunc_h(const float* __restrict__ src, __half* __restrict__ hi, int n)
{
    int i = blockIdx.x * 256 + threadIdx.x;
    if (i < n) hi[i] = __float2half_rn(src[i]);
}
__global__ void packb(const float* __restrict__ bq, const float* __restrict__ bk,
                      const float* __restrict__ bv, const float* __restrict__ bs)
{
    int i = blockIdx.x * 256 + threadIdx.x;
    if (i < H) {
        g_bqkv[i]       = bq[i];
        g_bqkv[H + i]   = bk[i];
        g_bqkv[2*H + i] = bv[i];
        g_bavg[i] = (bs[i] + bs[i + H] + bs[i + 2*H]) * (1.0f/3.0f);
    }
}
// WaT[h][j] = mean_n Ws[n][j][h], hi only (B side of Wc GEMM)
__global__ void avgT_split(const float* __restrict__ Ws)
{
    __shared__ float tile[32][33];
    int j0 = blockIdx.x * 32, h0 = blockIdx.y * 32;
    int tx = threadIdx.x, ty = threadIdx.y;
    #pragma unroll
    for (int dy = 0; dy < 32; dy += 8) {
        int j = j0 + ty + dy, h = h0 + tx;
        tile[ty + dy][tx] = (Ws[j*H + h] + Ws[H*H + j*H + h] + Ws[2*H*H + j*H + h])
                            * (1.0f/3.0f);
    }
    __syncthreads();
    #pragma unroll
    for (int dy = 0; dy < 32; dy += 8) {
        int h = h0 + ty + dy, j = j0 + tx;
        g_wath[h*H + j] = __float2half_rn(tile[tx][ty + dy]);
    }
}
__global__ void bc_kernel(const float* __restrict__ Wo, const float* __restrict__ bo)
{
    int g = blockIdx.x * 8 + (threadIdx.x >> 5);
    int lane = threadIdx.x & 31;
    float s = 0.0f;
    for (int j = lane; j < H; j += 32) s += Wo[(size_t)g*H + j] * g_bavg[j];
    #pragma unroll
    for (int o = 16; o; o >>= 1) s += __shfl_xor_sync(0xffffffffu, s, o);
    if (lane == 0) g_bc[g] = s + bo[g];
}

// ---------------------------------------------------------------------------
// GEMM: C = (Ahi+Alo)[M,K] @ Bhi[N,K]^T + bias  (2-pass fp16, B truncated).
// BM=BN=128, BK=32, 256 thr, cp.async double-buffered. 3 smem arrays.
// OUTMODE 0: fp32 C.  1: hi-only Ohi.  2: QKV routing (Q split+scale, K hi, V hi).
// ---------------------------------------------------------------------------
#define GSTR 20
#define GARR (128*GSTR)
#define GEMM_SMEM (2*3*GARR*4)      // 61440 B
template<int OUTMODE>
__global__ __launch_bounds__(256, 2) void gemm_sp(
    const __half* __restrict__ Ahi, const __half* __restrict__ Alo,
    const __half* __restrict__ Bhi,
    const float* __restrict__ bias, float scale,
    float* __restrict__ C,
    __half* __restrict__ Ohi,  __half* __restrict__ Olo,
    __half* __restrict__ Khi,  __half* __restrict__ Vhi,
    int M, int N, int K)
{
    extern __shared__ unsigned gsm[];
    const int t = threadIdx.x, lane = t & 31, warp = t >> 5;
    const int wm = (warp >> 2) * 64, wn = (warp & 3) * 32;
    const int m0 = blockIdx.y * 128, n0 = blockIdx.x * 128;

    float acc[16][4];
    #pragma unroll
    for (int i = 0; i < 16; i++)
        #pragma unroll
        for (int j = 0; j < 4; j++) acc[i][j] = 0.0f;

    const int lr = t >> 1, half = t & 1;
    const size_t arow = (size_t)(m0 + lr) * K + half * 16;
    const size_t brow = (size_t)(n0 + lr) * K + half * 16;
    const int sw = lr * GSTR + half * 8;
    const int NB = K / 32;

    {
        unsigned* B0 = gsm;
        cpa16(smaddr(&B0[0*GARR + sw]),     Ahi + arow);
        cpa16(smaddr(&B0[0*GARR + sw + 4]), Ahi + arow + 8);
        cpa16(smaddr(&B0[1*GARR + sw]),     Alo + arow);
        cpa16(smaddr(&B0[1*GARR + sw + 4]), Alo + arow + 8);
        cpa16(smaddr(&B0[2*GARR + sw]),     Bhi + brow);
        cpa16(smaddr(&B0[2*GARR + sw + 4]), Bhi + brow + 8);
        asm volatile("cp.async.commit_group;");
    }

    for (int bi = 0; bi < NB; bi++) {
        if (bi + 1 < NB) {
            unsigned* Bn = gsm + ((bi + 1) & 1) * 3 * GARR;
            size_t ko = (size_t)(bi + 1) * 32;
            cpa16(smaddr(&Bn[0*GARR + sw]),     Ahi + arow + ko);
            cpa16(smaddr(&Bn[0*GARR + sw + 4]), Ahi + arow + ko + 8);
            cpa16(smaddr(&Bn[1*GARR + sw]),     Alo + arow + ko);
            cpa16(smaddr(&Bn[1*GARR + sw + 4]), Alo + arow + ko + 8);
            cpa16(smaddr(&Bn[2*GARR + sw]),     Bhi + brow + ko);
            cpa16(smaddr(&Bn[2*GARR + sw + 4]), Bhi + brow + ko + 8);
            asm volatile("cp.async.commit_group;");
            asm volatile("cp.async.wait_group 1;");
        } else {
            asm volatile("cp.async.wait_group 0;");
        }
        __syncthreads();

        unsigned* Ah = gsm + (bi & 1) * 3 * GARR;
        unsigned* Al = Ah + GARR;
        unsigned* Bh = Ah + 2*GARR;

        #pragma unroll
        for (int ks = 0; ks < 2; ks++) {
            const int ar = ((lane >> 3) & 1) * 8 + (lane & 7);
            const int aw = ks * 8 + (lane >> 4) * 4;
            unsigned ah[4][4], am[4][4];
            #pragma unroll
            for (int mt = 0; mt < 4; mt++) {
                int r = (wm + mt*16 + ar) * GSTR + aw;
                ldsm4(ah[mt][0], ah[mt][1], ah[mt][2], ah[mt][3], smaddr(&Ah[r]));
                ldsm4(am[mt][0], am[mt][1], am[mt][2], am[mt][3], smaddr(&Al[r]));
            }
            const int br = ((lane >> 4) & 1) * 8 + (lane & 7);
            const int bw = ks * 8 + ((lane >> 3) & 1) * 4;
            unsigned bh[2][4];
            #pragma unroll
            for (int np = 0; np < 2; np++) {
                int r = (wn + np*16 + br) * GSTR + bw;
                ldsm4(bh[np][0], bh[np][1], bh[np][2], bh[np][3], smaddr(&Bh[r]));
            }
            #pragma unroll
            for (int mt = 0; mt < 4; mt++)
                #pragma unroll
                for (int nt = 0; nt < 4; nt++) {
                    unsigned* bhp = &bh[nt >> 1][(nt & 1) * 2];
                    mma16h(acc[mt*4+nt], ah[mt], bhp);
                    mma16h(acc[mt*4+nt], am[mt], bhp);
                }
        }
        __syncthreads();
    }

    #pragma unroll
    for (int mt = 0; mt < 4; mt++) {
        int row = m0 + wm + mt*16 + (lane >> 2);
        #pragma unroll
        for (int nt = 0; nt < 4; nt++) {
            int col = n0 + wn + nt*8 + (lane & 3) * 2;
            float b0 = __ldg(bias + col), b1 = __ldg(bias + col + 1);
            float* a = acc[mt*4+nt];
            float v00 = a[0] + b0, v01 = a[1] + b1;
            float v10 = a[2] + b0, v11 = a[3] + b1;
            if (OUTMODE == 0) {
                float2 u;
                u.x = v00; u.y = v01; *(float2*)(C + (size_t)row * N + col) = u;
                u.x = v10; u.y = v11; *(float2*)(C + (size_t)(row + 8) * N + col) = u;
            } else if (OUTMODE == 1) {
                *(unsigned*)(Ohi + (size_t)row * N + col)       = pack2h(v00, v01);
                *(unsigned*)(Ohi + (size_t)(row + 8) * N + col) = pack2h(v10, v11);
            } else {
                int which = n0 >> 10;
                int cl = col & 1023;
                if (which == 0) {
                    // Q: apply softmax scale, split hi/lo
                    unsigned hh, ll;
                    split2h(v00 * scale, v01 * scale, hh, ll);
                    *(unsigned*)(Ohi + (size_t)row * H + cl) = hh;
                    *(unsigned*)(Olo + (size_t)row * H + cl) = ll;
                    split2h(v10 * scale, v11 * scale, hh, ll);
                    *(unsigned*)(Ohi + (size_t)(row + 8) * H + cl) = hh;
                    *(unsigned*)(Olo + (size_t)(row + 8) * H + cl) = ll;
                } else {
                    __half* dst = (which == 1) ? Khi : Vhi;
                    *(unsigned*)(dst + (size_t)row * H + cl)       = pack2h(v00, v01);
                    *(unsigned*)(dst + (size_t)(row + 8) * H + cl) = pack2h(v10, v11);
                }
            }
        }
    }
}

// ---------------------------------------------------------------------------
// Flash attention, 2-pass fp16: S = (Qhi+Qlo) @ Khi^T, O = (Phi+Plo) @ Vhi.
// CTA = 64 q-rows, 4 warps; K/V hi-only double-buffered via cp.async.
// Q staged through buffer 1. P in registers. Split fp16 output (A of final GEMM).
// ---------------------------------------------------------------------------
#define ASTR 36
#define TILE_W (64*ASTR)
#define ATTN_SMEM (4*TILE_W*4)  // 2 buffers x 2 arrays = 36864 B

__global__ __launch_bounds__(128, 3) void attn_h2(
    const __half* __restrict__ qhi, const __half* __restrict__ qlo,
    const __half* __restrict__ khi, const __half* __restrict__ vhi,
    __half* __restrict__ athi, __half* __restrict__ atlo)
{
    extern __shared__ unsigned smu[];
    unsigned* bufs = smu;   // buffer b: Kh at b*2*TILE_W, Vh at b*2*TILE_W + TILE_W

    const int t = threadIdx.x, lane = t & 31, warp = t >> 5;
    const int qb = blockIdx.x, h = blockIdx.y, b = blockIdx.z;
    const int lrow = t >> 1, cb = (t & 1) * 4;
    const int NT = SEQ / 64;
    const unsigned d0 = lrow * ASTR + cb * 4;

    // stage Q (split) into buffer 1's two arrays
    {
        size_t qoff = ((size_t)(b*SEQ + qb*64 + lrow)) * H + h*HD + cb*8;
        unsigned* B1 = bufs + 2*TILE_W;
        #pragma unroll
        for (int i = 0; i < 4; i++) {
            cpa16(smaddr(&B1[0*TILE_W + d0 + i*4]), qhi + qoff + i*8);
            cpa16(smaddr(&B1[1*TILE_W + d0 + i*4]), qlo + qoff + i*8);
        }
        asm volatile("cp.async.commit_group;");
    }
    // KV tile 0 -> buffer 0
    {
        size_t base = ((size_t)(b*SEQ + lrow)) * H + h*HD + cb*8;
        #pragma unroll
        for (int i = 0; i < 4; i++) {
            cpa16(smaddr(&bufs[0*TILE_W + d0 + i*4]), khi + base + i*8);
            cpa16(smaddr(&bufs[1*TILE_W + d0 + i*4]), vhi + base + i*8);
        }
        asm volatile("cp.async.commit_group;");
    }

    asm volatile("cp.async.wait_group 1;");
    __syncthreads();

    // persistent Q fragments
    unsigned qh[4][4], ql[4][4];
    {
        const int ar = warp*16 + ((lane >> 3) & 1) * 8 + (lane & 7);
        unsigned* B1 = bufs + 2*TILE_W;
        #pragma unroll
        for (int ks = 0; ks < 4; ks++) {
            int w = ks * 8 + (lane >> 4) * 4;
            ldsm4(qh[ks][0], qh[ks][1], qh[ks][2], qh[ks][3],
                  smaddr(&B1[0*TILE_W + ar*ASTR + w]));
            ldsm4(ql[ks][0], ql[ks][1], ql[ks][2], ql[ks][3],
                  smaddr(&B1[1*TILE_W + ar*ASTR + w]));
        }
    }
    __syncthreads();   // buffer 1 free for KV prefetch

    float o[8][4];
    #pragma unroll
    for (int i = 0; i < 8; i++)
        #pragma unroll
        for (int j = 0; j < 4; j++) o[i][j] = 0.0f;
    float m0 = -1e30f, m1 = -1e30f, l0 = 0.0f, l1 = 0.0f;
    const int r = warp*16 + (lane >> 2);

    for (int kb = 0; kb < NT; kb++) {
        if (kb + 1 < NT) {
            size_t base = ((size_t)(b*SEQ + (kb+1)*64 + lrow)) * H + h*HD + cb*8;
            unsigned* Bn = bufs + ((kb+1) & 1) * 2 * TILE_W;
            #pragma unroll
            for (int i = 0; i < 4; i++) {
                cpa16(smaddr(&Bn[0*TILE_W + d0 + i*4]), khi + base + i*8);
                cpa16(smaddr(&Bn[1*TILE_W + d0 + i*4]), vhi + base + i*8);
            }
            asm volatile("cp.async.commit_group;");
            asm volatile("cp.async.wait_group 1;");
        } else {
            asm volatile("cp.async.wait_group 0;");
        }
        __syncthreads();

        unsigned* Kh = bufs + (kb & 1) * 2 * TILE_W;
        unsigned* Vh = Kh + TILE_W;

        // S = Q @ K^T (2-pass: qh*kh + ql*kh)
        float s[8][4];
        #pragma unroll
        for (int i = 0; i < 8; i++)
            #pragma unroll
            for (int j = 0; j < 4; j++) s[i][j] = 0.0f;

        #pragma unroll
        for (int ks = 0; ks < 4; ks++) {
            const int br = ((lane >> 4) & 1) * 8 + (lane & 7);
            const int bw = ks * 8 + ((lane >> 3) & 1) * 4;
            unsigned bh[4][4];
            #pragma unroll
            for (int np = 0; np < 4; np++) {
                int rr = (np*16 + br) * ASTR + bw;
                ldsm4(bh[np][0], bh[np][1], bh[np][2], bh[np][3], smaddr(&Kh[rr]));
            }
            #pragma unroll
            for (int nt = 0; nt < 8; nt++) {
                unsigned* bhp = &bh[nt >> 1][(nt & 1) * 2];
                mma16h(s[nt], qh[ks], bhp);
                mma16h(s[nt], ql[ks], bhp);
            }
        }

        // online softmax
        float mx0 = -1e30f, mx1 = -1e30f;
        #pragma unroll
        for (int nt = 0; nt < 8; nt++) {
            mx0 = fmaxf(mx0, fmaxf(s[nt][0], s[nt][1]));
            mx1 = fmaxf(mx1, fmaxf(s[nt][2], s[nt][3]));
        }
        mx0 = fmaxf(mx0, __shfl_xor_sync(0xffffffffu, mx0, 1));
        mx0 = fmaxf(mx0, __shfl_xor_sync(0xffffffffu, mx0, 2));
        mx1 = fmaxf(mx1, __shfl_xor_sync(0xffffffffu, mx1, 1));
        mx1 = fmaxf(mx1, __shfl_xor_sync(0xffffffffu, mx1, 2));
        float nm0 = fmaxf(m0, mx0), nm1 = fmaxf(m1, mx1);
        float a0 = __expf(m0 - nm0), a1 = __expf(m1 - nm1);

        float sum0 = 0.0f, sum1 = 0.0f;
        #pragma unroll
        for (int nt = 0; nt < 8; nt++) {
            s[nt][0] = __expf(s[nt][0] - nm0); sum0 += s[nt][0];
            s[nt][1] = __expf(s[nt][1] - nm0); sum0 += s[nt][1];
            s[nt][2] = __expf(s[nt][2] - nm1); sum1 += s[nt][2];
            s[nt][3] = __expf(s[nt][3] - nm1); sum1 += s[nt][3];
        }
        sum0 += __shfl_xor_sync(0xffffffffu, sum0, 1);
        sum0 += __shfl_xor_sync(0xffffffffu, sum0, 2);
        sum1 += __shfl_xor_sync(0xffffffffu, sum1, 1);
        sum1 += __shfl_xor_sync(0xffffffffu, sum1, 2);
        l0 = l0*a0 + sum0;  l1 = l1*a1 + sum1;
        m0 = nm0;           m1 = nm1;
        #pragma unroll
        for (int nt = 0; nt < 8; nt++) {
            o[nt][0] *= a0; o[nt][1] *= a0;
            o[nt][2] *= a1; o[nt][3] *= a1;
        }

        // O += P @ V  (2-pass: ph*vh + pl*vh), P built from S registers
        #pragma unroll
        for (int ks = 0; ks < 4; ks++) {
            unsigned ph[4], pl[4];
            split2h(s[2*ks][0],   s[2*ks][1],   ph[0], pl[0]);
            split2h(s[2*ks][2],   s[2*ks][3],   ph[1], pl[1]);
            split2h(s[2*ks+1][0], s[2*ks+1][1], ph[2], pl[2]);
            split2h(s[2*ks+1][2], s[2*ks+1][3], ph[3], pl[3]);

            const int vr = ks*16 + ((lane >> 3) & 1) * 8 + (lane & 7);
            unsigned vh[4][4];
            #pragma unroll
            for (int np = 0; np < 4; np++) {
                int vw = np*8 + (lane >> 4) * 4;
                ldsm4t(vh[np][0], vh[np][1], vh[np][2], vh[np][3], smaddr(&Vh[vr*ASTR + vw]));
            }
            #pragma unroll
            for (int nt = 0; nt < 8; nt++) {
                unsigned* bvh = &vh[nt >> 1][(nt & 1) * 2];
                mma16h(o[nt], ph, bvh);
                mma16h(o[nt], pl, bvh);
            }
        }
        __syncthreads();
    }

    float inv0 = 1.0f / l0, inv1 = 1.0f / l1;
    size_t gr0 = (size_t)(b*SEQ + qb*64 + r) * H + h*HD;
    size_t gr1 = (size_t)(b*SEQ + qb*64 + r + 8) * H + h*HD;
    int col = (lane & 3) * 2;
    #pragma unroll
    for (int nt = 0; nt < 8; nt++) {
        unsigned hh, ll;
        split2h(o[nt][0]*inv0, o[nt][1]*inv0, hh, ll);
        *(unsigned*)(athi + gr0 + nt*8 + col) = hh;
        *(unsigned*)(atlo + gr0 + nt*8 + col) = ll;
        split2h(o[nt][2]*inv1, o[nt][3]*inv1, hh, ll);
        *(unsigned*)(athi + gr1 + nt*8 + col) = hh;
        *(unsigned*)(atlo + gr1 + nt*8 + col) = ll;
    }
}

// ---------------------------------------------------------------------------
extern "C" void kernel_launch(void* const* d_in, const int* in_sizes, int n_in,
                              void* d_out, int out_size)
{
    const float* x  = (const float*)d_in[0];
    const float* Wq = (const float*)d_in[1];
    const float* bq = (const float*)d_in[2];
    const float* Wk = (const float*)d_in[3];
    const float* bk = (const float*)d_in[4];
    const float* Wv = (const float*)d_in[5];
    const float* bv = (const float*)d_in[6];
    const float* Ws = (const float*)d_in[7];
    const float* bs = (const float*)d_in[8];
    const float* Wo = (const float*)d_in[9];
    const float* bo = (const float*)d_in[10];

    __half *xh, *xl, *qh, *ql, *kh, *vh, *ath, *atl;
    __half *wqkvh, *woh, *wol, *wath, *wch;
    float *bqkvp, *bcp, *zerop;
    cudaGetSymbolAddress((void**)&xh, g_xh);   cudaGetSymbolAddress((void**)&xl, g_xl);
    cudaGetSymbolAddress((void**)&qh, g_qh);   cudaGetSymbolAddress((void**)&ql, g_ql);
    cudaGetSymbolAddress((void**)&kh, g_kh);
    cudaGetSymbolAddress((void**)&vh, g_vh);
    cudaGetSymbolAddress((void**)&ath, g_ath); cudaGetSymbolAddress((void**)&atl, g_atl);
    cudaGetSymbolAddress((void**)&wqkvh, g_wqkvh);
    cudaGetSymbolAddress((void**)&woh, g_woh); cudaGetSymbolAddress((void**)&wol, g_wol);
    cudaGetSymbolAddress((void**)&wath, g_wath);
    cudaGetSymbolAddress((void**)&wch, g_wch);
    cudaGetSymbolAddress((void**)&bqkvp, g_bqkv);
    cudaGetSymbolAddress((void**)&bcp, g_bc);
    cudaGetSymbolAddress((void**)&zerop, g_zero);

    cudaFuncSetAttribute(attn_h2,
                         cudaFuncAttributeMaxDynamicSharedMemorySize, ATTN_SMEM);
    cudaFuncSetAttribute(gemm_sp<0>,
                         cudaFuncAttributeMaxDynamicSharedMemorySize, GEMM_SMEM);
    cudaFuncSetAttribute(gemm_sp<1>,
                         cudaFuncAttributeMaxDynamicSharedMemorySize, GEMM_SMEM);
    cudaFuncSetAttribute(gemm_sp<2>,
                         cudaFuncAttributeMaxDynamicSharedMemorySize, GEMM_SMEM);

    // pre-split / precompute
    split_h<<<(ROWS*H + 255)/256, 256>>>(x, xh, xl, ROWS*H);
    trunc_h<<<(H*H + 255)/256, 256>>>(Wq, wqkvh,         H*H);
    trunc_h<<<(H*H + 255)/256, 256>>>(Wk, wqkvh + H*H,   H*H);
    trunc_h<<<(H*H + 255)/256, 256>>>(Wv, wqkvh + 2*H*H, H*H);
    split_h<<<(H*H + 255)/256, 256>>>(Wo, woh, wol, H*H);
    packb<<<4, 256>>>(bq, bk, bv, bs);
    avgT_split<<<dim3(32, 32), dim3(32, 8)>>>(Ws);

    // Wc = Wo @ mean(Ws): A = Wo split, B = WaT hi
    gemm_sp<1><<<dim3(8, 8), 256, GEMM_SMEM>>>(
        woh, wol, wath, zerop, 1.0f,
        nullptr, wch, nullptr, nullptr, nullptr, H, H, H);
    bc_kernel<<<H/8, 256>>>(Wo, bo);

    // fused QKV: [4096, 3072]; Q band scaled+split, K/V bands hi-only
    gemm_sp<2><<<dim3(3*H/128, ROWS/128), 256, GEMM_SMEM>>>(
        xh, xl, wqkvh, bqkvp, 0.125f,
        nullptr, qh, ql, kh, vh, ROWS, 3*H, H);

    attn_h2<<<dim3(SEQ/64, NHEADS, BATCH), 128, ATTN_SMEM>>>(
        qh, ql, kh, vh, ath, atl);

    // out = att @ Wc^T + bc
    gemm_sp<0><<<dim3(H/128, ROWS/128), 256, GEMM_SMEM>>>(
        ath, atl, wch, bcp, 1.0f,
        (float*)d_out, nullptr, nullptr, nullptr, nullptr, ROWS, H, H);
}

// round 10
// speedup vs baseline: 8.4454x; 1.2572x over previous
#include <cuda_runtime.h>
#include <cuda_fp16.h>
#include <math.h>
#include <stdint.h>

#define H 1024
#define NHEADS 16
#define HD 64
#define SEQ 2048
#define BATCH 2
#define ROWS (BATCH*SEQ)   // 4096

// ---------------- scratch (device globals; allocation-free) ----------------
__device__ __half g_xh[ROWS*H];
__device__ __half g_qh[ROWS*H],  g_ql[ROWS*H];
__device__ __half g_kh[ROWS*H];
__device__ __half g_vh[ROWS*H];
__device__ __half g_ath[ROWS*H], g_atl[ROWS*H];
__device__ __half g_wqkvh[3*H*H];          // packed Wq|Wk|Wv, hi only
__device__ __half g_woh[H*H], g_wol[H*H];  // Wo split (A of Wc GEMM)
__device__ __half g_wath[H*H];             // mean(Ws)^T hi only
__device__ __half g_wch[H*H];              // Wc = Wo @ Wa, hi only
__device__ float g_bqkv[3*H];
__device__ float g_bavg[H];
__device__ float g_bc[H];
__device__ float g_zero[H];                // stays 0

// ---------------------------------------------------------------------------
__device__ __forceinline__ unsigned smaddr(const void* p) {
    return (unsigned)__cvta_generic_to_shared(p);
}
__device__ __forceinline__ void ldsm4(unsigned& r0, unsigned& r1, unsigned& r2,
                                      unsigned& r3, unsigned a) {
    asm volatile("ldmatrix.sync.aligned.m8n8.x4.shared.b16 {%0,%1,%2,%3}, [%4];"
                 : "=r"(r0), "=r"(r1), "=r"(r2), "=r"(r3) : "r"(a));
}
__device__ __forceinline__ void ldsm4t(unsigned& r0, unsigned& r1, unsigned& r2,
                                       unsigned& r3, unsigned a) {
    asm volatile("ldmatrix.sync.aligned.m8n8.x4.trans.shared.b16 {%0,%1,%2,%3}, [%4];"
                 : "=r"(r0), "=r"(r1), "=r"(r2), "=r"(r3) : "r"(a));
}
__device__ __forceinline__ void mma16h(float* c, const unsigned* a, const unsigned* b) {
    asm volatile(
        "mma.sync.aligned.m16n8k16.row.col.f32.f16.f16.f32 "
        "{%0,%1,%2,%3}, {%4,%5,%6,%7}, {%8,%9}, {%0,%1,%2,%3};"
        : "+f"(c[0]), "+f"(c[1]), "+f"(c[2]), "+f"(c[3])
        : "r"(a[0]), "r"(a[1]), "r"(a[2]), "r"(a[3]), "r"(b[0]), "r"(b[1]));
}
__device__ __forceinline__ void cpa16(unsigned dst, const void* src) {
    asm volatile("cp.async.ca.shared.global [%0], [%1], 16;" :: "r"(dst), "l"(src));
}
__device__ __forceinline__ void split2h(float x0, float x1, unsigned& hi, unsigned& lo) {
    __half h0 = __float2half_rn(x0), h1 = __float2half_rn(x1);
    __half e0 = __float2half_rn(x0 - __half2float(h0));
    __half e1 = __float2half_rn(x1 - __half2float(h1));
    hi = ((unsigned)__half_as_ushort(h1) << 16) | __half_as_ushort(h0);
    lo = ((unsigned)__half_as_ushort(e1) << 16) | __half_as_ushort(e0);
}
__device__ __forceinline__ unsigned pack2h(float x0, float x1) {
    __half h0 = __float2half_rn(x0), h1 = __float2half_rn(x1);
    return ((unsigned)__half_as_ushort(h1) << 16) | __half_as_ushort(h0);
}

// ---------------------------------------------------------------------------
// fused prep: x trunc, Wq/Wk/Wv trunc (packed), Wo split, bias packing
// ---------------------------------------------------------------------------
__global__ void prep_all(const float* __restrict__ x,
                         const float* __restrict__ Wq, const float* __restrict__ Wk,
                         const float* __restrict__ Wv, const float* __restrict__ Wo,
                         const float* __restrict__ bq, const float* __restrict__ bk,
                         const float* __restrict__ bv, const float* __restrict__ bs)
{
    int i = blockIdx.x * 256 + threadIdx.x;
    if (i < ROWS*H) g_xh[i] = __float2half_rn(x[i]);
    if (i < H*H) {
        g_wqkvh[i]         = __float2half_rn(Wq[i]);
        g_wqkvh[H*H + i]   = __float2half_rn(Wk[i]);
        g_wqkvh[2*H*H + i] = __float2half_rn(Wv[i]);
        float w = Wo[i];
        __half h = __float2half_rn(w);
        g_woh[i] = h;
        g_wol[i] = __float2half_rn(w - __half2float(h));
    }
    if (i < H) {
        g_bqkv[i]       = bq[i];
        g_bqkv[H + i]   = bk[i];
        g_bqkv[2*H + i] = bv[i];
        g_bavg[i] = (bs[i] + bs[i + H] + bs[i + 2*H]) * (1.0f/3.0f);
    }
}
// WaT[h][j] = mean_n Ws[n][j][h], hi only (B side of Wc GEMM)
__global__ void avgT_split(const float* __restrict__ Ws)
{
    __shared__ float tile[32][33];
    int j0 = blockIdx.x * 32, h0 = blockIdx.y * 32;
    int tx = threadIdx.x, ty = threadIdx.y;
    #pragma unroll
    for (int dy = 0; dy < 32; dy += 8) {
        int j = j0 + ty + dy, h = h0 + tx;
        tile[ty + dy][tx] = (Ws[j*H + h] + Ws[H*H + j*H + h] + Ws[2*H*H + j*H + h])
                            * (1.0f/3.0f);
    }
    __syncthreads();
    #pragma unroll
    for (int dy = 0; dy < 32; dy += 8) {
        int h = h0 + ty + dy, j = j0 + tx;
        g_wath[h*H + j] = __float2half_rn(tile[tx][ty + dy]);
    }
}
__global__ void bc_kernel(const float* __restrict__ Wo, const float* __restrict__ bo)
{
    int g = blockIdx.x * 8 + (threadIdx.x >> 5);
    int lane = threadIdx.x & 31;
    float s = 0.0f;
    for (int j = lane; j < H; j += 32) s += Wo[(size_t)g*H + j] * g_bavg[j];
    #pragma unroll
    for (int o = 16; o; o >>= 1) s += __shfl_xor_sync(0xffffffffu, s, o);
    if (lane == 0) g_bc[g] = s + bo[g];
}

// ---------------------------------------------------------------------------
// GEMM: C = A[M,K] @ Bhi[N,K]^T + bias.  AP = A passes (1: hi only, 2: hi+lo).
// BM=BN=128, BK=32, 256 thr, cp.async double-buffered, (AP+1) smem arrays.
// OUTMODE 0: fp32 C.  1: hi-only Ohi.  2: QKV routing (Q split+scale, K hi, V hi).
// ---------------------------------------------------------------------------
#define GSTR 20
#define GARR (128*GSTR)
template<int OUTMODE, int AP>
__global__ __launch_bounds__(256, 2) void gemm_sp(
    const __half* __restrict__ Ahi, const __half* __restrict__ Alo,
    const __half* __restrict__ Bhi,
    const float* __restrict__ bias, float scale,
    float* __restrict__ C,
    __half* __restrict__ Ohi,  __half* __restrict__ Olo,
    __half* __restrict__ Khi,  __half* __restrict__ Vhi,
    int M, int N, int K)
{
    extern __shared__ unsigned gsm[];
    const int NARR = AP + 1;
    const int t = threadIdx.x, lane = t & 31, warp = t >> 5;
    const int wm = (warp >> 2) * 64, wn = (warp & 3) * 32;
    const int m0 = blockIdx.y * 128, n0 = blockIdx.x * 128;

    float acc[16][4];
    #pragma unroll
    for (int i = 0; i < 16; i++)
        #pragma unroll
        for (int j = 0; j < 4; j++) acc[i][j] = 0.0f;

    const int lr = t >> 1, half = t & 1;
    const size_t arow = (size_t)(m0 + lr) * K + half * 16;
    const size_t brow = (size_t)(n0 + lr) * K + half * 16;
    const int sw = lr * GSTR + half * 8;
    const int NB = K / 32;

    {
        unsigned* B0 = gsm;
        cpa16(smaddr(&B0[0*GARR + sw]),     Ahi + arow);
        cpa16(smaddr(&B0[0*GARR + sw + 4]), Ahi + arow + 8);
        if (AP == 2) {
            cpa16(smaddr(&B0[1*GARR + sw]),     Alo + arow);
            cpa16(smaddr(&B0[1*GARR + sw + 4]), Alo + arow + 8);
        }
        cpa16(smaddr(&B0[(NARR-1)*GARR + sw]),     Bhi + brow);
        cpa16(smaddr(&B0[(NARR-1)*GARR + sw + 4]), Bhi + brow + 8);
        asm volatile("cp.async.commit_group;");
    }

    for (int bi = 0; bi < NB; bi++) {
        if (bi + 1 < NB) {
            unsigned* Bn = gsm + ((bi + 1) & 1) * NARR * GARR;
            size_t ko = (size_t)(bi + 1) * 32;
            cpa16(smaddr(&Bn[0*GARR + sw]),     Ahi + arow + ko);
            cpa16(smaddr(&Bn[0*GARR + sw + 4]), Ahi + arow + ko + 8);
            if (AP == 2) {
                cpa16(smaddr(&Bn[1*GARR + sw]),     Alo + arow + ko);
                cpa16(smaddr(&Bn[1*GARR + sw + 4]), Alo + arow + ko + 8);
            }
            cpa16(smaddr(&Bn[(NARR-1)*GARR + sw]),     Bhi + brow + ko);
            cpa16(smaddr(&Bn[(NARR-1)*GARR + sw + 4]), Bhi + brow + ko + 8);
            asm volatile("cp.async.commit_group;");
            asm volatile("cp.async.wait_group 1;");
        } else {
            asm volatile("cp.async.wait_group 0;");
        }
        __syncthreads();

        unsigned* Ah = gsm + (bi & 1) * NARR * GARR;
        unsigned* Al = Ah + GARR;                 // valid only if AP==2
        unsigned* Bh = Ah + (NARR-1)*GARR;

        #pragma unroll
        for (int ks = 0; ks < 2; ks++) {
            const int ar = ((lane >> 3) & 1) * 8 + (lane & 7);
            const int aw = ks * 8 + (lane >> 4) * 4;
            unsigned ah[4][4], am[4][4];
            #pragma unroll
            for (int mt = 0; mt < 4; mt++) {
                int r = (wm + mt*16 + ar) * GSTR + aw;
                ldsm4(ah[mt][0], ah[mt][1], ah[mt][2], ah[mt][3], smaddr(&Ah[r]));
                if (AP == 2)
                    ldsm4(am[mt][0], am[mt][1], am[mt][2], am[mt][3], smaddr(&Al[r]));
            }
            const int br = ((lane >> 4) & 1) * 8 + (lane & 7);
            const int bw = ks * 8 + ((lane >> 3) & 1) * 4;
            unsigned bh[2][4];
            #pragma unroll
            for (int np = 0; np < 2; np++) {
                int r = (wn + np*16 + br) * GSTR + bw;
                ldsm4(bh[np][0], bh[np][1], bh[np][2], bh[np][3], smaddr(&Bh[r]));
            }
            #pragma unroll
            for (int mt = 0; mt < 4; mt++)
                #pragma unroll
                for (int nt = 0; nt < 4; nt++) {
                    unsigned* bhp = &bh[nt >> 1][(nt & 1) * 2];
                    mma16h(acc[mt*4+nt], ah[mt], bhp);
                    if (AP == 2) mma16h(acc[mt*4+nt], am[mt], bhp);
                }
        }
        __syncthreads();
    }

    #pragma unroll
    for (int mt = 0; mt < 4; mt++) {
        int row = m0 + wm + mt*16 + (lane >> 2);
        #pragma unroll
        for (int nt = 0; nt < 4; nt++) {
            int col = n0 + wn + nt*8 + (lane & 3) * 2;
            float b0 = __ldg(bias + col), b1 = __ldg(bias + col + 1);
            float* a = acc[mt*4+nt];
            float v00 = a[0] + b0, v01 = a[1] + b1;
            float v10 = a[2] + b0, v11 = a[3] + b1;
            if (OUTMODE == 0) {
                float2 u;
                u.x = v00; u.y = v01; *(float2*)(C + (size_t)row * N + col) = u;
                u.x = v10; u.y = v11; *(float2*)(C + (size_t)(row + 8) * N + col) = u;
            } else if (OUTMODE == 1) {
                *(unsigned*)(Ohi + (size_t)row * N + col)       = pack2h(v00, v01);
                *(unsigned*)(Ohi + (size_t)(row + 8) * N + col) = pack2h(v10, v11);
            } else {
                int which = n0 >> 10;
                int cl = col & 1023;
                if (which == 0) {
                    unsigned hh, ll;
                    split2h(v00 * scale, v01 * scale, hh, ll);
                    *(unsigned*)(Ohi + (size_t)row * H + cl) = hh;
                    *(unsigned*)(Olo + (size_t)row * H + cl) = ll;
                    split2h(v10 * scale, v11 * scale, hh, ll);
                    *(unsigned*)(Ohi + (size_t)(row + 8) * H + cl) = hh;
                    *(unsigned*)(Olo + (size_t)(row + 8) * H + cl) = ll;
                } else {
                    __half* dst = (which == 1) ? Khi : Vhi;
                    *(unsigned*)(dst + (size_t)row * H + cl)       = pack2h(v00, v01);
                    *(unsigned*)(dst + (size_t)(row + 8) * H + cl) = pack2h(v10, v11);
                }
            }
        }
    }
}

// ---------------------------------------------------------------------------
// Flash attention: S = (Qhi+Qlo) @ Khi^T (2-pass), O = Phi @ Vhi (1-pass).
// CTA = 64 q-rows, 4 warps; K/V hi-only double-buffered via cp.async.
// Q staged through buffer 1. P in registers. Split fp16 output.
// ---------------------------------------------------------------------------
#define ASTR 36
#define TILE_W (64*ASTR)
#define ATTN_SMEM (4*TILE_W*4)  // 36864 B

__global__ __launch_bounds__(128, 3) void attn_h2(
    const __half* __restrict__ qhi, const __half* __restrict__ qlo,
    const __half* __restrict__ khi, const __half* __restrict__ vhi,
    __half* __restrict__ athi, __half* __restrict__ atlo)
{
    extern __shared__ unsigned smu[];
    unsigned* bufs = smu;

    const int t = threadIdx.x, lane = t & 31, warp = t >> 5;
    const int qb = blockIdx.x, h = blockIdx.y, b = blockIdx.z;
    const int lrow = t >> 1, cb = (t & 1) * 4;
    const int NT = SEQ / 64;
    const unsigned d0 = lrow * ASTR + cb * 4;

    {
        size_t qoff = ((size_t)(b*SEQ + qb*64 + lrow)) * H + h*HD + cb*8;
        unsigned* B1 = bufs + 2*TILE_W;
        #pragma unroll
        for (int i = 0; i < 4; i++) {
            cpa16(smaddr(&B1[0*TILE_W + d0 + i*4]), qhi + qoff + i*8);
            cpa16(smaddr(&B1[1*TILE_W + d0 + i*4]), qlo + qoff + i*8);
        }
        asm volatile("cp.async.commit_group;");
    }
    {
        size_t base = ((size_t)(b*SEQ + lrow)) * H + h*HD + cb*8;
        #pragma unroll
        for (int i = 0; i < 4; i++) {
            cpa16(smaddr(&bufs[0*TILE_W + d0 + i*4]), khi + base + i*8);
            cpa16(smaddr(&bufs[1*TILE_W + d0 + i*4]), vhi + base + i*8);
        }
        asm volatile("cp.async.commit_group;");
    }

    asm volatile("cp.async.wait_group 1;");
    __syncthreads();

    unsigned qh[4][4], ql[4][4];
    {
        const int ar = warp*16 + ((lane >> 3) & 1) * 8 + (lane & 7);
        unsigned* B1 = bufs + 2*TILE_W;
        #pragma unroll
        for (int ks = 0; ks < 4; ks++) {
            int w = ks * 8 + (lane >> 4) * 4;
            ldsm4(qh[ks][0], qh[ks][1], qh[ks][2], qh[ks][3],
                  smaddr(&B1[0*TILE_W + ar*ASTR + w]));
            ldsm4(ql[ks][0], ql[ks][1], ql[ks][2], ql[ks][3],
                  smaddr(&B1[1*TILE_W + ar*ASTR + w]));
        }
    }
    __syncthreads();

    float o[8][4];
    #pragma unroll
    for (int i = 0; i < 8; i++)
        #pragma unroll
        for (int j = 0; j < 4; j++) o[i][j] = 0.0f;
    float m0 = -1e30f, m1 = -1e30f, l0 = 0.0f, l1 = 0.0f;
    const int r = warp*16 + (lane >> 2);

    for (int kb = 0; kb < NT; kb++) {
        if (kb + 1 < NT) {
            size_t base = ((size_t)(b*SEQ + (kb+1)*64 + lrow)) * H + h*HD + cb*8;
            unsigned* Bn = bufs + ((kb+1) & 1) * 2 * TILE_W;
            #pragma unroll
            for (int i = 0; i < 4; i++) {
                cpa16(smaddr(&Bn[0*TILE_W + d0 + i*4]), khi + base + i*8);
                cpa16(smaddr(&Bn[1*TILE_W + d0 + i*4]), vhi + base + i*8);
            }
            asm volatile("cp.async.commit_group;");
            asm volatile("cp.async.wait_group 1;");
        } else {
            asm volatile("cp.async.wait_group 0;");
        }
        __syncthreads();

        unsigned* Kh = bufs + (kb & 1) * 2 * TILE_W;
        unsigned* Vh = Kh + TILE_W;

        float s[8][4];
        #pragma unroll
        for (int i = 0; i < 8; i++)
            #pragma unroll
            for (int j = 0; j < 4; j++) s[i][j] = 0.0f;

        #pragma unroll
        for (int ks = 0; ks < 4; ks++) {
            const int br = ((lane >> 4) & 1) * 8 + (lane & 7);
            const int bw = ks * 8 + ((lane >> 3) & 1) * 4;
            unsigned bh[4][4];
            #pragma unroll
            for (int np = 0; np < 4; np++) {
                int rr = (np*16 + br) * ASTR + bw;
                ldsm4(bh[np][0], bh[np][1], bh[np][2], bh[np][3], smaddr(&Kh[rr]));
            }
            #pragma unroll
            for (int nt = 0; nt < 8; nt++) {
                unsigned* bhp = &bh[nt >> 1][(nt & 1) * 2];
                mma16h(s[nt], qh[ks], bhp);
                mma16h(s[nt], ql[ks], bhp);
            }
        }

        float mx0 = -1e30f, mx1 = -1e30f;
        #pragma unroll
        for (int nt = 0; nt < 8; nt++) {
            mx0 = fmaxf(mx0, fmaxf(s[nt][0], s[nt][1]));
            mx1 = fmaxf(mx1, fmaxf(s[nt][2], s[nt][3]));
        }
        mx0 = fmaxf(mx0, __shfl_xor_sync(0xffffffffu, mx0, 1));
        mx0 = fmaxf(mx0, __shfl_xor_sync(0xffffffffu, mx0, 2));
        mx1 = fmaxf(mx1, __shfl_xor_sync(0xffffffffu, mx1, 1));
        mx1 = fmaxf(mx1, __shfl_xor_sync(0xffffffffu, mx1, 2));
        float nm0 = fmaxf(m0, mx0), nm1 = fmaxf(m1, mx1);
        float a0 = __expf(m0 - nm0), a1 = __expf(m1 - nm1);

        float sum0 = 0.0f, sum1 = 0.0f;
        #pragma unroll
        for (int nt = 0; nt < 8; nt++) {
            s[nt][0] = __expf(s[nt][0] - nm0); sum0 += s[nt][0];
            s[nt][1] = __expf(s[nt][1] - nm0); sum0 += s[nt][1];
            s[nt][2] = __expf(s[nt][2] - nm1); sum1 += s[nt][2];
            s[nt][3] = __expf(s[nt][3] - nm1); sum1 += s[nt][3];
        }
        sum0 += __shfl_xor_sync(0xffffffffu, sum0, 1);
        sum0 += __shfl_xor_sync(0xffffffffu, sum0, 2);
        sum1 += __shfl_xor_sync(0xffffffffu, sum1, 1);
        sum1 += __shfl_xor_sync(0xffffffffu, sum1, 2);
        l0 = l0*a0 + sum0;  l1 = l1*a1 + sum1;
        m0 = nm0;           m1 = nm1;
        #pragma unroll
        for (int nt = 0; nt < 8; nt++) {
            o[nt][0] *= a0; o[nt][1] *= a0;
            o[nt][2] *= a1; o[nt][3] *= a1;
        }

        // O += P @ V  (single pass, P fp16 from S registers)
        #pragma unroll
        for (int ks = 0; ks < 4; ks++) {
            unsigned ph[4];
            ph[0] = pack2h(s[2*ks][0],   s[2*ks][1]);
            ph[1] = pack2h(s[2*ks][2],   s[2*ks][3]);
            ph[2] = pack2h(s[2*ks+1][0], s[2*ks+1][1]);
            ph[3] = pack2h(s[2*ks+1][2], s[2*ks+1][3]);

            const int vr = ks*16 + ((lane >> 3) & 1) * 8 + (lane & 7);
            unsigned vh[4][4];
            #pragma unroll
            for (int np = 0; np < 4; np++) {
                int vw = np*8 + (lane >> 4) * 4;
                ldsm4t(vh[np][0], vh[np][1], vh[np][2], vh[np][3], smaddr(&Vh[vr*ASTR + vw]));
            }
            #pragma unroll
            for (int nt = 0; nt < 8; nt++) {
                unsigned* bvh = &vh[nt >> 1][(nt & 1) * 2];
                mma16h(o[nt], ph, bvh);
            }
        }
        __syncthreads();
    }

    float inv0 = 1.0f / l0, inv1 = 1.0f / l1;
    size_t gr0 = (size_t)(b*SEQ + qb*64 + r) * H + h*HD;
    size_t gr1 = (size_t)(b*SEQ + qb*64 + r + 8) * H + h*HD;
    int col = (lane & 3) * 2;
    #pragma unroll
    for (int nt = 0; nt < 8; nt++) {
        unsigned hh, ll;
        split2h(o[nt][0]*inv0, o[nt][1]*inv0, hh, ll);
        *(unsigned*)(athi + gr0 + nt*8 + col) = hh;
        *(unsigned*)(atlo + gr0 + nt*8 + col) = ll;
        split2h(o[nt][2]*inv1, o[nt][3]*inv1, hh, ll);
        *(unsigned*)(athi + gr1 + nt*8 + col) = hh;
        *(unsigned*)(atlo + gr1 + nt*8 + col) = ll;
    }
}

// ---------------------------------------------------------------------------
extern "C" void kernel_launch(void* const* d_in, const int* in_sizes, int n_in,
                              void* d_out, int out_size)
{
    const float* x  = (const float*)d_in[0];
    const float* Wq = (const float*)d_in[1];
    const float* bq = (const float*)d_in[2];
    const float* Wk = (const float*)d_in[3];
    const float* bk = (const float*)d_in[4];
    const float* Wv = (const float*)d_in[5];
    const float* bv = (const float*)d_in[6];
    const float* Ws = (const float*)d_in[7];
    const float* bs = (const float*)d_in[8];
    const float* Wo = (const float*)d_in[9];
    const float* bo = (const float*)d_in[10];

    __half *xh, *qh, *ql, *kh, *vh, *ath, *atl;
    __half *wqkvh, *woh, *wol, *wath, *wch;
    float *bqkvp, *bcp, *zerop;
    cudaGetSymbolAddress((void**)&xh, g_xh);
    cudaGetSymbolAddress((void**)&qh, g_qh);   cudaGetSymbolAddress((void**)&ql, g_ql);
    cudaGetSymbolAddress((void**)&kh, g_kh);
    cudaGetSymbolAddress((void**)&vh, g_vh);
    cudaGetSymbolAddress((void**)&ath, g_ath); cudaGetSymbolAddress((void**)&atl, g_atl);
    cudaGetSymbolAddress((void**)&wqkvh, g_wqkvh);
    cudaGetSymbolAddress((void**)&woh, g_woh); cudaGetSymbolAddress((void**)&wol, g_wol);
    cudaGetSymbolAddress((void**)&wath, g_wath);
    cudaGetSymbolAddress((void**)&wch, g_wch);
    cudaGetSymbolAddress((void**)&bqkvp, g_bqkv);
    cudaGetSymbolAddress((void**)&bcp, g_bc);
    cudaGetSymbolAddress((void**)&zerop, g_zero);

    const int SM1 = 2*2*GARR*4;   // AP=1: 40960 B
    const int SM2 = 2*3*GARR*4;   // AP=2: 61440 B
    cudaFuncSetAttribute(attn_h2,
                         cudaFuncAttributeMaxDynamicSharedMemorySize, ATTN_SMEM);
    cudaFuncSetAttribute(gemm_sp<0,2>,
                         cudaFuncAttributeMaxDynamicSharedMemorySize, SM2);
    cudaFuncSetAttribute(gemm_sp<1,2>,
                         cudaFuncAttributeMaxDynamicSharedMemorySize, SM2);
    cudaFuncSetAttribute(gemm_sp<2,1>,
                         cudaFuncAttributeMaxDynamicSharedMemorySize, SM1);

    // fused prep
    prep_all<<<(ROWS*H + 255)/256, 256>>>(x, Wq, Wk, Wv, Wo, bq, bk, bv, bs);
    avgT_split<<<dim3(32, 32), dim3(32, 8)>>>(Ws);

    // Wc = Wo @ mean(Ws): A = Wo split (2-pass), B = WaT hi
    gemm_sp<1,2><<<dim3(8, 8), 256, SM2>>>(
        woh, wol, wath, zerop, 1.0f,
        nullptr, wch, nullptr, nullptr, nullptr, H, H, H);
    bc_kernel<<<H/8, 256>>>(Wo, bo);

    // fused QKV (single-pass A): [4096, 3072]
    gemm_sp<2,1><<<dim3(3*H/128, ROWS/128), 256, SM1>>>(
        xh, nullptr, wqkvh, bqkvp, 0.125f,
        nullptr, qh, ql, kh, vh, ROWS, 3*H, H);

    attn_h2<<<dim3(SEQ/64, NHEADS, BATCH), 128, ATTN_SMEM>>>(
        qh, ql, kh, vh, ath, atl);

    // out = att @ Wc^T + bc (2-pass A)
    gemm_sp<0,2><<<dim3(H/128, ROWS/128), 256, SM2>>>(
        ath, atl, wch, bcp, 1.0f,
        (float*)d_out, nullptr, nullptr, nullptr, nullptr, ROWS, H, H);
}

// round 11
// speedup vs baseline: 9.2235x; 1.0921x over previous
#include <cuda_runtime.h>
#include <cuda_fp16.h>
#include <math.h>
#include <stdint.h>

#define H 1024
#define NHEADS 16
#define HD 64
#define SEQ 2048
#define BATCH 2
#define ROWS (BATCH*SEQ)   // 4096

// ---------------- scratch (device globals; allocation-free) ----------------
__device__ __half g_xh[ROWS*H];
__device__ __half g_qh[ROWS*H];
__device__ __half g_kh[ROWS*H];
__device__ __half g_vh[ROWS*H];
__device__ __half g_ath[ROWS*H];
__device__ __half g_wqkvh[3*H*H];          // packed Wq|Wk|Wv, hi only
__device__ __half g_woh[H*H], g_wol[H*H];  // Wo split (A of Wc GEMM)
__device__ __half g_wath[H*H];             // mean(Ws)^T hi only
__device__ __half g_wch[H*H];              // Wc = Wo @ Wa, hi only
__device__ float g_bqkv[3*H];
__device__ float g_bavg[H];
__device__ float g_bc[H];
__device__ float g_zero[H];                // stays 0

// ---------------------------------------------------------------------------
__device__ __forceinline__ unsigned smaddr(const void* p) {
    return (unsigned)__cvta_generic_to_shared(p);
}
__device__ __forceinline__ void ldsm4(unsigned& r0, unsigned& r1, unsigned& r2,
                                      unsigned& r3, unsigned a) {
    asm volatile("ldmatrix.sync.aligned.m8n8.x4.shared.b16 {%0,%1,%2,%3}, [%4];"
                 : "=r"(r0), "=r"(r1), "=r"(r2), "=r"(r3) : "r"(a));
}
__device__ __forceinline__ void ldsm4t(unsigned& r0, unsigned& r1, unsigned& r2,
                                       unsigned& r3, unsigned a) {
    asm volatile("ldmatrix.sync.aligned.m8n8.x4.trans.shared.b16 {%0,%1,%2,%3}, [%4];"
                 : "=r"(r0), "=r"(r1), "=r"(r2), "=r"(r3) : "r"(a));
}
__device__ __forceinline__ void mma16h(float* c, const unsigned* a, const unsigned* b) {
    asm volatile(
        "mma.sync.aligned.m16n8k16.row.col.f32.f16.f16.f32 "
        "{%0,%1,%2,%3}, {%4,%5,%6,%7}, {%8,%9}, {%0,%1,%2,%3};"
        : "+f"(c[0]), "+f"(c[1]), "+f"(c[2]), "+f"(c[3])
        : "r"(a[0]), "r"(a[1]), "r"(a[2]), "r"(a[3]), "r"(b[0]), "r"(b[1]));
}
__device__ __forceinline__ void cpa16(unsigned dst, const void* src) {
    asm volatile("cp.async.ca.shared.global [%0], [%1], 16;" :: "r"(dst), "l"(src));
}
__device__ __forceinline__ unsigned pack2h(float x0, float x1) {
    __half h0 = __float2half_rn(x0), h1 = __float2half_rn(x1);
    return ((unsigned)__half_as_ushort(h1) << 16) | __half_as_ushort(h0);
}

// ---------------------------------------------------------------------------
// fused prep: x trunc, Wq/Wk/Wv trunc (packed), Wo split, bias packing
// ---------------------------------------------------------------------------
__global__ void prep_all(const float* __restrict__ x,
                         const float* __restrict__ Wq, const float* __restrict__ Wk,
                         const float* __restrict__ Wv, const float* __restrict__ Wo,
                         const float* __restrict__ bq, const float* __restrict__ bk,
                         const float* __restrict__ bv, const float* __restrict__ bs)
{
    int i = blockIdx.x * 256 + threadIdx.x;
    if (i < ROWS*H) g_xh[i] = __float2half_rn(x[i]);
    if (i < H*H) {
        g_wqkvh[i]         = __float2half_rn(Wq[i]);
        g_wqkvh[H*H + i]   = __float2half_rn(Wk[i]);
        g_wqkvh[2*H*H + i] = __float2half_rn(Wv[i]);
        float w = Wo[i];
        __half h = __float2half_rn(w);
        g_woh[i] = h;
        g_wol[i] = __float2half_rn(w - __half2float(h));
    }
    if (i < H) {
        g_bqkv[i]       = bq[i];
        g_bqkv[H + i]   = bk[i];
        g_bqkv[2*H + i] = bv[i];
        g_bavg[i] = (bs[i] + bs[i + H] + bs[i + 2*H]) * (1.0f/3.0f);
    }
}
// WaT[h][j] = mean_n Ws[n][j][h], hi only (B side of Wc GEMM)
__global__ void avgT_split(const float* __restrict__ Ws)
{
    __shared__ float tile[32][33];
    int j0 = blockIdx.x * 32, h0 = blockIdx.y * 32;
    int tx = threadIdx.x, ty = threadIdx.y;
    #pragma unroll
    for (int dy = 0; dy < 32; dy += 8) {
        int j = j0 + ty + dy, h = h0 + tx;
        tile[ty + dy][tx] = (Ws[j*H + h] + Ws[H*H + j*H + h] + Ws[2*H*H + j*H + h])
                            * (1.0f/3.0f);
    }
    __syncthreads();
    #pragma unroll
    for (int dy = 0; dy < 32; dy += 8) {
        int h = h0 + ty + dy, j = j0 + tx;
        g_wath[h*H + j] = __float2half_rn(tile[tx][ty + dy]);
    }
}
__global__ void bc_kernel(const float* __restrict__ Wo, const float* __restrict__ bo)
{
    int g = blockIdx.x * 8 + (threadIdx.x >> 5);
    int lane = threadIdx.x & 31;
    float s = 0.0f;
    for (int j = lane; j < H; j += 32) s += Wo[(size_t)g*H + j] * g_bavg[j];
    #pragma unroll
    for (int o = 16; o; o >>= 1) s += __shfl_xor_sync(0xffffffffu, s, o);
    if (lane == 0) g_bc[g] = s + bo[g];
}

// ---------------------------------------------------------------------------
// GEMM: C = A[M,K] @ Bhi[N,K]^T + bias.  AP = A passes (1: hi only, 2: hi+lo).
// BM=BN=128, BK=32, 256 thr, cp.async double-buffered, (AP+1) smem arrays.
// OUTMODE 0: fp32 C.  1: hi-only Ohi.  2: QKV routing (hi-only; Q band scaled).
// ---------------------------------------------------------------------------
#define GSTR 20
#define GARR (128*GSTR)
template<int OUTMODE, int AP>
__global__ __launch_bounds__(256, 2) void gemm_sp(
    const __half* __restrict__ Ahi, const __half* __restrict__ Alo,
    const __half* __restrict__ Bhi,
    const float* __restrict__ bias, float scale,
    float* __restrict__ C,
    __half* __restrict__ Ohi,
    __half* __restrict__ Khi,  __half* __restrict__ Vhi,
    int M, int N, int K)
{
    extern __shared__ unsigned gsm[];
    const int NARR = AP + 1;
    const int t = threadIdx.x, lane = t & 31, warp = t >> 5;
    const int wm = (warp >> 2) * 64, wn = (warp & 3) * 32;
    const int m0 = blockIdx.y * 128, n0 = blockIdx.x * 128;

    float acc[16][4];
    #pragma unroll
    for (int i = 0; i < 16; i++)
        #pragma unroll
        for (int j = 0; j < 4; j++) acc[i][j] = 0.0f;

    const int lr = t >> 1, half = t & 1;
    const size_t arow = (size_t)(m0 + lr) * K + half * 16;
    const size_t brow = (size_t)(n0 + lr) * K + half * 16;
    const int sw = lr * GSTR + half * 8;
    const int NB = K / 32;

    {
        unsigned* B0 = gsm;
        cpa16(smaddr(&B0[0*GARR + sw]),     Ahi + arow);
        cpa16(smaddr(&B0[0*GARR + sw + 4]), Ahi + arow + 8);
        if (AP == 2) {
            cpa16(smaddr(&B0[1*GARR + sw]),     Alo + arow);
            cpa16(smaddr(&B0[1*GARR + sw + 4]), Alo + arow + 8);
        }
        cpa16(smaddr(&B0[(NARR-1)*GARR + sw]),     Bhi + brow);
        cpa16(smaddr(&B0[(NARR-1)*GARR + sw + 4]), Bhi + brow + 8);
        asm volatile("cp.async.commit_group;");
    }

    for (int bi = 0; bi < NB; bi++) {
        if (bi + 1 < NB) {
            unsigned* Bn = gsm + ((bi + 1) & 1) * NARR * GARR;
            size_t ko = (size_t)(bi + 1) * 32;
            cpa16(smaddr(&Bn[0*GARR + sw]),     Ahi + arow + ko);
            cpa16(smaddr(&Bn[0*GARR + sw + 4]), Ahi + arow + ko + 8);
            if (AP == 2) {
                cpa16(smaddr(&Bn[1*GARR + sw]),     Alo + arow + ko);
                cpa16(smaddr(&Bn[1*GARR + sw + 4]), Alo + arow + ko + 8);
            }
            cpa16(smaddr(&Bn[(NARR-1)*GARR + sw]),     Bhi + brow + ko);
            cpa16(smaddr(&Bn[(NARR-1)*GARR + sw + 4]), Bhi + brow + ko + 8);
            asm volatile("cp.async.commit_group;");
            asm volatile("cp.async.wait_group 1;");
        } else {
            asm volatile("cp.async.wait_group 0;");
        }
        __syncthreads();

        unsigned* Ah = gsm + (bi & 1) * NARR * GARR;
        unsigned* Al = Ah + GARR;
        unsigned* Bh = Ah + (NARR-1)*GARR;

        #pragma unroll
        for (int ks = 0; ks < 2; ks++) {
            const int ar = ((lane >> 3) & 1) * 8 + (lane & 7);
            const int aw = ks * 8 + (lane >> 4) * 4;
            unsigned ah[4][4], am[4][4];
            #pragma unroll
            for (int mt = 0; mt < 4; mt++) {
                int r = (wm + mt*16 + ar) * GSTR + aw;
                ldsm4(ah[mt][0], ah[mt][1], ah[mt][2], ah[mt][3], smaddr(&Ah[r]));
                if (AP == 2)
                    ldsm4(am[mt][0], am[mt][1], am[mt][2], am[mt][3], smaddr(&Al[r]));
            }
            const int br = ((lane >> 4) & 1) * 8 + (lane & 7);
            const int bw = ks * 8 + ((lane >> 3) & 1) * 4;
            unsigned bh[2][4];
            #pragma unroll
            for (int np = 0; np < 2; np++) {
                int r = (wn + np*16 + br) * GSTR + bw;
                ldsm4(bh[np][0], bh[np][1], bh[np][2], bh[np][3], smaddr(&Bh[r]));
            }
            #pragma unroll
            for (int mt = 0; mt < 4; mt++)
                #pragma unroll
                for (int nt = 0; nt < 4; nt++) {
                    unsigned* bhp = &bh[nt >> 1][(nt & 1) * 2];
                    mma16h(acc[mt*4+nt], ah[mt], bhp);
                    if (AP == 2) mma16h(acc[mt*4+nt], am[mt], bhp);
                }
        }
        __syncthreads();
    }

    #pragma unroll
    for (int mt = 0; mt < 4; mt++) {
        int row = m0 + wm + mt*16 + (lane >> 2);
        #pragma unroll
        for (int nt = 0; nt < 4; nt++) {
            int col = n0 + wn + nt*8 + (lane & 3) * 2;
            float b0 = __ldg(bias + col), b1 = __ldg(bias + col + 1);
            float* a = acc[mt*4+nt];
            float v00 = a[0] + b0, v01 = a[1] + b1;
            float v10 = a[2] + b0, v11 = a[3] + b1;
            if (OUTMODE == 0) {
                float2 u;
                u.x = v00; u.y = v01; *(float2*)(C + (size_t)row * N + col) = u;
                u.x = v10; u.y = v11; *(float2*)(C + (size_t)(row + 8) * N + col) = u;
            } else if (OUTMODE == 1) {
                *(unsigned*)(Ohi + (size_t)row * N + col)       = pack2h(v00, v01);
                *(unsigned*)(Ohi + (size_t)(row + 8) * N + col) = pack2h(v10, v11);
            } else {
                int which = n0 >> 10;
                int cl = col & 1023;
                __half* dst = (which == 0) ? Ohi : ((which == 1) ? Khi : Vhi);
                float sc = (which == 0) ? scale : 1.0f;
                *(unsigned*)(dst + (size_t)row * H + cl) =
                    pack2h(v00 * sc, v01 * sc);
                *(unsigned*)(dst + (size_t)(row + 8) * H + cl) =
                    pack2h(v10 * sc, v11 * sc);
            }
        }
    }
}

// ---------------------------------------------------------------------------
// Flash attention, all-fp16 single-pass: S = Qhi @ Khi^T, O = Phi @ Vhi.
// CTA = 64 q-rows, 4 warps; K/V double-buffered via cp.async.
// Q staged through buffer 1. P in registers. hi-only fp16 output.
// ---------------------------------------------------------------------------
#define ASTR 36
#define TILE_W (64*ASTR)
#define ATTN_SMEM (4*TILE_W*4)  // 36864 B

__global__ __launch_bounds__(128, 3) void attn_h1(
    const __half* __restrict__ qhi,
    const __half* __restrict__ khi, const __half* __restrict__ vhi,
    __half* __restrict__ athi)
{
    extern __shared__ unsigned smu[];
    unsigned* bufs = smu;

    const int t = threadIdx.x, lane = t & 31, warp = t >> 5;
    const int qb = blockIdx.x, h = blockIdx.y, b = blockIdx.z;
    const int lrow = t >> 1, cb = (t & 1) * 4;
    const int NT = SEQ / 64;
    const unsigned d0 = lrow * ASTR + cb * 4;

    // stage Q into buffer 1 array 0
    {
        size_t qoff = ((size_t)(b*SEQ + qb*64 + lrow)) * H + h*HD + cb*8;
        unsigned* B1 = bufs + 2*TILE_W;
        #pragma unroll
        for (int i = 0; i < 4; i++)
            cpa16(smaddr(&B1[d0 + i*4]), qhi + qoff + i*8);
        asm volatile("cp.async.commit_group;");
    }
    // KV tile 0 -> buffer 0
    {
        size_t base = ((size_t)(b*SEQ + lrow)) * H + h*HD + cb*8;
        #pragma unroll
        for (int i = 0; i < 4; i++) {
            cpa16(smaddr(&bufs[0*TILE_W + d0 + i*4]), khi + base + i*8);
            cpa16(smaddr(&bufs[1*TILE_W + d0 + i*4]), vhi + base + i*8);
        }
        asm volatile("cp.async.commit_group;");
    }

    asm volatile("cp.async.wait_group 1;");
    __syncthreads();

    unsigned qh[4][4];
    {
        const int ar = warp*16 + ((lane >> 3) & 1) * 8 + (lane & 7);
        unsigned* B1 = bufs + 2*TILE_W;
        #pragma unroll
        for (int ks = 0; ks < 4; ks++) {
            int w = ks * 8 + (lane >> 4) * 4;
            ldsm4(qh[ks][0], qh[ks][1], qh[ks][2], qh[ks][3],
                  smaddr(&B1[ar*ASTR + w]));
        }
    }
    __syncthreads();

    float o[8][4];
    #pragma unroll
    for (int i = 0; i < 8; i++)
        #pragma unroll
        for (int j = 0; j < 4; j++) o[i][j] = 0.0f;
    float m0 = -1e30f, m1 = -1e30f, l0 = 0.0f, l1 = 0.0f;
    const int r = warp*16 + (lane >> 2);

    for (int kb = 0; kb < NT; kb++) {
        if (kb + 1 < NT) {
            size_t base = ((size_t)(b*SEQ + (kb+1)*64 + lrow)) * H + h*HD + cb*8;
            unsigned* Bn = bufs + ((kb+1) & 1) * 2 * TILE_W;
            #pragma unroll
            for (int i = 0; i < 4; i++) {
                cpa16(smaddr(&Bn[0*TILE_W + d0 + i*4]), khi + base + i*8);
                cpa16(smaddr(&Bn[1*TILE_W + d0 + i*4]), vhi + base + i*8);
            }
            asm volatile("cp.async.commit_group;");
            asm volatile("cp.async.wait_group 1;");
        } else {
            asm volatile("cp.async.wait_group 0;");
        }
        __syncthreads();

        unsigned* Kh = bufs + (kb & 1) * 2 * TILE_W;
        unsigned* Vh = Kh + TILE_W;

        // S = Q @ K^T (single pass)
        float s[8][4];
        #pragma unroll
        for (int i = 0; i < 8; i++)
            #pragma unroll
            for (int j = 0; j < 4; j++) s[i][j] = 0.0f;

        #pragma unroll
        for (int ks = 0; ks < 4; ks++) {
            const int br = ((lane >> 4) & 1) * 8 + (lane & 7);
            const int bw = ks * 8 + ((lane >> 3) & 1) * 4;
            unsigned bh[4][4];
            #pragma unroll
            for (int np = 0; np < 4; np++) {
                int rr = (np*16 + br) * ASTR + bw;
                ldsm4(bh[np][0], bh[np][1], bh[np][2], bh[np][3], smaddr(&Kh[rr]));
            }
            #pragma unroll
            for (int nt = 0; nt < 8; nt++)
                mma16h(s[nt], qh[ks], &bh[nt >> 1][(nt & 1) * 2]);
        }

        // online softmax
        float mx0 = -1e30f, mx1 = -1e30f;
        #pragma unroll
        for (int nt = 0; nt < 8; nt++) {
            mx0 = fmaxf(mx0, fmaxf(s[nt][0], s[nt][1]));
            mx1 = fmaxf(mx1, fmaxf(s[nt][2], s[nt][3]));
        }
        mx0 = fmaxf(mx0, __shfl_xor_sync(0xffffffffu, mx0, 1));
        mx0 = fmaxf(mx0, __shfl_xor_sync(0xffffffffu, mx0, 2));
        mx1 = fmaxf(mx1, __shfl_xor_sync(0xffffffffu, mx1, 1));
        mx1 = fmaxf(mx1, __shfl_xor_sync(0xffffffffu, mx1, 2));
        float nm0 = fmaxf(m0, mx0), nm1 = fmaxf(m1, mx1);
        float a0 = __expf(m0 - nm0), a1 = __expf(m1 - nm1);

        float sum0 = 0.0f, sum1 = 0.0f;
        #pragma unroll
        for (int nt = 0; nt < 8; nt++) {
            s[nt][0] = __expf(s[nt][0] - nm0); sum0 += s[nt][0];
            s[nt][1] = __expf(s[nt][1] - nm0); sum0 += s[nt][1];
            s[nt][2] = __expf(s[nt][2] - nm1); sum1 += s[nt][2];
            s[nt][3] = __expf(s[nt][3] - nm1); sum1 += s[nt][3];
        }
        sum0 += __shfl_xor_sync(0xffffffffu, sum0, 1);
        sum0 += __shfl_xor_sync(0xffffffffu, sum0, 2);
        sum1 += __shfl_xor_sync(0xffffffffu, sum1, 1);
        sum1 += __shfl_xor_sync(0xffffffffu, sum1, 2);
        l0 = l0*a0 + sum0;  l1 = l1*a1 + sum1;
        m0 = nm0;           m1 = nm1;
        #pragma unroll
        for (int nt = 0; nt < 8; nt++) {
            o[nt][0] *= a0; o[nt][1] *= a0;
            o[nt][2] *= a1; o[nt][3] *= a1;
        }

        // O += P @ V  (single pass)
        #pragma unroll
        for (int ks = 0; ks < 4; ks++) {
            unsigned ph[4];
            ph[0] = pack2h(s[2*ks][0],   s[2*ks][1]);
            ph[1] = pack2h(s[2*ks][2],   s[2*ks][3]);
            ph[2] = pack2h(s[2*ks+1][0], s[2*ks+1][1]);
            ph[3] = pack2h(s[2*ks+1][2], s[2*ks+1][3]);

            const int vr = ks*16 + ((lane >> 3) & 1) * 8 + (lane & 7);
            unsigned vh[4][4];
            #pragma unroll
            for (int np = 0; np < 4; np++) {
                int vw = np*8 + (lane >> 4) * 4;
                ldsm4t(vh[np][0], vh[np][1], vh[np][2], vh[np][3], smaddr(&Vh[vr*ASTR + vw]));
            }
            #pragma unroll
            for (int nt = 0; nt < 8; nt++)
                mma16h(o[nt], ph, &vh[nt >> 1][(nt & 1) * 2]);
        }
        __syncthreads();
    }

    float inv0 = 1.0f / l0, inv1 = 1.0f / l1;
    size_t gr0 = (size_t)(b*SEQ + qb*64 + r) * H + h*HD;
    size_t gr1 = (size_t)(b*SEQ + qb*64 + r + 8) * H + h*HD;
    int col = (lane & 3) * 2;
    #pragma unroll
    for (int nt = 0; nt < 8; nt++) {
        *(unsigned*)(athi + gr0 + nt*8 + col) = pack2h(o[nt][0]*inv0, o[nt][1]*inv0);
        *(unsigned*)(athi + gr1 + nt*8 + col) = pack2h(o[nt][2]*inv1, o[nt][3]*inv1);
    }
}

// ---------------------------------------------------------------------------
extern "C" void kernel_launch(void* const* d_in, const int* in_sizes, int n_in,
                              void* d_out, int out_size)
{
    const float* x  = (const float*)d_in[0];
    const float* Wq = (const float*)d_in[1];
    const float* bq = (const float*)d_in[2];
    const float* Wk = (const float*)d_in[3];
    const float* bk = (const float*)d_in[4];
    const float* Wv = (const float*)d_in[5];
    const float* bv = (const float*)d_in[6];
    const float* Ws = (const float*)d_in[7];
    const float* bs = (const float*)d_in[8];
    const float* Wo = (const float*)d_in[9];
    const float* bo = (const float*)d_in[10];

    __half *xh, *qh, *kh, *vh, *ath;
    __half *wqkvh, *woh, *wol, *wath, *wch;
    float *bqkvp, *bcp, *zerop;
    cudaGetSymbolAddress((void**)&xh, g_xh);
    cudaGetSymbolAddress((void**)&qh, g_qh);
    cudaGetSymbolAddress((void**)&kh, g_kh);
    cudaGetSymbolAddress((void**)&vh, g_vh);
    cudaGetSymbolAddress((void**)&ath, g_ath);
    cudaGetSymbolAddress((void**)&wqkvh, g_wqkvh);
    cudaGetSymbolAddress((void**)&woh, g_woh); cudaGetSymbolAddress((void**)&wol, g_wol);
    cudaGetSymbolAddress((void**)&wath, g_wath);
    cudaGetSymbolAddress((void**)&wch, g_wch);
    cudaGetSymbolAddress((void**)&bqkvp, g_bqkv);
    cudaGetSymbolAddress((void**)&bcp, g_bc);
    cudaGetSymbolAddress((void**)&zerop, g_zero);

    const int SM1 = 2*2*GARR*4;   // AP=1: 40960 B
    const int SM2 = 2*3*GARR*4;   // AP=2: 61440 B
    cudaFuncSetAttribute(attn_h1,
                         cudaFuncAttributeMaxDynamicSharedMemorySize, ATTN_SMEM);
    cudaFuncSetAttribute(gemm_sp<0,1>,
                         cudaFuncAttributeMaxDynamicSharedMemorySize, SM1);
    cudaFuncSetAttribute(gemm_sp<1,2>,
                         cudaFuncAttributeMaxDynamicSharedMemorySize, SM2);
    cudaFuncSetAttribute(gemm_sp<2,1>,
                         cudaFuncAttributeMaxDynamicSharedMemorySize, SM1);

    // fused prep
    prep_all<<<(ROWS*H + 255)/256, 256>>>(x, Wq, Wk, Wv, Wo, bq, bk, bv, bs);
    avgT_split<<<dim3(32, 32), dim3(32, 8)>>>(Ws);

    // Wc = Wo @ mean(Ws): A = Wo split (2-pass), B = WaT hi
    gemm_sp<1,2><<<dim3(8, 8), 256, SM2>>>(
        woh, wol, wath, zerop, 1.0f,
        nullptr, wch, nullptr, nullptr, H, H, H);
    bc_kernel<<<H/8, 256>>>(Wo, bo);

    // fused QKV (single-pass A): [4096, 3072]
    gemm_sp<2,1><<<dim3(3*H/128, ROWS/128), 256, SM1>>>(
        xh, nullptr, wqkvh, bqkvp, 0.125f,
        nullptr, qh, kh, vh, ROWS, 3*H, H);

    attn_h1<<<dim3(SEQ/64, NHEADS, BATCH), 128, ATTN_SMEM>>>(qh, kh, vh, ath);

    // out = att @ Wc^T + bc (single-pass A)
    gemm_sp<0,1><<<dim3(H/128, ROWS/128), 256, SM1>>>(
        ath, nullptr, wch, bcp, 1.0f,
        (float*)d_out, nullptr, nullptr, nullptr, ROWS, H, H);
}

// round 12
// speedup vs baseline: 9.6823x; 1.0497x over previous
#include <cuda_runtime.h>
#include <cuda_fp16.h>
#include <math.h>
#include <stdint.h>

#define H 1024
#define NHEADS 16
#define HD 64
#define SEQ 2048
#define BATCH 2
#define ROWS (BATCH*SEQ)   // 4096

// ---------------- scratch (device globals; allocation-free) ----------------
__device__ __half g_xh[ROWS*H];
__device__ __half g_qh[ROWS*H];
__device__ __half g_kh[ROWS*H];
__device__ __half g_vh[ROWS*H];
__device__ __half g_ath[ROWS*H];
__device__ __half g_wqkvh[3*H*H];          // packed 0.125*Wq|Wk|Wv, hi only
__device__ __half g_woh[H*H], g_wol[H*H];  // Wo split (A of Wc GEMM)
__device__ __half g_wath[H*H];             // mean(Ws)^T hi only
__device__ __half g_wch[H*H];              // Wc = Wo @ Wa, hi only
__device__ float g_bqkv[3*H];              // 0.125*bq | bk | bv
__device__ float g_bavg[H];
__device__ float g_bc[H];
__device__ float g_zero[H];                // stays 0

// ---------------------------------------------------------------------------
__device__ __forceinline__ unsigned smaddr(const void* p) {
    return (unsigned)__cvta_generic_to_shared(p);
}
__device__ __forceinline__ void ldsm4(unsigned& r0, unsigned& r1, unsigned& r2,
                                      unsigned& r3, unsigned a) {
    asm volatile("ldmatrix.sync.aligned.m8n8.x4.shared.b16 {%0,%1,%2,%3}, [%4];"
                 : "=r"(r0), "=r"(r1), "=r"(r2), "=r"(r3) : "r"(a));
}
__device__ __forceinline__ void ldsm4t(unsigned& r0, unsigned& r1, unsigned& r2,
                                       unsigned& r3, unsigned a) {
    asm volatile("ldmatrix.sync.aligned.m8n8.x4.trans.shared.b16 {%0,%1,%2,%3}, [%4];"
                 : "=r"(r0), "=r"(r1), "=r"(r2), "=r"(r3) : "r"(a));
}
__device__ __forceinline__ void mma16h(float* c, const unsigned* a, const unsigned* b) {
    asm volatile(
        "mma.sync.aligned.m16n8k16.row.col.f32.f16.f16.f32 "
        "{%0,%1,%2,%3}, {%4,%5,%6,%7}, {%8,%9}, {%0,%1,%2,%3};"
        : "+f"(c[0]), "+f"(c[1]), "+f"(c[2]), "+f"(c[3])
        : "r"(a[0]), "r"(a[1]), "r"(a[2]), "r"(a[3]), "r"(b[0]), "r"(b[1]));
}
__device__ __forceinline__ void cpa16(unsigned dst, const void* src) {
    asm volatile("cp.async.ca.shared.global [%0], [%1], 16;" :: "r"(dst), "l"(src));
}
__device__ __forceinline__ unsigned pack2h(float x0, float x1) {
    __half h0 = __float2half_rn(x0), h1 = __float2half_rn(x1);
    return ((unsigned)__half_as_ushort(h1) << 16) | __half_as_ushort(h0);
}

// ---------------------------------------------------------------------------
// fused prep: x trunc, (0.125Wq)/Wk/Wv trunc (packed), Wo split, bias packing
// ---------------------------------------------------------------------------
__global__ void prep_all(const float* __restrict__ x,
                         const float* __restrict__ Wq, const float* __restrict__ Wk,
                         const float* __restrict__ Wv, const float* __restrict__ Wo,
                         const float* __restrict__ bq, const float* __restrict__ bk,
                         const float* __restrict__ bv, const float* __restrict__ bs)
{
    int i = blockIdx.x * 256 + threadIdx.x;
    if (i < ROWS*H) g_xh[i] = __float2half_rn(x[i]);
    if (i < H*H) {
        g_wqkvh[i]         = __float2half_rn(Wq[i] * 0.125f);
        g_wqkvh[H*H + i]   = __float2half_rn(Wk[i]);
        g_wqkvh[2*H*H + i] = __float2half_rn(Wv[i]);
        float w = Wo[i];
        __half h = __float2half_rn(w);
        g_woh[i] = h;
        g_wol[i] = __float2half_rn(w - __half2float(h));
    }
    if (i < H) {
        g_bqkv[i]       = bq[i] * 0.125f;
        g_bqkv[H + i]   = bk[i];
        g_bqkv[2*H + i] = bv[i];
        g_bavg[i] = (bs[i] + bs[i + H] + bs[i + 2*H]) * (1.0f/3.0f);
    }
}
// WaT[h][j] = mean_n Ws[n][j][h], hi only (B side of Wc GEMM)
__global__ void avgT_split(const float* __restrict__ Ws)
{
    __shared__ float tile[32][33];
    int j0 = blockIdx.x * 32, h0 = blockIdx.y * 32;
    int tx = threadIdx.x, ty = threadIdx.y;
    #pragma unroll
    for (int dy = 0; dy < 32; dy += 8) {
        int j = j0 + ty + dy, h = h0 + tx;
        tile[ty + dy][tx] = (Ws[j*H + h] + Ws[H*H + j*H + h] + Ws[2*H*H + j*H + h])
                            * (1.0f/3.0f);
    }
    __syncthreads();
    #pragma unroll
    for (int dy = 0; dy < 32; dy += 8) {
        int h = h0 + ty + dy, j = j0 + tx;
        g_wath[h*H + j] = __float2half_rn(tile[tx][ty + dy]);
    }
}
__global__ void bc_kernel(const float* __restrict__ Wo, const float* __restrict__ bo)
{
    int g = blockIdx.x * 8 + (threadIdx.x >> 5);
    int lane = threadIdx.x & 31;
    float s = 0.0f;
    for (int j = lane; j < H; j += 32) s += Wo[(size_t)g*H + j] * g_bavg[j];
    #pragma unroll
    for (int o = 16; o; o >>= 1) s += __shfl_xor_sync(0xffffffffu, s, o);
    if (lane == 0) g_bc[g] = s + bo[g];
}

// ---------------------------------------------------------------------------
// GEMM: C = A[M,K] @ Bhi[N,K]^T + bias.  AP = A passes (1: hi only, 2: hi+lo).
// BM=BN=128, BK=32, 256 thr, cp.async double-buffered, (AP+1) smem arrays.
// OUTMODE 0: fp32 C.  1: hi-only Ohi.  2: QKV band routing (pure pack).
// ---------------------------------------------------------------------------
#define GSTR 20
#define GARR (128*GSTR)
template<int OUTMODE, int AP>
__global__ __launch_bounds__(256, 2) void gemm_sp(
    const __half* __restrict__ Ahi, const __half* __restrict__ Alo,
    const __half* __restrict__ Bhi,
    const float* __restrict__ bias,
    float* __restrict__ C,
    __half* __restrict__ Ohi,
    __half* __restrict__ Khi,  __half* __restrict__ Vhi,
    int M, int N, int K)
{
    extern __shared__ unsigned gsm[];
    const int NARR = AP + 1;
    const int t = threadIdx.x, lane = t & 31, warp = t >> 5;
    const int wm = (warp >> 2) * 64, wn = (warp & 3) * 32;
    const int m0 = blockIdx.y * 128, n0 = blockIdx.x * 128;

    float acc[16][4];
    #pragma unroll
    for (int i = 0; i < 16; i++)
        #pragma unroll
        for (int j = 0; j < 4; j++) acc[i][j] = 0.0f;

    const int lr = t >> 1, half = t & 1;
    const size_t arow = (size_t)(m0 + lr) * K + half * 16;
    const size_t brow = (size_t)(n0 + lr) * K + half * 16;
    const int sw = lr * GSTR + half * 8;
    const int NB = K / 32;

    {
        unsigned* B0 = gsm;
        cpa16(smaddr(&B0[0*GARR + sw]),     Ahi + arow);
        cpa16(smaddr(&B0[0*GARR + sw + 4]), Ahi + arow + 8);
        if (AP == 2) {
            cpa16(smaddr(&B0[1*GARR + sw]),     Alo + arow);
            cpa16(smaddr(&B0[1*GARR + sw + 4]), Alo + arow + 8);
        }
        cpa16(smaddr(&B0[(NARR-1)*GARR + sw]),     Bhi + brow);
        cpa16(smaddr(&B0[(NARR-1)*GARR + sw + 4]), Bhi + brow + 8);
        asm volatile("cp.async.commit_group;");
    }

    for (int bi = 0; bi < NB; bi++) {
        if (bi + 1 < NB) {
            unsigned* Bn = gsm + ((bi + 1) & 1) * NARR * GARR;
            size_t ko = (size_t)(bi + 1) * 32;
            cpa16(smaddr(&Bn[0*GARR + sw]),     Ahi + arow + ko);
            cpa16(smaddr(&Bn[0*GARR + sw + 4]), Ahi + arow + ko + 8);
            if (AP == 2) {
                cpa16(smaddr(&Bn[1*GARR + sw]),     Alo + arow + ko);
                cpa16(smaddr(&Bn[1*GARR + sw + 4]), Alo + arow + ko + 8);
            }
            cpa16(smaddr(&Bn[(NARR-1)*GARR + sw]),     Bhi + brow + ko);
            cpa16(smaddr(&Bn[(NARR-1)*GARR + sw + 4]), Bhi + brow + ko + 8);
            asm volatile("cp.async.commit_group;");
            asm volatile("cp.async.wait_group 1;");
        } else {
            asm volatile("cp.async.wait_group 0;");
        }
        __syncthreads();

        unsigned* Ah = gsm + (bi & 1) * NARR * GARR;
        unsigned* Al = Ah + GARR;
        unsigned* Bh = Ah + (NARR-1)*GARR;

        #pragma unroll
        for (int ks = 0; ks < 2; ks++) {
            const int ar = ((lane >> 3) & 1) * 8 + (lane & 7);
            const int aw = ks * 8 + (lane >> 4) * 4;
            unsigned ah[4][4], am[4][4];
            #pragma unroll
            for (int mt = 0; mt < 4; mt++) {
                int r = (wm + mt*16 + ar) * GSTR + aw;
                ldsm4(ah[mt][0], ah[mt][1], ah[mt][2], ah[mt][3], smaddr(&Ah[r]));
                if (AP == 2)
                    ldsm4(am[mt][0], am[mt][1], am[mt][2], am[mt][3], smaddr(&Al[r]));
            }
            const int br = ((lane >> 4) & 1) * 8 + (lane & 7);
            const int bw = ks * 8 + ((lane >> 3) & 1) * 4;
            unsigned bh[2][4];
            #pragma unroll
            for (int np = 0; np < 2; np++) {
                int r = (wn + np*16 + br) * GSTR + bw;
                ldsm4(bh[np][0], bh[np][1], bh[np][2], bh[np][3], smaddr(&Bh[r]));
            }
            #pragma unroll
            for (int mt = 0; mt < 4; mt++)
                #pragma unroll
                for (int nt = 0; nt < 4; nt++) {
                    unsigned* bhp = &bh[nt >> 1][(nt & 1) * 2];
                    mma16h(acc[mt*4+nt], ah[mt], bhp);
                    if (AP == 2) mma16h(acc[mt*4+nt], am[mt], bhp);
                }
        }
        __syncthreads();
    }

    #pragma unroll
    for (int mt = 0; mt < 4; mt++) {
        int row = m0 + wm + mt*16 + (lane >> 2);
        #pragma unroll
        for (int nt = 0; nt < 4; nt++) {
            int col = n0 + wn + nt*8 + (lane & 3) * 2;
            float b0 = __ldg(bias + col), b1 = __ldg(bias + col + 1);
            float* a = acc[mt*4+nt];
            float v00 = a[0] + b0, v01 = a[1] + b1;
            float v10 = a[2] + b0, v11 = a[3] + b1;
            if (OUTMODE == 0) {
                float2 u;
                u.x = v00; u.y = v01; *(float2*)(C + (size_t)row * N + col) = u;
                u.x = v10; u.y = v11; *(float2*)(C + (size_t)(row + 8) * N + col) = u;
            } else if (OUTMODE == 1) {
                *(unsigned*)(Ohi + (size_t)row * N + col)       = pack2h(v00, v01);
                *(unsigned*)(Ohi + (size_t)(row + 8) * N + col) = pack2h(v10, v11);
            } else {
                int which = n0 >> 10;
                int cl = col & 1023;
                __half* dst = (which == 0) ? Ohi : ((which == 1) ? Khi : Vhi);
                *(unsigned*)(dst + (size_t)row * H + cl)       = pack2h(v00, v01);
                *(unsigned*)(dst + (size_t)(row + 8) * H + cl) = pack2h(v10, v11);
            }
        }
    }
}

// ---------------------------------------------------------------------------
// Flash attention, all-fp16, BQ=128: one CTA = 128 q-rows of one (b,h),
// 256 threads / 8 warps (16 rows each). KV 64-row tiles double-buffered;
// Q staged through buffer 1 (both arrays). P in registers. fp16 output.
// ---------------------------------------------------------------------------
#define ASTR 36
#define TILE_W (64*ASTR)
#define ATTN_SMEM (4*TILE_W*4)  // 36864 B

__global__ __launch_bounds__(256, 2) void attn_h1(
    const __half* __restrict__ qhi,
    const __half* __restrict__ khi, const __half* __restrict__ vhi,
    __half* __restrict__ athi)
{
    extern __shared__ unsigned smu[];
    unsigned* bufs = smu;

    const int t = threadIdx.x, lane = t & 31, warp = t >> 5;
    const int qb = blockIdx.x, h = blockIdx.y, b = blockIdx.z;
    const int NT = SEQ / 64;

    // KV loader mapping: 4 threads/row, 2 chunks each
    const int krow = t >> 2, kcb = t & 3;
    const unsigned kd0 = krow * ASTR + kcb * 8;

    // stage Q (128 rows) into buffer 1 (contiguous 2*TILE_W words)
    {
        const int qrow = t >> 1, qhf = t & 1;   // 2 threads/row, 4 chunks each
        size_t qoff = ((size_t)(b*SEQ + qb*128 + qrow)) * H + h*HD + qhf*32;
        unsigned d = 2*TILE_W + qrow * ASTR + qhf * 16;
        #pragma unroll
        for (int i = 0; i < 4; i++)
            cpa16(smaddr(&bufs[d + i*4]), qhi + qoff + i*8);
        asm volatile("cp.async.commit_group;");
    }
    // KV tile 0 -> buffer 0
    {
        size_t base = ((size_t)(b*SEQ + krow)) * H + h*HD + kcb*16;
        cpa16(smaddr(&bufs[0*TILE_W + kd0]),     khi + base);
        cpa16(smaddr(&bufs[0*TILE_W + kd0 + 4]), khi + base + 8);
        cpa16(smaddr(&bufs[1*TILE_W + kd0]),     vhi + base);
        cpa16(smaddr(&bufs[1*TILE_W + kd0 + 4]), vhi + base + 8);
        asm volatile("cp.async.commit_group;");
    }

    asm volatile("cp.async.wait_group 1;");
    __syncthreads();

    // persistent Q fragments (warp rows warp*16..+15)
    unsigned qfr[4][4];
    {
        const int ar = warp*16 + ((lane >> 3) & 1) * 8 + (lane & 7);
        #pragma unroll
        for (int ks = 0; ks < 4; ks++) {
            int w = ks * 8 + (lane >> 4) * 4;
            ldsm4(qfr[ks][0], qfr[ks][1], qfr[ks][2], qfr[ks][3],
                  smaddr(&bufs[2*TILE_W + ar*ASTR + w]));
        }
    }
    __syncthreads();   // buffer 1 free for KV prefetch

    float o[8][4];
    #pragma unroll
    for (int i = 0; i < 8; i++)
        #pragma unroll
        for (int j = 0; j < 4; j++) o[i][j] = 0.0f;
    float m0 = -1e30f, m1 = -1e30f, l0 = 0.0f, l1 = 0.0f;
    const int r = warp*16 + (lane >> 2);

    for (int kb = 0; kb < NT; kb++) {
        if (kb + 1 < NT) {
            size_t base = ((size_t)(b*SEQ + (kb+1)*64 + krow)) * H + h*HD + kcb*16;
            unsigned* Bn = bufs + ((kb+1) & 1) * 2 * TILE_W;
            cpa16(smaddr(&Bn[0*TILE_W + kd0]),     khi + base);
            cpa16(smaddr(&Bn[0*TILE_W + kd0 + 4]), khi + base + 8);
            cpa16(smaddr(&Bn[1*TILE_W + kd0]),     vhi + base);
            cpa16(smaddr(&Bn[1*TILE_W + kd0 + 4]), vhi + base + 8);
            asm volatile("cp.async.commit_group;");
            asm volatile("cp.async.wait_group 1;");
        } else {
            asm volatile("cp.async.wait_group 0;");
        }
        __syncthreads();

        unsigned* Kh = bufs + (kb & 1) * 2 * TILE_W;
        unsigned* Vh = Kh + TILE_W;

        // S = Q @ K^T (single pass)
        float s[8][4];
        #pragma unroll
        for (int i = 0; i < 8; i++)
            #pragma unroll
            for (int j = 0; j < 4; j++) s[i][j] = 0.0f;

        #pragma unroll
        for (int ks = 0; ks < 4; ks++) {
            const int br = ((lane >> 4) & 1) * 8 + (lane & 7);
            const int bw = ks * 8 + ((lane >> 3) & 1) * 4;
            unsigned bh[4][4];
            #pragma unroll
            for (int np = 0; np < 4; np++) {
                int rr = (np*16 + br) * ASTR + bw;
                ldsm4(bh[np][0], bh[np][1], bh[np][2], bh[np][3], smaddr(&Kh[rr]));
            }
            #pragma unroll
            for (int nt = 0; nt < 8; nt++)
                mma16h(s[nt], qfr[ks], &bh[nt >> 1][(nt & 1) * 2]);
        }

        // online softmax
        float mx0 = -1e30f, mx1 = -1e30f;
        #pragma unroll
        for (int nt = 0; nt < 8; nt++) {
            mx0 = fmaxf(mx0, fmaxf(s[nt][0], s[nt][1]));
            mx1 = fmaxf(mx1, fmaxf(s[nt][2], s[nt][3]));
        }
        mx0 = fmaxf(mx0, __shfl_xor_sync(0xffffffffu, mx0, 1));
        mx0 = fmaxf(mx0, __shfl_xor_sync(0xffffffffu, mx0, 2));
        mx1 = fmaxf(mx1, __shfl_xor_sync(0xffffffffu, mx1, 1));
        mx1 = fmaxf(mx1, __shfl_xor_sync(0xffffffffu, mx1, 2));
        float nm0 = fmaxf(m0, mx0), nm1 = fmaxf(m1, mx1);
        float a0 = __expf(m0 - nm0), a1 = __expf(m1 - nm1);

        float sum0 = 0.0f, sum1 = 0.0f;
        #pragma unroll
        for (int nt = 0; nt < 8; nt++) {
            s[nt][0] = __expf(s[nt][0] - nm0); sum0 += s[nt][0];
            s[nt][1] = __expf(s[nt][1] - nm0); sum0 += s[nt][1];
            s[nt][2] = __expf(s[nt][2] - nm1); sum1 += s[nt][2];
            s[nt][3] = __expf(s[nt][3] - nm1); sum1 += s[nt][3];
        }
        sum0 += __shfl_xor_sync(0xffffffffu, sum0, 1);
        sum0 += __shfl_xor_sync(0xffffffffu, sum0, 2);
        sum1 += __shfl_xor_sync(0xffffffffu, sum1, 1);
        sum1 += __shfl_xor_sync(0xffffffffu, sum1, 2);
        l0 = l0*a0 + sum0;  l1 = l1*a1 + sum1;
        m0 = nm0;           m1 = nm1;
        #pragma unroll
        for (int nt = 0; nt < 8; nt++) {
            o[nt][0] *= a0; o[nt][1] *= a0;
            o[nt][2] *= a1; o[nt][3] *= a1;
        }

        // O += P @ V  (single pass, P from S registers)
        #pragma unroll
        for (int ks = 0; ks < 4; ks++) {
            unsigned ph[4];
            ph[0] = pack2h(s[2*ks][0],   s[2*ks][1]);
            ph[1] = pack2h(s[2*ks][2],   s[2*ks][3]);
            ph[2] = pack2h(s[2*ks+1][0], s[2*ks+1][1]);
            ph[3] = pack2h(s[2*ks+1][2], s[2*ks+1][3]);

            const int vr = ks*16 + ((lane >> 3) & 1) * 8 + (lane & 7);
            unsigned vh[4][4];
            #pragma unroll
            for (int np = 0; np < 4; np++) {
                int vw = np*8 + (lane >> 4) * 4;
                ldsm4t(vh[np][0], vh[np][1], vh[np][2], vh[np][3], smaddr(&Vh[vr*ASTR + vw]));
            }
            #pragma unroll
            for (int nt = 0; nt < 8; nt++)
                mma16h(o[nt], ph, &vh[nt >> 1][(nt & 1) * 2]);
        }
        __syncthreads();
    }

    float inv0 = 1.0f / l0, inv1 = 1.0f / l1;
    size_t gr0 = (size_t)(b*SEQ + qb*128 + r) * H + h*HD;
    size_t gr1 = (size_t)(b*SEQ + qb*128 + r + 8) * H + h*HD;
    int col = (lane & 3) * 2;
    #pragma unroll
    for (int nt = 0; nt < 8; nt++) {
        *(unsigned*)(athi + gr0 + nt*8 + col) = pack2h(o[nt][0]*inv0, o[nt][1]*inv0);
        *(unsigned*)(athi + gr1 + nt*8 + col) = pack2h(o[nt][2]*inv1, o[nt][3]*inv1);
    }
}

// ---------------------------------------------------------------------------
extern "C" void kernel_launch(void* const* d_in, const int* in_sizes, int n_in,
                              void* d_out, int out_size)
{
    const float* x  = (const float*)d_in[0];
    const float* Wq = (const float*)d_in[1];
    const float* bq = (const float*)d_in[2];
    const float* Wk = (const float*)d_in[3];
    const float* bk = (const float*)d_in[4];
    const float* Wv = (const float*)d_in[5];
    const float* bv = (const float*)d_in[6];
    const float* Ws = (const float*)d_in[7];
    const float* bs = (const float*)d_in[8];
    const float* Wo = (const float*)d_in[9];
    const float* bo = (const float*)d_in[10];

    __half *xh, *qh, *kh, *vh, *ath;
    __half *wqkvh, *woh, *wol, *wath, *wch;
    float *bqkvp, *bcp, *zerop;
    cudaGetSymbolAddress((void**)&xh, g_xh);
    cudaGetSymbolAddress((void**)&qh, g_qh);
    cudaGetSymbolAddress((void**)&kh, g_kh);
    cudaGetSymbolAddress((void**)&vh, g_vh);
    cudaGetSymbolAddress((void**)&ath, g_ath);
    cudaGetSymbolAddress((void**)&wqkvh, g_wqkvh);
    cudaGetSymbolAddress((void**)&woh, g_woh); cudaGetSymbolAddress((void**)&wol, g_wol);
    cudaGetSymbolAddress((void**)&wath, g_wath);
    cudaGetSymbolAddress((void**)&wch, g_wch);
    cudaGetSymbolAddress((void**)&bqkvp, g_bqkv);
    cudaGetSymbolAddress((void**)&bcp, g_bc);
    cudaGetSymbolAddress((void**)&zerop, g_zero);

    const int SM1 = 2*2*GARR*4;   // AP=1: 40960 B
    const int SM2 = 2*3*GARR*4;   // AP=2: 61440 B
    cudaFuncSetAttribute(attn_h1,
                         cudaFuncAttributeMaxDynamicSharedMemorySize, ATTN_SMEM);
    cudaFuncSetAttribute(gemm_sp<0,1>,
                         cudaFuncAttributeMaxDynamicSharedMemorySize, SM1);
    cudaFuncSetAttribute(gemm_sp<1,2>,
                         cudaFuncAttributeMaxDynamicSharedMemorySize, SM2);
    cudaFuncSetAttribute(gemm_sp<2,1>,
                         cudaFuncAttributeMaxDynamicSharedMemorySize, SM1);

    // fused prep
    prep_all<<<(ROWS*H + 255)/256, 256>>>(x, Wq, Wk, Wv, Wo, bq, bk, bv, bs);
    avgT_split<<<dim3(32, 32), dim3(32, 8)>>>(Ws);

    // Wc = Wo @ mean(Ws): A = Wo split (2-pass), B = WaT hi
    gemm_sp<1,2><<<dim3(8, 8), 256, SM2>>>(
        woh, wol, wath, zerop,
        nullptr, wch, nullptr, nullptr, H, H, H);
    bc_kernel<<<H/8, 256>>>(Wo, bo);

    // fused QKV (single-pass A): [4096, 3072]
    gemm_sp<2,1><<<dim3(3*H/128, ROWS/128), 256, SM1>>>(
        xh, nullptr, wqkvh, bqkvp,
        nullptr, qh, kh, vh, ROWS, 3*H, H);

    attn_h1<<<dim3(SEQ/128, NHEADS, BATCH), 256, ATTN_SMEM>>>(qh, kh, vh, ath);

    // out = att @ Wc^T + bc (single-pass A)
    gemm_sp<0,1><<<dim3(H/128, ROWS/128), 256, SM1>>>(
        ath, nullptr, wch, bcp,
        (float*)d_out, nullptr, nullptr, nullptr, ROWS, H, H);
}